// round 11
// baseline (speedup 1.0000x reference)
#include <cuda_runtime.h>
#include <math.h>

#define B 8
#define T 512
#define C 512
#define DFF 2048
#define H 8
#define LYR 6
#define W 4
#define DK 64
#define NREL 9

typedef unsigned long long u64;
typedef unsigned int u32;

// ---------------- scratch ----------------------------------------------------
__device__ float g_h[B*C*T];
__device__ float g_qkv[B*3*C*T];
__device__ float g_ctx[B*C*T];
__device__ float g_y[B*C*T];
__device__ float g_p[(size_t)B*H*T*T];
__device__ float g_f[B*DFF*T];
__device__ float g_mask[B*T];
__device__ float g_b3[LYR*3*C];
// activation panels, pair-major: [b][ct][pair 32][516], bf16x2 hi/lo
__device__ u32 g_px512_hi[B*8*32*516],   g_px512_lo[B*8*32*516];
__device__ u32 g_px2048_hi[B*32*32*516], g_px2048_lo[B*32*32*516];
// weight fragment arrays (per-layer reused => L2-resident)
__device__ u32 g_wqkvo_hi[32*16*1024], g_wqkvo_lo[32*16*1024];  // q(0-3) k(4-7) v(8-11) o(12-15)
__device__ u32 g_w1_hi[3*32*16*1024],  g_w1_lo[3*32*16*1024];
__device__ u32 g_w2_hi[3*128*4*1024],  g_w2_lo[3*128*4*1024];
__device__ u32 g_pj_hi[32*8*1024],     g_pj_lo[32*8*1024];

// ---------------- helpers ------------------------------------------------------
__device__ __forceinline__ u64 ffma2(u64 a, u64 b, u64 c) {
    u64 d; asm("fma.rn.f32x2 %0, %1, %2, %3;" : "=l"(d) : "l"(a), "l"(b), "l"(c));
    return d;
}
__device__ __forceinline__ u64 fpack2(float lo, float hi) {
    u64 d; asm("mov.b64 %0, {%1, %2};" : "=l"(d) : "f"(lo), "f"(hi));
    return d;
}
__device__ __forceinline__ float2 funpack2(u64 v) {
    float2 r; asm("mov.b64 {%0, %1}, %2;" : "=f"(r.x), "=f"(r.y) : "l"(v));
    return r;
}
__device__ __forceinline__ u32 bf2(float h, float l) {
    u32 r; asm("cvt.rn.bf16x2.f32 %0, %1, %2;" : "=r"(r) : "f"(h), "f"(l));
    return r;
}
__device__ __forceinline__ void split2(float f0, float f1, u32& hv, u32& lv) {
    hv = bf2(f1, f0);
    float r0 = f0 - __uint_as_float(hv << 16);
    float r1 = f1 - __uint_as_float(hv & 0xffff0000u);
    lv = bf2(r1, r0);
}
__device__ __forceinline__ void mma16(float* d, const u32* a, u32 b0, u32 b1) {
    asm("mma.sync.aligned.m16n8k16.row.col.f32.bf16.bf16.f32 "
        "{%0,%1,%2,%3}, {%4,%5,%6,%7}, {%8,%9}, {%0,%1,%2,%3};"
        : "+f"(d[0]), "+f"(d[1]), "+f"(d[2]), "+f"(d[3])
        : "r"(a[0]), "r"(a[1]), "r"(a[2]), "r"(a[3]), "r"(b0), "r"(b1));
}
__device__ __forceinline__ u32 smem_u32(const void* p) {
    u32 a; asm("{ .reg .u64 t; cvta.to.shared.u64 t, %1; cvt.u32.u64 %0, t; }"
               : "=r"(a) : "l"(p));
    return a;
}
__device__ __forceinline__ void cp16(u32 dst, const void* src) {
    asm volatile("{ .reg .u64 g; cvta.to.global.u64 g, %1; "
                 "cp.async.cg.shared.global [%0], [g], 16; }"
                 :: "r"(dst), "l"(src) : "memory");
}

// ---------------- embedding + mask -------------------------------------------
__global__ void k_embed(const int* __restrict__ x, const int* __restrict__ xlen,
                        const float* __restrict__ emb,
                        float* __restrict__ out_xemb, float* __restrict__ out_mask) {
    int b = blockIdx.y;
    int t = blockIdx.x * 32 + threadIdx.x;
    int xi = x[b*T + t];
    float mk = (t < xlen[b]) ? 1.f : 0.f;
    const float SQ = 22.627416997969522f;
    for (int c = threadIdx.y; c < C; c += 8) {
        float v = emb[xi*C + c] * SQ;
        out_xemb[((size_t)b*C + c)*T + t] = v;
        g_h[((size_t)b*C + c)*T + t] = v * mk;
    }
    if (threadIdx.y == 0) {
        g_mask[b*T + t] = mk;
        out_mask[b*T + t] = mk;
    }
}

__global__ void k_copy4(const float4* __restrict__ src, float4* __restrict__ dst) {
    int i = blockIdx.x * 256 + threadIdx.x;
    dst[i] = src[i];
}

__global__ void k_bias3(const float* __restrict__ bq, const float* __restrict__ bk,
                        const float* __restrict__ bv, float* __restrict__ b3) {
    int l = blockIdx.y;
    int i = blockIdx.x*256 + threadIdx.x;
    float v;
    if (i < 512)       v = bq[l*C + i] * 0.125f;
    else if (i < 1024) v = bk[l*C + i - 512];
    else               v = bv[l*C + i - 1024];
    b3[l*1536 + i] = v;
}

// ---------------- generic weight pack (w1/w2/proj) ------------------------------
__global__ void k_packwf(const float* __restrict__ Wm, float scale,
                         u32* __restrict__ hi, u32* __restrict__ lo,
                         int ostride, int KKf, int CT16, int OT, int otOff) {
    int ot = blockIdx.x, c16 = blockIdx.y, kp = blockIdx.z;
    int tid = threadIdx.x, s = tid >> 5, l = tid & 31;
    int g = l >> 2, tq = l & 3;
    int wm = s >> 2, mi = s & 3;
    int obase = ot*128 + wm*64 + mi*16 + g;
    u32 rh[4], rl[4];
#pragma unroll
    for (int r = 0; r < 4; r++) {
        int o = obase + (r & 1)*8;
        int pair = (r < 2) ? tq : tq + 4;
        int ce = c16*16 + 2*pair;
        float f0 = Wm[(size_t)o*ostride + (size_t)ce*KKf + kp] * scale;
        float f1 = Wm[(size_t)o*ostride + (size_t)(ce+1)*KKf + kp] * scale;
        split2(f0, f1, rh[r], rl[r]);
    }
    size_t base = ((size_t)((kp*CT16 + c16)*OT + otOff + ot))*1024 + (s*32 + l)*4;
    *(uint4*)&hi[base] = make_uint4(rh[0], rh[1], rh[2], rh[3]);
    *(uint4*)&lo[base] = make_uint4(rl[0], rl[1], rl[2], rl[3]);
}

// ---------------- combined q/k/v/o pack: one launch, z = matrix ----------------
__global__ void k_packw4(const float* __restrict__ Wq, const float* __restrict__ Wk,
                         const float* __restrict__ Wv, const float* __restrict__ Wo,
                         u32* __restrict__ hi, u32* __restrict__ lo) {
    int ot = blockIdx.x, c16 = blockIdx.y, m = blockIdx.z;
    const float* Wm = (m == 0) ? Wq : (m == 1) ? Wk : (m == 2) ? Wv : Wo;
    float scale = (m == 0) ? 0.125f : 1.f;
    int tid = threadIdx.x, s = tid >> 5, l = tid & 31;
    int g = l >> 2, tq = l & 3;
    int wm = s >> 2, mi = s & 3;
    int obase = ot*128 + wm*64 + mi*16 + g;
    u32 rh[4], rl[4];
#pragma unroll
    for (int r = 0; r < 4; r++) {
        int o = obase + (r & 1)*8;
        int pair = (r < 2) ? tq : tq + 4;
        int ce = c16*16 + 2*pair;
        float f0 = Wm[(size_t)o*C + ce] * scale;
        float f1 = Wm[(size_t)o*C + ce + 1] * scale;
        split2(f0, f1, rh[r], rl[r]);
    }
    size_t base = ((size_t)(c16*16 + m*4 + ot))*1024 + (s*32 + l)*4;
    *(uint4*)&hi[base] = make_uint4(rh[0], rh[1], rh[2], rh[3]);
    *(uint4*)&lo[base] = make_uint4(rl[0], rl[1], rl[2], rl[3]);
}

// ---------------- activation pack: f32 [b][c][t] -> pair-major padded panels ----
__global__ void k_packx(const float* __restrict__ X, u32* __restrict__ Phi,
                        u32* __restrict__ Plo, int Cin, int useMask) {
    __shared__ float tile[64][65];
    int t0 = blockIdx.x*64, ct = blockIdx.y, b = blockIdx.z;
    int CT = gridDim.y;
    int tid = threadIdx.x;
    int tx = tid & 63, ty = tid >> 6;
    float mk = useMask ? g_mask[b*T + t0 + tx] : 1.f;
#pragma unroll
    for (int i = 0; i < 16; i++) {
        int cc = ty + i*4;
        tile[cc][tx] = X[((size_t)b*Cin + ct*64 + cc)*T + t0 + tx] * mk;
    }
    __syncthreads();
    size_t base = (size_t)(b*CT + ct)*32*516;
#pragma unroll
    for (int i = 0; i < 8; i++) {
        int e = tid + i*256;
        int p = e >> 6, tt = e & 63;
        u32 hv, lv; split2(tile[2*p][tt], tile[2*p+1][tt], hv, lv);
        Phi[base + (size_t)p*516 + t0 + tt + 1] = hv;
        Plo[base + (size_t)p*516 + t0 + tt + 1] = lv;
    }
    if (t0 == 0 && tid < 32) {
        Phi[base + (size_t)tid*516] = 0u; Plo[base + (size_t)tid*516] = 0u;
    }
    if (t0 == T-64 && tid < 96) {
        int p = tid/3, j = 513 + tid%3;
        Phi[base + (size_t)p*516 + j] = 0u; Plo[base + (size_t)p*516 + j] = 0u;
    }
}

// ---------------- fragment-direct bf16 mma GEMM/conv ---------------------------
#define LOADA(AH, AL, ct_, kp_, k16_) do { \
    size_t ab_ = ((size_t)(((kp_)*CT16 + (ct_)*4 + (k16_))*OTW + otW0 + oy)) << 8; \
    const uint4* Abh_ = (const uint4*)Whi + ab_; \
    const uint4* Abl_ = (const uint4*)Wlo + ab_; \
    _Pragma("unroll") \
    for (int mi_ = 0; mi_ < 4; mi_++) { \
        int s_ = (wm*4 + mi_)*32 + lane; \
        (AH)[mi_] = Abh_[s_]; (AL)[mi_] = Abl_[s_]; \
    } \
} while (0)

template<int KK, int NT>
__global__ __launch_bounds__(256, 1) void k_mma_f(
        const u32* __restrict__ Whi, const u32* __restrict__ Wlo,
        const u32* __restrict__ Xhi, const u32* __restrict__ Xlo,
        const float* __restrict__ bias,
        float* __restrict__ Y0, float* __restrict__ Y1,
        int Osplit, int Cin, int relu, int maskOut, int OTW, int otW0) {
    extern __shared__ char smc[];
    const int STG = 64*136;          // u32 per stage
    const int CHUNKS = 33;
    const int PAD = (KK - 1) / 2;
    u32 sb = smem_u32(smc);
    int tid = threadIdx.x, warp = tid >> 5, lane = tid & 31;
    int g = lane >> 2, tq = lane & 3;
    int wm = warp >> 2, wn = warp & 3;
    int t0 = blockIdx.x*NT, oy = blockIdx.y, b = blockIdx.z;
    int CT = Cin >> 6, CT16 = Cin >> 4;
    const float* mrow = g_mask + b*T;

    float acc[4][4][4];
#pragma unroll
    for (int mi = 0; mi < 4; mi++)
#pragma unroll
        for (int ni = 0; ni < 4; ni++)
#pragma unroll
            for (int q = 0; q < 4; q++) acc[mi][ni][q] = 0.f;

    // prologue: stages 0..2
#pragma unroll
    for (int st = 0; st < 3; st++) {
        size_t prow = (size_t)(b*CT + st)*32;
        for (int e = tid; e < 64*CHUNKS; e += 256) {
            int r = e / CHUNKS, cch = e - r*CHUNKS;
            const u32* src = ((r < 32) ? Xhi : Xlo) + (prow + (r & 31))*516 + t0 + cch*4;
            cp16(sb + (u32)(st*STG + r*136 + cch*4)*4, src);
        }
        asm volatile("cp.async.commit_group;" ::: "memory");
    }

    uint4 ahA[4], alA[4], ahB[4], alB[4];
    LOADA(ahA, alA, 0, 0, 0);

    for (int ct = 0; ct < CT; ct++) {
        asm volatile("cp.async.wait_group 2;" ::: "memory");
        __syncthreads();
        if (ct + 3 < CT) {
            int stg = (ct + 3) & 3;
            size_t prow = (size_t)(b*CT + ct + 3)*32;
            for (int e = tid; e < 64*CHUNKS; e += 256) {
                int r = e / CHUNKS, cch = e - r*CHUNKS;
                const u32* src = ((r < 32) ? Xhi : Xlo) + (prow + (r & 31))*516 + t0 + cch*4;
                cp16(sb + (u32)(stg*STG + r*136 + cch*4)*4, src);
            }
        }
        asm volatile("cp.async.commit_group;" ::: "memory");

        const u32* Bst = (const u32*)smc + (ct & 3)*STG;
#pragma unroll
        for (int kp = 0; kp < KK; kp++) {
            int ccoff = kp + 1 - PAD;
#pragma unroll
            for (int k16 = 0; k16 < 4; k16++) {
                const int ui = kp*4 + k16;
                const int nu = ui + 1;
                if (nu < KK*4) {
                    if ((ui & 1) == 0) LOADA(ahB, alB, ct, (nu >> 2), (nu & 3));
                    else               LOADA(ahA, alA, ct, (nu >> 2), (nu & 3));
                } else {
                    if (ct + 1 < CT) {
                        if ((ui & 1) == 0) LOADA(ahB, alB, ct + 1, 0, 0);
                        else               LOADA(ahA, alA, ct + 1, 0, 0);
                    }
                }
                int rb = k16*8;
#pragma unroll
                for (int ni = 0; ni < 4; ni++) {
                    int cc = wn*32 + ni*8 + g + ccoff;
                    u32 bh0 = Bst[(rb+tq)*136 + cc];
                    u32 bh1 = Bst[(rb+tq+4)*136 + cc];
                    u32 bl0 = Bst[(32+rb+tq)*136 + cc];
                    u32 bl1 = Bst[(32+rb+tq+4)*136 + cc];
#pragma unroll
                    for (int mi = 0; mi < 4; mi++) {
                        if ((ui & 1) == 0) {
                            mma16(acc[mi][ni], (const u32*)&alA[mi], bh0, bh1);
                            mma16(acc[mi][ni], (const u32*)&ahA[mi], bl0, bl1);
                            mma16(acc[mi][ni], (const u32*)&ahA[mi], bh0, bh1);
                        } else {
                            mma16(acc[mi][ni], (const u32*)&alB[mi], bh0, bh1);
                            mma16(acc[mi][ni], (const u32*)&ahB[mi], bl0, bl1);
                            mma16(acc[mi][ni], (const u32*)&ahB[mi], bh0, bh1);
                        }
                    }
                }
            }
        }
    }
    __syncthreads();
    // epilogue
#pragma unroll
    for (int mi = 0; mi < 4; mi++) {
#pragma unroll
        for (int half = 0; half < 2; half++) {
            int o = oy*128 + wm*64 + mi*16 + g + half*8;
            float bi = bias[o];
            float* Yp; size_t rowb;
            if (o < Osplit) { Yp = Y0; rowb = ((size_t)b*Osplit + o)*T; }
            else            { Yp = Y1; rowb = ((size_t)b*Osplit + (o - Osplit))*T; }
#pragma unroll
            for (int ni = 0; ni < 4; ni++) {
                int t = t0 + wn*32 + ni*8 + 2*tq;
                float v0 = acc[mi][ni][half*2 + 0] + bi;
                float v1 = acc[mi][ni][half*2 + 1] + bi;
                if (relu) { v0 = fmaxf(v0, 0.f); v1 = fmaxf(v1, 0.f); }
                if (maskOut) { v0 *= mrow[t]; v1 *= mrow[t+1]; }
                *(float2*)&Yp[rowb + t] = make_float2(v0, v1);
            }
        }
    }
}

// ---------------- scores = q@k^T (f32x2), fused-qkv input ----------------------
__global__ __launch_bounds__(256) void k_qk(const float* __restrict__ qkv,
                                            float* __restrict__ p) {
    __shared__ u64 Qd[128*35];
    __shared__ float Ks[32*68];
    int lid = threadIdx.x;
    int tx = lid & 7, ty = lid >> 3;
    int s0 = blockIdx.x*64, t0 = blockIdx.y*128;
    int bh = blockIdx.z, b = bh >> 3, h = bh & 7;
    const float* qb = qkv + ((size_t)b*1536 + h*DK)*T;
    const float* kb = qkv + ((size_t)b*1536 + 512 + h*DK)*T;
    u64 acc[4][4];
#pragma unroll
    for (int i = 0; i < 4; i++)
#pragma unroll
        for (int j = 0; j < 4; j++) acc[i][j] = 0ull;

    for (int d0 = 0; d0 < DK; d0 += 32) {
#pragma unroll
        for (int it = 0; it < 16; it++) {
            int e = lid + it*256; int dd = e >> 7, tt = e & 127;
            float v = qb[(size_t)(d0+dd)*T + t0 + tt];
            Qd[tt*35 + dd] = fpack2(v, v);
        }
#pragma unroll
        for (int it = 0; it < 8; it++) {
            int e = lid + it*256; int r = e >> 6, cc = e & 63;
            Ks[r*68 + cc] = kb[(size_t)(d0+r)*T + s0 + cc];
        }
        __syncthreads();
#pragma unroll
        for (int kk = 0; kk < 32; kk++) {
            ulonglong2 xa = *(const ulonglong2*)&Ks[kk*68 + tx*8];
            ulonglong2 xb = *(const ulonglong2*)&Ks[kk*68 + tx*8 + 4];
#pragma unroll
            for (int i = 0; i < 4; i++) {
                u64 w = Qd[(ty*4+i)*35 + kk];
                acc[i][0] = ffma2(w, xa.x, acc[i][0]);
                acc[i][1] = ffma2(w, xa.y, acc[i][1]);
                acc[i][2] = ffma2(w, xb.x, acc[i][2]);
                acc[i][3] = ffma2(w, xb.y, acc[i][3]);
            }
        }
        __syncthreads();
    }
#pragma unroll
    for (int i = 0; i < 4; i++) {
        int t = t0 + ty*4 + i;
        float2 p0 = funpack2(acc[i][0]), p1 = funpack2(acc[i][1]);
        float2 p2 = funpack2(acc[i][2]), p3 = funpack2(acc[i][3]);
        float4 r0 = make_float4(p0.x, p0.y, p1.x, p1.y);
        float4 r1 = make_float4(p2.x, p2.y, p3.x, p3.y);
        *(float4*)&p[((size_t)bh*T + t)*T + s0 + tx*8] = r0;
        *(float4*)&p[((size_t)bh*T + t)*T + s0 + tx*8 + 4] = r1;
    }
}

// ---------------- masked softmax with fused relative band ----------------------
__global__ void k_softmax(float* __restrict__ p, const float* __restrict__ qkv,
                          const float* __restrict__ rk) {
    int t = blockIdx.x, h = blockIdx.y, b = blockIdx.z;
    float* row = p + (((size_t)(b*H + h))*T + t)*T;
    int tid = threadIdx.x;
    int wid = tid >> 5, lane = tid & 31;
    __shared__ float band[NREL];
    const float* qb = qkv + ((size_t)b*1536 + h*DK)*T + t;
    float a0 = qb[(size_t)(2*lane)*T];
    float a1 = qb[(size_t)(2*lane + 1)*T];
    for (int dt = wid; dt < NREL; dt += 8) {
        float dot = a0*rk[dt*DK + 2*lane] + a1*rk[dt*DK + 2*lane + 1];
#pragma unroll
        for (int o = 16; o; o >>= 1) dot += __shfl_xor_sync(0xffffffffu, dot, o);
        if (!lane) band[dt] = dot;
    }
    __syncthreads();
    float mt = g_mask[b*T + t];
    float v0 = row[tid], v1 = row[tid+256];
    int d0i = tid - t + W, d1i = tid + 256 - t + W;
    if ((unsigned)d0i < NREL) v0 += band[d0i];
    if ((unsigned)d1i < NREL) v1 += band[d1i];
    if (mt * g_mask[b*T + tid]       == 0.f) v0 = -1e4f;
    if (mt * g_mask[b*T + tid + 256] == 0.f) v1 = -1e4f;
    float mx = fmaxf(v0, v1);
#pragma unroll
    for (int o = 16; o; o >>= 1) mx = fmaxf(mx, __shfl_xor_sync(0xffffffffu, mx, o));
    __shared__ float sm[8], ss[8];
    if (!lane) sm[wid] = mx;
    __syncthreads();
    mx = sm[0];
#pragma unroll
    for (int i = 1; i < 8; i++) mx = fmaxf(mx, sm[i]);
    float e0 = expf(v0 - mx), e1 = expf(v1 - mx);
    float s = e0 + e1;
#pragma unroll
    for (int o = 16; o; o >>= 1) s += __shfl_xor_sync(0xffffffffu, s, o);
    if (!lane) ss[wid] = s;
    __syncthreads();
    s = ss[0];
#pragma unroll
    for (int i = 1; i < 8; i++) s += ss[i];
    float inv = 1.f / s;
    row[tid]     = e0 * inv;
    row[tid+256] = e1 * inv;
}

// ---------------- ctx = p@v + band(p)@rel_v (f32x2) ----------------------------
__global__ __launch_bounds__(256) void k_ctx(const float* __restrict__ p,
                                             const float* __restrict__ qkv,
                                             float* __restrict__ ctx,
                                             const float* __restrict__ rv_g) {
    __shared__ u64 Vd[64*35];
    __shared__ float Ps[32*132];
    __shared__ u64 pbs[NREL*64];
    __shared__ u64 rvd[NREL*64];
    int lid = threadIdx.x;
    int tx = lid & 15, ty = lid >> 4;
    int t0 = blockIdx.x*128;
    int bh = blockIdx.y, b = bh >> 3, h = bh & 7;
    const float* vb = qkv + ((size_t)b*1536 + 1024 + h*DK)*T;
    const float* prow = p + (size_t)bh*T*T;

    for (int e = lid; e < NREL*64; e += 256) rvd[e] = fpack2(rv_g[e], rv_g[e]);
    for (int e = lid; e < NREL*64; e += 256) {
        int dt = e >> 6, tp = e & 63;
        int te = t0 + tp*2;
        int se = te + dt - W, so = se + 1;
        float a = (se >= 0 && se < T) ? prow[(size_t)te*T + se] : 0.f;
        float c = (so >= 0 && so < T) ? prow[(size_t)(te+1)*T + so] : 0.f;
        pbs[e] = fpack2(a, c);
    }

    u64 acc[4][4];
#pragma unroll
    for (int i = 0; i < 4; i++)
#pragma unroll
        for (int j = 0; j < 4; j++) acc[i][j] = 0ull;

    for (int s0 = 0; s0 < T; s0 += 32) {
#pragma unroll
        for (int it = 0; it < 8; it++) {
            int e = lid + it*256; int dd = e >> 5, sscol = e & 31;
            float val = vb[(size_t)dd*T + s0 + sscol];
            Vd[dd*35 + sscol] = fpack2(val, val);
        }
#pragma unroll
        for (int it = 0; it < 4; it++) {
            int u = lid + it*256; int sg = u & 7, tt = u >> 3;
            float4 pv = *(const float4*)&prow[(size_t)(t0+tt)*T + s0 + sg*4];
            Ps[(sg*4+0)*132 + tt] = pv.x;
            Ps[(sg*4+1)*132 + tt] = pv.y;
            Ps[(sg*4+2)*132 + tt] = pv.z;
            Ps[(sg*4+3)*132 + tt] = pv.w;
        }
        __syncthreads();
#pragma unroll
        for (int kk = 0; kk < 32; kk++) {
            ulonglong2 xa = *(const ulonglong2*)&Ps[kk*132 + tx*8];
            ulonglong2 xb = *(const ulonglong2*)&Ps[kk*132 + tx*8 + 4];
#pragma unroll
            for (int i = 0; i < 4; i++) {
                u64 w = Vd[(ty*4+i)*35 + kk];
                acc[i][0] = ffma2(w, xa.x, acc[i][0]);
                acc[i][1] = ffma2(w, xa.y, acc[i][1]);
                acc[i][2] = ffma2(w, xb.x, acc[i][2]);
                acc[i][3] = ffma2(w, xb.y, acc[i][3]);
            }
        }
        __syncthreads();
    }
#pragma unroll
    for (int dt = 0; dt < NREL; dt++) {
#pragma unroll
        for (int i = 0; i < 4; i++) {
            u64 w = rvd[dt*64 + ty*4 + i];
#pragma unroll
            for (int jp = 0; jp < 4; jp++)
                acc[i][jp] = ffma2(w, pbs[dt*64 + tx*4 + jp], acc[i][jp]);
        }
    }
#pragma unroll
    for (int i = 0; i < 4; i++) {
        float2 p0 = funpack2(acc[i][0]), p1 = funpack2(acc[i][1]);
        float2 p2 = funpack2(acc[i][2]), p3 = funpack2(acc[i][3]);
        float4 r0 = make_float4(p0.x, p0.y, p1.x, p1.y);
        float4 r1 = make_float4(p2.x, p2.y, p3.x, p3.y);
        size_t base = ((size_t)b*C + h*DK + ty*4 + i)*T + t0 + tx*8;
        *(float4*)&ctx[base]     = r0;
        *(float4*)&ctx[base + 4] = r1;
    }
}

// ---------------- channel LayerNorm -------------------------------------------
__global__ void k_ln(float* __restrict__ hbuf, const float* __restrict__ yv,
                     const float* __restrict__ g, const float* __restrict__ bb,
                     int maskOut) {
    int tx = threadIdx.x, ty = threadIdx.y;
    int t = blockIdx.x*32 + tx, b = blockIdx.y;
    float s = 0.f, s2 = 0.f;
    for (int c = ty; c < C; c += 8) {
        size_t idx = ((size_t)b*C + c)*T + t;
        float v = hbuf[idx] + yv[idx];
        s += v; s2 += v*v;
    }
    __shared__ float rs[8][32], rs2[8][32];
    rs[ty][tx] = s; rs2[ty][tx] = s2;
    __syncthreads();
    if (ty == 0) {
        for (int j = 1; j < 8; j++) { s += rs[j][tx]; s2 += rs2[j][tx]; }
        float m = s / C;
        float var = s2 / C - m*m;
        rs[0][tx] = m;
        rs2[0][tx] = rsqrtf(var + 1e-5f);
    }
    __syncthreads();
    float m = rs[0][tx], r = rs2[0][tx];
    float mk = maskOut ? g_mask[b*T + t] : 1.f;
    for (int c = ty; c < C; c += 8) {
        size_t idx = ((size_t)b*C + c)*T + t;
        float v = hbuf[idx] + yv[idx];
        hbuf[idx] = ((v - m)*r*g[c] + bb[c]) * mk;
    }
}

// ---------------- launch -------------------------------------------------------
extern "C" void kernel_launch(void* const* d_in, const int* in_sizes, int n_in,
                              void* d_out, int out_size) {
    const int*   x    = (const int*)d_in[0];
    const int*   xlen = (const int*)d_in[1];
    const float* emb  = (const float*)d_in[2];
    const float* Wq = (const float*)d_in[3],  *bq = (const float*)d_in[4];
    const float* Wk = (const float*)d_in[5],  *bk = (const float*)d_in[6];
    const float* Wv = (const float*)d_in[7],  *bv = (const float*)d_in[8];
    const float* Wo = (const float*)d_in[9],  *bo = (const float*)d_in[10];
    const float* rel_k = (const float*)d_in[11], *rel_v = (const float*)d_in[12];
    const float* ln1g = (const float*)d_in[13], *ln1b = (const float*)d_in[14];
    const float* ln2g = (const float*)d_in[15], *ln2b = (const float*)d_in[16];
    const float* w1 = (const float*)d_in[17], *b1 = (const float*)d_in[18];
    const float* w2 = (const float*)d_in[19], *b2 = (const float*)d_in[20];
    const float* pw = (const float*)d_in[21], *pbv = (const float*)d_in[22];
    float* out = (float*)d_out;
    size_t SZ = (size_t)B*C*T;

    float *ph,*pqkv,*pctx,*py,*pp,*pf,*pb3;
    u32 *x5h,*x5l,*x2h,*x2l,*wqh,*wql,*w1h,*w1l,*w2h,*w2l,*pjh,*pjl;
    cudaGetSymbolAddress((void**)&ph,   g_h);
    cudaGetSymbolAddress((void**)&pqkv, g_qkv);
    cudaGetSymbolAddress((void**)&pctx, g_ctx);
    cudaGetSymbolAddress((void**)&py,   g_y);
    cudaGetSymbolAddress((void**)&pp,   g_p);
    cudaGetSymbolAddress((void**)&pf,   g_f);
    cudaGetSymbolAddress((void**)&pb3,  g_b3);
    cudaGetSymbolAddress((void**)&x5h,  g_px512_hi);
    cudaGetSymbolAddress((void**)&x5l,  g_px512_lo);
    cudaGetSymbolAddress((void**)&x2h,  g_px2048_hi);
    cudaGetSymbolAddress((void**)&x2l,  g_px2048_lo);
    cudaGetSymbolAddress((void**)&wqh,  g_wqkvo_hi);
    cudaGetSymbolAddress((void**)&wql,  g_wqkvo_lo);
    cudaGetSymbolAddress((void**)&w1h,  g_w1_hi);
    cudaGetSymbolAddress((void**)&w1l,  g_w1_lo);
    cudaGetSymbolAddress((void**)&w2h,  g_w2_hi);
    cudaGetSymbolAddress((void**)&w2l,  g_w2_lo);
    cudaGetSymbolAddress((void**)&pjh,  g_pj_hi);
    cudaGetSymbolAddress((void**)&pjl,  g_pj_lo);

    const int SMB = 64*136*4*4;   // 139264 bytes, 4-stage B pipeline
    static int attr_set = 0;
    if (!attr_set) {
        cudaFuncSetAttribute(k_mma_f<1,128>, cudaFuncAttributeMaxDynamicSharedMemorySize, SMB);
        cudaFuncSetAttribute(k_mma_f<3,128>, cudaFuncAttributeMaxDynamicSharedMemorySize, SMB);
        attr_set = 1;
    }

    dim3 tb(32,8);
    k_embed<<<dim3(T/32, B), tb>>>(x, xlen, emb, out, out + 4*SZ);
    k_packwf<<<dim3(8, 32, 1), 256>>>(pw, 1.f, pjh, pjl, C, 1, 32, 8, 0);
    k_bias3<<<dim3(6, LYR), 256>>>(bq, bk, bv, pb3);

    for (int i = 0; i < LYR; i++) {
        // per-layer packs into reused (L2-hot) buffers
        k_packw4<<<dim3(4, 32, 4), 256>>>(Wq + (size_t)i*C*C, Wk + (size_t)i*C*C,
                                          Wv + (size_t)i*C*C, Wo + (size_t)i*C*C, wqh, wql);
        k_packwf<<<dim3(16, 32, 3), 256>>>(w1 + (size_t)i*DFF*C*3, 1.f, w1h, w1l, C*3, 3, 32, 16, 0);
        k_packwf<<<dim3(4, 128, 3), 256>>>(w2 + (size_t)i*C*DFF*3, 1.f, w2h, w2l, DFF*3, 3, 128, 4, 0);

        k_packx<<<dim3(8, 8, B), 256>>>(ph, x5h, x5l, C, 0);
        k_mma_f<1,128><<<dim3(4, 12, B), 256, SMB>>>(wqh, wql, x5h, x5l,
            pb3 + i*1536, pqkv, pqkv, 1536, C, 0, 0, 16, 0);
        k_qk<<<dim3(T/64, T/128, B*H), 256>>>(pqkv, pp);
        k_softmax<<<dim3(T, H, B), 256>>>(pp, pqkv, rel_k + (size_t)i*NREL*DK);
        k_ctx<<<dim3(T/128, B*H), 256>>>(pp, pqkv, pctx, rel_v + (size_t)i*NREL*DK);
        k_packx<<<dim3(8, 8, B), 256>>>(pctx, x5h, x5l, C, 0);
        k_mma_f<1,128><<<dim3(4, 4, B), 256, SMB>>>(wqh, wql, x5h, x5l,
            bo + i*C, py, py, C, C, 0, 0, 16, 12);
        k_ln<<<dim3(T/32, B), tb>>>(ph, py, ln1g + i*C, ln1b + i*C, 0);

        k_packx<<<dim3(8, 8, B), 256>>>(ph, x5h, x5l, C, 1);
        k_mma_f<3,128><<<dim3(4, 16, B), 256, SMB>>>(w1h, w1l, x5h, x5l,
            b1 + i*DFF, pf, pf, DFF, C, 1, 0, 16, 0);
        k_packx<<<dim3(8, 32, B), 256>>>(pf, x2h, x2l, DFF, 1);
        k_mma_f<3,128><<<dim3(4, 4, B), 256, SMB>>>(w2h, w2l, x2h, x2l,
            b2 + i*C, py, py, C, DFF, 0, 1, 4, 0);
        k_ln<<<dim3(T/32, B), tb>>>(ph, py, ln2g + i*C, ln2b + i*C, 1);
    }

    k_copy4<<<(B*C*T)/1024, 256>>>((const float4*)ph, (float4*)(out + SZ));
    k_packx<<<dim3(8, 8, B), 256>>>(ph, x5h, x5l, C, 0);
    k_mma_f<1,128><<<dim3(4, 8, B), 256, SMB>>>(pjh, pjl, x5h, x5l, pbv,
        out + 2*SZ, out + 3*SZ, 512, C, 0, 1, 8, 0);
}

// round 12
// speedup vs baseline: 1.0620x; 1.0620x over previous
#include <cuda_runtime.h>
#include <math.h>

#define B 8
#define T 512
#define C 512
#define DFF 2048
#define H 8
#define LYR 6
#define W 4
#define DK 64
#define NREL 9

typedef unsigned long long u64;
typedef unsigned int u32;

// ---------------- scratch ----------------------------------------------------
__device__ float g_h[B*C*T];
__device__ float g_qkv[B*3*C*T];
__device__ float g_ctx[B*C*T];
__device__ float g_y[B*C*T];
__device__ float g_f[B*DFF*T];
__device__ float g_mask[B*T];
__device__ float g_b3[3*C];
// activation panels, pair-major: [b][ct][pair 32][516], bf16x2 hi/lo
__device__ u32 g_px512_hi[B*8*32*516],   g_px512_lo[B*8*32*516];
__device__ u32 g_px2048_hi[B*32*32*516], g_px2048_lo[B*32*32*516];
// weight fragment arrays (per-layer reused => L2-resident)
__device__ u32 g_wqkv_hi[32*12*1024],  g_wqkv_lo[32*12*1024];
__device__ u32 g_wo_hi[32*4*1024],     g_wo_lo[32*4*1024];
__device__ u32 g_w1_hi[3*32*16*1024],  g_w1_lo[3*32*16*1024];
__device__ u32 g_w2_hi[3*128*4*1024],  g_w2_lo[3*128*4*1024];
__device__ u32 g_pj_hi[32*8*1024],     g_pj_lo[32*8*1024];

// ---------------- helpers ------------------------------------------------------
__device__ __forceinline__ u64 ffma2(u64 a, u64 b, u64 c) {
    u64 d; asm("fma.rn.f32x2 %0, %1, %2, %3;" : "=l"(d) : "l"(a), "l"(b), "l"(c));
    return d;
}
__device__ __forceinline__ u64 fpack2(float lo, float hi) {
    u64 d; asm("mov.b64 %0, {%1, %2};" : "=l"(d) : "f"(lo), "f"(hi));
    return d;
}
__device__ __forceinline__ float2 funpack2(u64 v) {
    float2 r; asm("mov.b64 {%0, %1}, %2;" : "=f"(r.x), "=f"(r.y) : "l"(v));
    return r;
}
__device__ __forceinline__ u32 bf2(float h, float l) {
    u32 r; asm("cvt.rn.bf16x2.f32 %0, %1, %2;" : "=r"(r) : "f"(h), "f"(l));
    return r;
}
__device__ __forceinline__ void mma16(float* d, const u32* a, u32 b0, u32 b1) {
    asm("mma.sync.aligned.m16n8k16.row.col.f32.bf16.bf16.f32 "
        "{%0,%1,%2,%3}, {%4,%5,%6,%7}, {%8,%9}, {%0,%1,%2,%3};"
        : "+f"(d[0]), "+f"(d[1]), "+f"(d[2]), "+f"(d[3])
        : "r"(a[0]), "r"(a[1]), "r"(a[2]), "r"(a[3]), "r"(b0), "r"(b1));
}
__device__ __forceinline__ u32 smem_u32(const void* p) {
    u32 a; asm("{ .reg .u64 t; cvta.to.shared.u64 t, %1; cvt.u32.u64 %0, t; }"
               : "=r"(a) : "l"(p));
    return a;
}
__device__ __forceinline__ void cp16(u32 dst, const void* src) {
    asm volatile("{ .reg .u64 g; cvta.to.global.u64 g, %1; "
                 "cp.async.cg.shared.global [%0], [g], 16; }"
                 :: "r"(dst), "l"(src) : "memory");
}

// ---------------- embedding + mask -------------------------------------------
__global__ void k_embed(const int* __restrict__ x, const int* __restrict__ xlen,
                        const float* __restrict__ emb,
                        float* __restrict__ out_xemb, float* __restrict__ out_mask) {
    int b = blockIdx.y;
    int t = blockIdx.x * 32 + threadIdx.x;
    int xi = x[b*T + t];
    float mk = (t < xlen[b]) ? 1.f : 0.f;
    const float SQ = 22.627416997969522f;
    for (int c = threadIdx.y; c < C; c += 8) {
        float v = emb[xi*C + c] * SQ;
        out_xemb[((size_t)b*C + c)*T + t] = v;
        g_h[((size_t)b*C + c)*T + t] = v * mk;
    }
    if (threadIdx.y == 0) {
        g_mask[b*T + t] = mk;
        out_mask[b*T + t] = mk;
    }
}

__global__ void k_copy4(const float4* __restrict__ src, float4* __restrict__ dst) {
    int i = blockIdx.x * 256 + threadIdx.x;
    dst[i] = src[i];
}

__global__ void k_bias3(const float* __restrict__ bq, const float* __restrict__ bk,
                        const float* __restrict__ bv, float* __restrict__ b3) {
    int i = blockIdx.x*256 + threadIdx.x;
    b3[i] = (i < 512) ? bq[i]*0.125f : (i < 1024 ? bk[i-512] : bv[i-1024]);
}

// ---------------- weight pack -> per-lane mma fragment order -------------------
__global__ void k_packwf(const float* __restrict__ Wm, float scale,
                         u32* __restrict__ hi, u32* __restrict__ lo,
                         int ostride, int KKf, int CT16, int OT, int otOff) {
    int ot = blockIdx.x, c16 = blockIdx.y, kp = blockIdx.z;
    int tid = threadIdx.x, s = tid >> 5, l = tid & 31;
    int g = l >> 2, tq = l & 3;
    int wm = s >> 2, mi = s & 3;
    int obase = ot*128 + wm*64 + mi*16 + g;
    u32 rh[4], rl[4];
#pragma unroll
    for (int r = 0; r < 4; r++) {
        int o = obase + (r & 1)*8;
        int pair = (r < 2) ? tq : tq + 4;
        int ce = c16*16 + 2*pair;
        float f0 = Wm[(size_t)o*ostride + (size_t)ce*KKf + kp] * scale;
        float f1 = Wm[(size_t)o*ostride + (size_t)(ce+1)*KKf + kp] * scale;
        u32 hv = bf2(f1, f0);
        float r0 = f0 - __uint_as_float(hv << 16);
        float r1 = f1 - __uint_as_float(hv & 0xffff0000u);
        rh[r] = hv; rl[r] = bf2(r1, r0);
    }
    size_t base = ((size_t)((kp*CT16 + c16)*OT + otOff + ot))*1024 + (s*32 + l)*4;
    *(uint4*)&hi[base] = make_uint4(rh[0], rh[1], rh[2], rh[3]);
    *(uint4*)&lo[base] = make_uint4(rl[0], rl[1], rl[2], rl[3]);
}

// ---------------- activation pack: f32 [b][c][t] -> pair-major padded panels ----
__global__ void k_packx(const float* __restrict__ X, u32* __restrict__ Phi,
                        u32* __restrict__ Plo, int Cin, int useMask) {
    __shared__ float tile[64][65];
    int t0 = blockIdx.x*64, ct = blockIdx.y, b = blockIdx.z;
    int CT = gridDim.y;
    int tid = threadIdx.x;
    int tx = tid & 63, ty = tid >> 6;
    float mk = useMask ? g_mask[b*T + t0 + tx] : 1.f;
#pragma unroll
    for (int i = 0; i < 16; i++) {
        int cc = ty + i*4;
        tile[cc][tx] = X[((size_t)b*Cin + ct*64 + cc)*T + t0 + tx] * mk;
    }
    __syncthreads();
    size_t base = (size_t)(b*CT + ct)*32*516;
#pragma unroll
    for (int i = 0; i < 8; i++) {
        int e = tid + i*256;
        int p = e >> 6, tt = e & 63;
        float f0 = tile[2*p][tt], f1 = tile[2*p+1][tt];
        u32 hv = bf2(f1, f0);
        float r0 = f0 - __uint_as_float(hv << 16);
        float r1 = f1 - __uint_as_float(hv & 0xffff0000u);
        Phi[base + (size_t)p*516 + t0 + tt + 1] = hv;
        Plo[base + (size_t)p*516 + t0 + tt + 1] = bf2(r1, r0);
    }
    if (t0 == 0 && tid < 32) {
        Phi[base + (size_t)tid*516] = 0u; Plo[base + (size_t)tid*516] = 0u;
    }
    if (t0 == T-64 && tid < 96) {
        int p = tid/3, j = 513 + tid%3;
        Phi[base + (size_t)p*516 + j] = 0u; Plo[base + (size_t)p*516 + j] = 0u;
    }
}

// ---------------- fragment-direct bf16 mma GEMM/conv ---------------------------
#define LOADA(AH, AL, ct_, kp_, k16_) do { \
    size_t ab_ = ((size_t)(((kp_)*CT16 + (ct_)*4 + (k16_))*OT + oy)) << 8; \
    const uint4* Abh_ = (const uint4*)Whi + ab_; \
    const uint4* Abl_ = (const uint4*)Wlo + ab_; \
    _Pragma("unroll") \
    for (int mi_ = 0; mi_ < 4; mi_++) { \
        int s_ = (wm*4 + mi_)*32 + lane; \
        (AH)[mi_] = Abh_[s_]; (AL)[mi_] = Abl_[s_]; \
    } \
} while (0)

template<int KK, int NT>
__global__ __launch_bounds__(256, 1) void k_mma_f(
        const u32* __restrict__ Whi, const u32* __restrict__ Wlo,
        const u32* __restrict__ Xhi, const u32* __restrict__ Xlo,
        const float* __restrict__ bias,
        float* __restrict__ Y0, float* __restrict__ Y1,
        int Osplit, int Cin, int relu, int maskOut) {
    extern __shared__ char smc[];
    const int STG = 64*136;          // u32 per stage
    const int CHUNKS = 33;
    const int PAD = (KK - 1) / 2;
    u32 sb = smem_u32(smc);
    int tid = threadIdx.x, warp = tid >> 5, lane = tid & 31;
    int g = lane >> 2, tq = lane & 3;
    int wm = warp >> 2, wn = warp & 3;
    int t0 = blockIdx.x*NT, oy = blockIdx.y, b = blockIdx.z;
    int OT = gridDim.y;
    int CT = Cin >> 6, CT16 = Cin >> 4;
    const float* mrow = g_mask + b*T;

    float acc[4][4][4];
#pragma unroll
    for (int mi = 0; mi < 4; mi++)
#pragma unroll
        for (int ni = 0; ni < 4; ni++)
#pragma unroll
            for (int q = 0; q < 4; q++) acc[mi][ni][q] = 0.f;

    // prologue: stages 0..2
#pragma unroll
    for (int st = 0; st < 3; st++) {
        size_t prow = (size_t)(b*CT + st)*32;
        for (int e = tid; e < 64*CHUNKS; e += 256) {
            int r = e / CHUNKS, cch = e - r*CHUNKS;
            const u32* src = ((r < 32) ? Xhi : Xlo) + (prow + (r & 31))*516 + t0 + cch*4;
            cp16(sb + (u32)(st*STG + r*136 + cch*4)*4, src);
        }
        asm volatile("cp.async.commit_group;" ::: "memory");
    }

    uint4 ahA[4], alA[4], ahB[4], alB[4];
    LOADA(ahA, alA, 0, 0, 0);

    for (int ct = 0; ct < CT; ct++) {
        asm volatile("cp.async.wait_group 2;" ::: "memory");
        __syncthreads();
        if (ct + 3 < CT) {
            int stg = (ct + 3) & 3;
            size_t prow = (size_t)(b*CT + ct + 3)*32;
            for (int e = tid; e < 64*CHUNKS; e += 256) {
                int r = e / CHUNKS, cch = e - r*CHUNKS;
                const u32* src = ((r < 32) ? Xhi : Xlo) + (prow + (r & 31))*516 + t0 + cch*4;
                cp16(sb + (u32)(stg*STG + r*136 + cch*4)*4, src);
            }
        }
        asm volatile("cp.async.commit_group;" ::: "memory");

        const u32* Bst = (const u32*)smc + (ct & 3)*STG;
#pragma unroll
        for (int kp = 0; kp < KK; kp++) {
            int ccoff = kp + 1 - PAD;
#pragma unroll
            for (int k16 = 0; k16 < 4; k16++) {
                const int ui = kp*4 + k16;
                const int nu = ui + 1;
                if (nu < KK*4) {
                    if ((ui & 1) == 0) LOADA(ahB, alB, ct, (nu >> 2), (nu & 3));
                    else               LOADA(ahA, alA, ct, (nu >> 2), (nu & 3));
                } else {
                    if (ct + 1 < CT) {
                        if ((ui & 1) == 0) LOADA(ahB, alB, ct + 1, 0, 0);
                        else               LOADA(ahA, alA, ct + 1, 0, 0);
                    }
                }
                int rb = k16*8;
#pragma unroll
                for (int ni = 0; ni < 4; ni++) {
                    int cc = wn*32 + ni*8 + g + ccoff;
                    u32 bh0 = Bst[(rb+tq)*136 + cc];
                    u32 bh1 = Bst[(rb+tq+4)*136 + cc];
                    u32 bl0 = Bst[(32+rb+tq)*136 + cc];
                    u32 bl1 = Bst[(32+rb+tq+4)*136 + cc];
#pragma unroll
                    for (int mi = 0; mi < 4; mi++) {
                        if ((ui & 1) == 0) {
                            mma16(acc[mi][ni], (const u32*)&alA[mi], bh0, bh1);
                            mma16(acc[mi][ni], (const u32*)&ahA[mi], bl0, bl1);
                            mma16(acc[mi][ni], (const u32*)&ahA[mi], bh0, bh1);
                        } else {
                            mma16(acc[mi][ni], (const u32*)&alB[mi], bh0, bh1);
                            mma16(acc[mi][ni], (const u32*)&ahB[mi], bl0, bl1);
                            mma16(acc[mi][ni], (const u32*)&ahB[mi], bh0, bh1);
                        }
                    }
                }
            }
        }
    }
    __syncthreads();
    // epilogue
#pragma unroll
    for (int mi = 0; mi < 4; mi++) {
#pragma unroll
        for (int half = 0; half < 2; half++) {
            int o = oy*128 + wm*64 + mi*16 + g + half*8;
            float bi = bias[o];
            float* Yp; size_t rowb;
            if (o < Osplit) { Yp = Y0; rowb = ((size_t)b*Osplit + o)*T; }
            else            { Yp = Y1; rowb = ((size_t)b*Osplit + (o - Osplit))*T; }
#pragma unroll
            for (int ni = 0; ni < 4; ni++) {
                int t = t0 + wn*32 + ni*8 + 2*tq;
                float v0 = acc[mi][ni][half*2 + 0] + bi;
                float v1 = acc[mi][ni][half*2 + 1] + bi;
                if (relu) { v0 = fmaxf(v0, 0.f); v1 = fmaxf(v1, 0.f); }
                if (maskOut) { v0 *= mrow[t]; v1 *= mrow[t+1]; }
                *(float2*)&Yp[rowb + t] = make_float2(v0, v1);
            }
        }
    }
}

// ---------------- fused flash attention (qk + band + softmax + ctx) ------------
// grid (T/128, B*H), 256 threads. Online softmax over s-chunks of 64.
#define FSM_TOTAL 155936
__global__ __launch_bounds__(256, 1) void k_flash(
        const float* __restrict__ qkv, float* __restrict__ ctx,
        const float* __restrict__ rk_g, const float* __restrict__ rv_g) {
    extern __shared__ char fsm[];
    u64*   Qd   = (u64*)(fsm);                 // [128][67] dup'd q
    float* Ks   = (float*)(fsm + 68608);       // [64][68]
    float* Ps   = (float*)(fsm + 86016);       // [64][132]
    u64*   Vd   = (u64*)(fsm + 119808);        // [64][33]
    float* bnd  = (float*)(fsm + 136704);      // [128][10] q.rel_k
    float* bacc = (float*)(fsm + 141824);      // [128][10] band e-acc
    float* rks  = (float*)(fsm + 146944);      // [9][68]
    float* rvs  = (float*)(fsm + 149392);      // [9][68]
    float* ms   = (float*)(fsm + 151840);      // [512] mask(s)
    float* mtv  = (float*)(fsm + 153888);      // [128] mask(t)
    float* mro  = (float*)(fsm + 154400);      // running max [128]
    float* ssum = (float*)(fsm + 154912);      // running sum [128]
    float* scal = (float*)(fsm + 155424);      // chunk rescale [128]

    int lid = threadIdx.x;
    int t0 = blockIdx.x * 128;
    int bh = blockIdx.y, b = bh >> 3, h = bh & 7;
    const float* qb = qkv + ((size_t)b*1536 + h*DK)*T;
    const float* kb = qkv + ((size_t)b*1536 + 512 + h*DK)*T;
    const float* vb = qkv + ((size_t)b*1536 + 1024 + h*DK)*T;
    int txq = lid & 7,  tyq = lid >> 3;   // score map: 4t x 8s
    int txc = lid & 15, tyc = lid >> 4;   // pv map: 4d x 4 t-pairs

#pragma unroll
    for (int it = 0; it < 32; it++) {
        int e = lid + it*256;
        int tloc = e & 127, dd = e >> 7;
        float v = qb[(size_t)dd*T + t0 + tloc];
        Qd[tloc*67 + dd] = fpack2(v, v);
    }
    for (int e = lid; e < 9*64; e += 256) {
        rks[(e >> 6)*68 + (e & 63)] = rk_g[e];
        rvs[(e >> 6)*68 + (e & 63)] = rv_g[e];
    }
    for (int e = lid; e < T; e += 256) ms[e] = g_mask[b*T + e];
    if (lid < 128) {
        mtv[lid] = g_mask[b*T + t0 + lid];
        mro[lid] = -3.4e38f;
        ssum[lid] = 0.f;
    }
    for (int e = lid; e < 128*10; e += 256) bacc[e] = 0.f;
    __syncthreads();
    for (int e = lid; e < 128*9; e += 256) {
        int t = e / 9, dt = e - t*9;
        float dot = 0.f;
#pragma unroll
        for (int d = 0; d < 64; d++)
            dot += funpack2(Qd[t*67 + d]).x * rks[dt*68 + d];
        bnd[t*10 + dt] = dot;
    }

    u64 oacc[4][4];
#pragma unroll
    for (int i = 0; i < 4; i++)
#pragma unroll
        for (int j = 0; j < 4; j++) oacc[i][j] = 0ull;

    for (int s0 = 0; s0 < T; s0 += 64) {
        __syncthreads();
#pragma unroll
        for (int it = 0; it < 16; it++) {
            int e = lid + it*256;
            int dd = e >> 6, ss = e & 63;
            Ks[dd*68 + ss] = kb[(size_t)dd*T + s0 + ss];
        }
        __syncthreads();
        // score GEMM 128t x 64s
        u64 sacc[4][4];
#pragma unroll
        for (int i = 0; i < 4; i++)
#pragma unroll
            for (int j = 0; j < 4; j++) sacc[i][j] = 0ull;
#pragma unroll 16
        for (int kk = 0; kk < 64; kk++) {
            ulonglong2 xa = *(const ulonglong2*)&Ks[kk*68 + txq*8];
            ulonglong2 xb = *(const ulonglong2*)&Ks[kk*68 + txq*8 + 4];
#pragma unroll
            for (int i = 0; i < 4; i++) {
                u64 w = Qd[(tyq*4+i)*67 + kk];
                sacc[i][0] = ffma2(w, xa.x, sacc[i][0]);
                sacc[i][1] = ffma2(w, xa.y, sacc[i][1]);
                sacc[i][2] = ffma2(w, xb.x, sacc[i][2]);
                sacc[i][3] = ffma2(w, xb.y, sacc[i][3]);
            }
        }
        // unpack + band + mask + row max
        float sv[4][8];
#pragma unroll
        for (int i = 0; i < 4; i++) {
            int tl = tyq*4 + i;
            float mt = mtv[tl];
            float rmax = -3.4e38f;
#pragma unroll
            for (int jp = 0; jp < 4; jp++) {
                float2 f = funpack2(sacc[i][jp]);
                sv[i][2*jp] = f.x; sv[i][2*jp+1] = f.y;
            }
#pragma unroll
            for (int j = 0; j < 8; j++) {
                int sg = s0 + txq*8 + j;
                float v = sv[i][j];
                int dtix = sg - (t0 + tl) + W;
                if ((unsigned)dtix < 9u) v += bnd[tl*10 + dtix];
                if (mt * ms[sg] == 0.f) v = -1e4f;
                sv[i][j] = v;
                rmax = fmaxf(rmax, v);
            }
#pragma unroll
            for (int o = 1; o <= 4; o <<= 1)
                rmax = fmaxf(rmax, __shfl_xor_sync(0xffffffffu, rmax, o));
            if (txq == 0) {
                float old = mro[tl];
                float nm = fmaxf(old, rmax);
                scal[tl] = expf(old - nm);
                mro[tl] = nm;
            }
        }
        __syncthreads();
        // exp + chunk sums + Ps (transposed [s][t])
#pragma unroll
        for (int i = 0; i < 4; i++) {
            int tl = tyq*4 + i;
            float nm = mro[tl];
            float cs = 0.f;
#pragma unroll
            for (int j = 0; j < 8; j++) {
                float e = expf(sv[i][j] - nm);
                cs += e;
                Ps[(txq*8 + j)*132 + tl] = e;
            }
#pragma unroll
            for (int o = 1; o <= 4; o <<= 1)
                cs += __shfl_xor_sync(0xffffffffu, cs, o);
            if (txq == 0) ssum[tl] = ssum[tl]*scal[tl] + cs;
        }
        __syncthreads();
        // band e-acc update (rescale + in-chunk add)
        for (int e = lid; e < 128*9; e += 256) {
            int t = e / 9, dt = e - t*9;
            float v = bacc[t*10 + dt] * scal[t];
            int sg = t0 + t + dt - W;
            if (sg >= s0 && sg < s0 + 64) v += Ps[(sg - s0)*132 + t];
            bacc[t*10 + dt] = v;
        }
        // rescale output accumulators
#pragma unroll
        for (int jp = 0; jp < 4; jp++) {
            int tp = txc*4 + jp;
            float se = scal[2*tp], so = scal[2*tp + 1];
#pragma unroll
            for (int i = 0; i < 4; i++) {
                float2 f = funpack2(oacc[i][jp]);
                oacc[i][jp] = fpack2(f.x*se, f.y*so);
            }
        }
        // PV over two 32-s subchunks
#pragma unroll
        for (int sub = 0; sub < 2; sub++) {
            __syncthreads();
#pragma unroll
            for (int it = 0; it < 8; it++) {
                int e = lid + it*256;
                int dd = e >> 5, ss = e & 31;
                float v = vb[(size_t)dd*T + s0 + sub*32 + ss];
                Vd[dd*33 + ss] = fpack2(v, v);
            }
            __syncthreads();
#pragma unroll 8
            for (int kk = 0; kk < 32; kk++) {
                ulonglong2 xa = *(const ulonglong2*)&Ps[(sub*32+kk)*132 + txc*8];
                ulonglong2 xb = *(const ulonglong2*)&Ps[(sub*32+kk)*132 + txc*8 + 4];
#pragma unroll
                for (int i = 0; i < 4; i++) {
                    u64 w = Vd[(tyc*4+i)*33 + kk];
                    oacc[i][0] = ffma2(w, xa.x, oacc[i][0]);
                    oacc[i][1] = ffma2(w, xa.y, oacc[i][1]);
                    oacc[i][2] = ffma2(w, xb.x, oacc[i][2]);
                    oacc[i][3] = ffma2(w, xb.y, oacc[i][3]);
                }
            }
        }
    }
    __syncthreads();
    // epilogue: + band@rel_v, normalize, store
#pragma unroll
    for (int jp = 0; jp < 4; jp++) {
        int tp = txc*4 + jp;
        float inve = 1.f / ssum[2*tp];
        float invo = 1.f / ssum[2*tp + 1];
#pragma unroll
        for (int i = 0; i < 4; i++) {
            int d = tyc*4 + i;
            float be = 0.f, bo = 0.f;
#pragma unroll
            for (int dt = 0; dt < 9; dt++) {
                float rv = rvs[dt*68 + d];
                be += bacc[(2*tp)*10 + dt]   * rv;
                bo += bacc[(2*tp+1)*10 + dt] * rv;
            }
            float2 f = funpack2(oacc[i][jp]);
            *(float2*)&ctx[((size_t)b*C + h*DK + d)*T + t0 + 2*tp] =
                make_float2((f.x + be)*inve, (f.y + bo)*invo);
        }
    }
}

// ---------------- channel LayerNorm -------------------------------------------
__global__ void k_ln(float* __restrict__ hbuf, const float* __restrict__ yv,
                     const float* __restrict__ g, const float* __restrict__ bb,
                     int maskOut) {
    int tx = threadIdx.x, ty = threadIdx.y;
    int t = blockIdx.x*32 + tx, b = blockIdx.y;
    float s = 0.f, s2 = 0.f;
    for (int c = ty; c < C; c += 8) {
        size_t idx = ((size_t)b*C + c)*T + t;
        float v = hbuf[idx] + yv[idx];
        s += v; s2 += v*v;
    }
    __shared__ float rs[8][32], rs2[8][32];
    rs[ty][tx] = s; rs2[ty][tx] = s2;
    __syncthreads();
    if (ty == 0) {
        for (int j = 1; j < 8; j++) { s += rs[j][tx]; s2 += rs2[j][tx]; }
        float m = s / C;
        float var = s2 / C - m*m;
        rs[0][tx] = m;
        rs2[0][tx] = rsqrtf(var + 1e-5f);
    }
    __syncthreads();
    float m = rs[0][tx], r = rs2[0][tx];
    float mk = maskOut ? g_mask[b*T + t] : 1.f;
    for (int c = ty; c < C; c += 8) {
        size_t idx = ((size_t)b*C + c)*T + t;
        float v = hbuf[idx] + yv[idx];
        hbuf[idx] = ((v - m)*r*g[c] + bb[c]) * mk;
    }
}

// ---------------- launch -------------------------------------------------------
extern "C" void kernel_launch(void* const* d_in, const int* in_sizes, int n_in,
                              void* d_out, int out_size) {
    const int*   x    = (const int*)d_in[0];
    const int*   xlen = (const int*)d_in[1];
    const float* emb  = (const float*)d_in[2];
    const float* Wq = (const float*)d_in[3],  *bq = (const float*)d_in[4];
    const float* Wk = (const float*)d_in[5],  *bk = (const float*)d_in[6];
    const float* Wv = (const float*)d_in[7],  *bv = (const float*)d_in[8];
    const float* Wo = (const float*)d_in[9],  *bo = (const float*)d_in[10];
    const float* rel_k = (const float*)d_in[11], *rel_v = (const float*)d_in[12];
    const float* ln1g = (const float*)d_in[13], *ln1b = (const float*)d_in[14];
    const float* ln2g = (const float*)d_in[15], *ln2b = (const float*)d_in[16];
    const float* w1 = (const float*)d_in[17], *b1 = (const float*)d_in[18];
    const float* w2 = (const float*)d_in[19], *b2 = (const float*)d_in[20];
    const float* pw = (const float*)d_in[21], *pbv = (const float*)d_in[22];
    float* out = (float*)d_out;
    size_t SZ = (size_t)B*C*T;

    float *ph,*pqkv,*pctx,*py,*pf,*pb3;
    u32 *x5h,*x5l,*x2h,*x2l,*wqh,*wql,*woh,*wol,*w1h,*w1l,*w2h,*w2l,*pjh,*pjl;
    cudaGetSymbolAddress((void**)&ph,   g_h);
    cudaGetSymbolAddress((void**)&pqkv, g_qkv);
    cudaGetSymbolAddress((void**)&pctx, g_ctx);
    cudaGetSymbolAddress((void**)&py,   g_y);
    cudaGetSymbolAddress((void**)&pf,   g_f);
    cudaGetSymbolAddress((void**)&pb3,  g_b3);
    cudaGetSymbolAddress((void**)&x5h,  g_px512_hi);
    cudaGetSymbolAddress((void**)&x5l,  g_px512_lo);
    cudaGetSymbolAddress((void**)&x2h,  g_px2048_hi);
    cudaGetSymbolAddress((void**)&x2l,  g_px2048_lo);
    cudaGetSymbolAddress((void**)&wqh,  g_wqkv_hi);
    cudaGetSymbolAddress((void**)&wql,  g_wqkv_lo);
    cudaGetSymbolAddress((void**)&woh,  g_wo_hi);
    cudaGetSymbolAddress((void**)&wol,  g_wo_lo);
    cudaGetSymbolAddress((void**)&w1h,  g_w1_hi);
    cudaGetSymbolAddress((void**)&w1l,  g_w1_lo);
    cudaGetSymbolAddress((void**)&w2h,  g_w2_hi);
    cudaGetSymbolAddress((void**)&w2l,  g_w2_lo);
    cudaGetSymbolAddress((void**)&pjh,  g_pj_hi);
    cudaGetSymbolAddress((void**)&pjl,  g_pj_lo);

    const int SMB = 64*136*4*4;   // 139264 bytes, 4-stage B pipeline
    static int attr_set = 0;
    if (!attr_set) {
        cudaFuncSetAttribute(k_mma_f<1,128>, cudaFuncAttributeMaxDynamicSharedMemorySize, SMB);
        cudaFuncSetAttribute(k_mma_f<3,128>, cudaFuncAttributeMaxDynamicSharedMemorySize, SMB);
        cudaFuncSetAttribute(k_flash, cudaFuncAttributeMaxDynamicSharedMemorySize, FSM_TOTAL);
        attr_set = 1;
    }

    dim3 tb(32,8);
    k_embed<<<dim3(T/32, B), dim3(32,8)>>>(x, xlen, emb, out, out + 4*SZ);
    k_packwf<<<dim3(8, 32, 1), 256>>>(pw, 1.f, pjh, pjl, C, 1, 32, 8, 0);

    for (int i = 0; i < LYR; i++) {
        k_packwf<<<dim3(4, 32, 1), 256>>>(Wq + (size_t)i*C*C, 0.125f, wqh, wql, C, 1, 32, 12, 0);
        k_packwf<<<dim3(4, 32, 1), 256>>>(Wk + (size_t)i*C*C, 1.f,    wqh, wql, C, 1, 32, 12, 4);
        k_packwf<<<dim3(4, 32, 1), 256>>>(Wv + (size_t)i*C*C, 1.f,    wqh, wql, C, 1, 32, 12, 8);
        k_packwf<<<dim3(4, 32, 1), 256>>>(Wo + (size_t)i*C*C, 1.f,    woh, wol, C, 1, 32, 4, 0);
        k_packwf<<<dim3(16, 32, 3), 256>>>(w1 + (size_t)i*DFF*C*3, 1.f, w1h, w1l, C*3, 3, 32, 16, 0);
        k_packwf<<<dim3(4, 128, 3), 256>>>(w2 + (size_t)i*C*DFF*3, 1.f, w2h, w2l, DFF*3, 3, 128, 4, 0);
        k_bias3<<<6, 256>>>(bq + i*C, bk + i*C, bv + i*C, pb3);

        k_packx<<<dim3(8, 8, B), 256>>>(ph, x5h, x5l, C, 0);
        k_mma_f<1,128><<<dim3(4, 12, B), 256, SMB>>>(wqh, wql, x5h, x5l, pb3,
            pqkv, pqkv, 1536, C, 0, 0);
        k_flash<<<dim3(T/128, B*H), 256, FSM_TOTAL>>>(pqkv, pctx,
            rel_k + (size_t)i*NREL*DK, rel_v + (size_t)i*NREL*DK);
        k_packx<<<dim3(8, 8, B), 256>>>(pctx, x5h, x5l, C, 0);
        k_mma_f<1,128><<<dim3(4, 4, B), 256, SMB>>>(woh, wol, x5h, x5l, bo + i*C,
            py, py, C, C, 0, 0);
        k_ln<<<dim3(T/32, B), tb>>>(ph, py, ln1g + i*C, ln1b + i*C, 0);

        k_packx<<<dim3(8, 8, B), 256>>>(ph, x5h, x5l, C, 1);
        k_mma_f<3,128><<<dim3(4, 16, B), 256, SMB>>>(w1h, w1l, x5h, x5l, b1 + i*DFF,
            pf, pf, DFF, C, 1, 0);
        k_packx<<<dim3(8, 32, B), 256>>>(pf, x2h, x2l, DFF, 1);
        k_mma_f<3,128><<<dim3(4, 4, B), 256, SMB>>>(w2h, w2l, x2h, x2l, b2 + i*C,
            py, py, C, DFF, 0, 1);
        k_ln<<<dim3(T/32, B), tb>>>(ph, py, ln2g + i*C, ln2b + i*C, 1);
    }

    k_copy4<<<(B*C*T)/1024, 256>>>((const float4*)ph, (float4*)(out + SZ));
    k_packx<<<dim3(8, 8, B), 256>>>(ph, x5h, x5l, C, 0);
    k_mma_f<1,128><<<dim3(4, 8, B), 256, SMB>>>(pjh, pjl, x5h, x5l, pbv,
        out + 2*SZ, out + 3*SZ, 512, C, 0, 1);
}

// round 13
// speedup vs baseline: 1.0701x; 1.0076x over previous
#include <cuda_runtime.h>
#include <math.h>

#define B 8
#define T 512
#define C 512
#define DFF 2048
#define H 8
#define LYR 6
#define W 4
#define DK 64
#define NREL 9

typedef unsigned long long u64;
typedef unsigned int u32;

// ---------------- scratch ----------------------------------------------------
__device__ float g_h[B*C*T];
__device__ float g_qkv[B*3*C*T];
__device__ float g_y[B*C*T];
__device__ float g_mask[B*T];
__device__ float g_b3[LYR*3*C];
// activation panels, pair-major: [b][ct][pair 32][516], bf16x2 hi/lo
__device__ u32 g_px512_hi[B*8*32*516],   g_px512_lo[B*8*32*516];
__device__ u32 g_px2048_hi[B*32*32*516], g_px2048_lo[B*32*32*516];
// weight fragment arrays (per-layer reused => L2-resident)
__device__ u32 g_wqkv_hi[32*12*1024],  g_wqkv_lo[32*12*1024];
__device__ u32 g_wo_hi[32*4*1024],     g_wo_lo[32*4*1024];
__device__ u32 g_w1_hi[3*32*16*1024],  g_w1_lo[3*32*16*1024];
__device__ u32 g_w2_hi[3*128*4*1024],  g_w2_lo[3*128*4*1024];
__device__ u32 g_pj_hi[32*8*1024],     g_pj_lo[32*8*1024];

// ---------------- helpers ------------------------------------------------------
__device__ __forceinline__ u64 ffma2(u64 a, u64 b, u64 c) {
    u64 d; asm("fma.rn.f32x2 %0, %1, %2, %3;" : "=l"(d) : "l"(a), "l"(b), "l"(c));
    return d;
}
__device__ __forceinline__ u64 fpack2(float lo, float hi) {
    u64 d; asm("mov.b64 %0, {%1, %2};" : "=l"(d) : "f"(lo), "f"(hi));
    return d;
}
__device__ __forceinline__ float2 funpack2(u64 v) {
    float2 r; asm("mov.b64 {%0, %1}, %2;" : "=f"(r.x), "=f"(r.y) : "l"(v));
    return r;
}
__device__ __forceinline__ u32 bf2(float h, float l) {
    u32 r; asm("cvt.rn.bf16x2.f32 %0, %1, %2;" : "=r"(r) : "f"(h), "f"(l));
    return r;
}
__device__ __forceinline__ void split2(float f0, float f1, u32& hv, u32& lv) {
    hv = bf2(f1, f0);
    float r0 = f0 - __uint_as_float(hv << 16);
    float r1 = f1 - __uint_as_float(hv & 0xffff0000u);
    lv = bf2(r1, r0);
}
__device__ __forceinline__ void mma16(float* d, const u32* a, u32 b0, u32 b1) {
    asm("mma.sync.aligned.m16n8k16.row.col.f32.bf16.bf16.f32 "
        "{%0,%1,%2,%3}, {%4,%5,%6,%7}, {%8,%9}, {%0,%1,%2,%3};"
        : "+f"(d[0]), "+f"(d[1]), "+f"(d[2]), "+f"(d[3])
        : "r"(a[0]), "r"(a[1]), "r"(a[2]), "r"(a[3]), "r"(b0), "r"(b1));
}
__device__ __forceinline__ u32 smem_u32(const void* p) {
    u32 a; asm("{ .reg .u64 t; cvta.to.shared.u64 t, %1; cvt.u32.u64 %0, t; }"
               : "=r"(a) : "l"(p));
    return a;
}
__device__ __forceinline__ void cp16(u32 dst, const void* src) {
    asm volatile("{ .reg .u64 g; cvta.to.global.u64 g, %1; "
                 "cp.async.cg.shared.global [%0], [g], 16; }"
                 :: "r"(dst), "l"(src) : "memory");
}

// ---------------- pad zeroing for the x2048 panel (written by conv1 epilogue) --
__global__ void k_zpad() {
    int r = blockIdx.x*256 + threadIdx.x;   // B*32*32 = 8192 rows
    if (r >= 8192) return;
    size_t base = (size_t)r * 516;
    g_px2048_hi[base] = 0u;     g_px2048_lo[base] = 0u;
    g_px2048_hi[base+513] = 0u; g_px2048_lo[base+513] = 0u;
    g_px2048_hi[base+514] = 0u; g_px2048_lo[base+514] = 0u;
    g_px2048_hi[base+515] = 0u; g_px2048_lo[base+515] = 0u;
}

// ---------------- embedding + mask -------------------------------------------
__global__ void k_embed(const int* __restrict__ x, const int* __restrict__ xlen,
                        const float* __restrict__ emb,
                        float* __restrict__ out_xemb, float* __restrict__ out_mask) {
    int b = blockIdx.y;
    int t = blockIdx.x * 32 + threadIdx.x;
    int xi = x[b*T + t];
    float mk = (t < xlen[b]) ? 1.f : 0.f;
    const float SQ = 22.627416997969522f;
    for (int c = threadIdx.y; c < C; c += 8) {
        float v = emb[xi*C + c] * SQ;
        out_xemb[((size_t)b*C + c)*T + t] = v;
        g_h[((size_t)b*C + c)*T + t] = v * mk;
    }
    if (threadIdx.y == 0) {
        g_mask[b*T + t] = mk;
        out_mask[b*T + t] = mk;
    }
}

__global__ void k_copy4(const float4* __restrict__ src, float4* __restrict__ dst) {
    int i = blockIdx.x * 256 + threadIdx.x;
    dst[i] = src[i];
}

__global__ void k_bias3(const float* __restrict__ bq, const float* __restrict__ bk,
                        const float* __restrict__ bv, float* __restrict__ b3) {
    int l = blockIdx.y;
    int i = blockIdx.x*256 + threadIdx.x;
    float v;
    if (i < 512)       v = bq[l*C + i] * 0.125f;
    else if (i < 1024) v = bk[l*C + i - 512];
    else               v = bv[l*C + i - 1024];
    b3[l*1536 + i] = v;
}

// ---------------- weight pack -> per-lane mma fragment order -------------------
__global__ void k_packwf(const float* __restrict__ Wm, float scale,
                         u32* __restrict__ hi, u32* __restrict__ lo,
                         int ostride, int KKf, int CT16, int OT, int otOff) {
    int ot = blockIdx.x, c16 = blockIdx.y, kp = blockIdx.z;
    int tid = threadIdx.x, s = tid >> 5, l = tid & 31;
    int g = l >> 2, tq = l & 3;
    int wm = s >> 2, mi = s & 3;
    int obase = ot*128 + wm*64 + mi*16 + g;
    u32 rh[4], rl[4];
#pragma unroll
    for (int r = 0; r < 4; r++) {
        int o = obase + (r & 1)*8;
        int pair = (r < 2) ? tq : tq + 4;
        int ce = c16*16 + 2*pair;
        float f0 = Wm[(size_t)o*ostride + (size_t)ce*KKf + kp] * scale;
        float f1 = Wm[(size_t)o*ostride + (size_t)(ce+1)*KKf + kp] * scale;
        split2(f0, f1, rh[r], rl[r]);
    }
    size_t base = ((size_t)((kp*CT16 + c16)*OT + otOff + ot))*1024 + (s*32 + l)*4;
    *(uint4*)&hi[base] = make_uint4(rh[0], rh[1], rh[2], rh[3]);
    *(uint4*)&lo[base] = make_uint4(rl[0], rl[1], rl[2], rl[3]);
}

// ---------------- activation pack: f32 [b][c][t] -> pair-major padded panels ----
__global__ void k_packx(const float* __restrict__ X, u32* __restrict__ Phi,
                        u32* __restrict__ Plo, int Cin, int useMask) {
    __shared__ float tile[64][65];
    int t0 = blockIdx.x*64, ct = blockIdx.y, b = blockIdx.z;
    int CT = gridDim.y;
    int tid = threadIdx.x;
    int tx = tid & 63, ty = tid >> 6;
    float mk = useMask ? g_mask[b*T + t0 + tx] : 1.f;
#pragma unroll
    for (int i = 0; i < 16; i++) {
        int cc = ty + i*4;
        tile[cc][tx] = X[((size_t)b*Cin + ct*64 + cc)*T + t0 + tx] * mk;
    }
    __syncthreads();
    size_t base = (size_t)(b*CT + ct)*32*516;
#pragma unroll
    for (int i = 0; i < 8; i++) {
        int e = tid + i*256;
        int p = e >> 6, tt = e & 63;
        u32 hv, lv; split2(tile[2*p][tt], tile[2*p+1][tt], hv, lv);
        Phi[base + (size_t)p*516 + t0 + tt + 1] = hv;
        Plo[base + (size_t)p*516 + t0 + tt + 1] = lv;
    }
    if (t0 == 0 && tid < 32) {
        Phi[base + (size_t)tid*516] = 0u; Plo[base + (size_t)tid*516] = 0u;
    }
    if (t0 == T-64 && tid < 96) {
        int p = tid/3, j = 513 + tid%3;
        Phi[base + (size_t)p*516 + j] = 0u; Plo[base + (size_t)p*516 + j] = 0u;
    }
}

// ---------------- fragment-direct bf16 mma GEMM/conv ---------------------------
#define LOADA(AH, AL, ct_, kp_, k16_) do { \
    size_t ab_ = ((size_t)(((kp_)*CT16 + (ct_)*4 + (k16_))*OT + oy)) << 8; \
    const uint4* Abh_ = (const uint4*)Whi + ab_; \
    const uint4* Abl_ = (const uint4*)Wlo + ab_; \
    _Pragma("unroll") \
    for (int mi_ = 0; mi_ < 4; mi_++) { \
        int s_ = (wm*4 + mi_)*32 + lane; \
        (AH)[mi_] = Abh_[s_]; (AL)[mi_] = Abl_[s_]; \
    } \
} while (0)

// PACK=0: f32 output (split Y0/Y1); PACK=1: packed bf16 panel output (masked).
template<int KK, int NT, int PACK>
__global__ __launch_bounds__(256, 1) void k_mma_f(
        const u32* __restrict__ Whi, const u32* __restrict__ Wlo,
        const u32* __restrict__ Xhi, const u32* __restrict__ Xlo,
        const float* __restrict__ bias,
        float* __restrict__ Y0, float* __restrict__ Y1, int Osplit,
        u32* __restrict__ PanHi, u32* __restrict__ PanLo, int CTpan,
        int Cin, int relu, int maskOut) {
    extern __shared__ char smc[];
    const int STG = 64*136;          // u32 per stage
    const int CHUNKS = 33;
    const int PAD = (KK - 1) / 2;
    u32 sb = smem_u32(smc);
    int tid = threadIdx.x, warp = tid >> 5, lane = tid & 31;
    int g = lane >> 2, tq = lane & 3;
    int wm = warp >> 2, wn = warp & 3;
    int t0 = blockIdx.x*NT, oy = blockIdx.y, b = blockIdx.z;
    int OT = gridDim.y;
    int CT = Cin >> 6, CT16 = Cin >> 4;
    const float* mrow = g_mask + b*T;

    float acc[4][4][4];
#pragma unroll
    for (int mi = 0; mi < 4; mi++)
#pragma unroll
        for (int ni = 0; ni < 4; ni++)
#pragma unroll
            for (int q = 0; q < 4; q++) acc[mi][ni][q] = 0.f;

    // prologue: stages 0..2
#pragma unroll
    for (int st = 0; st < 3; st++) {
        size_t prow = (size_t)(b*CT + st)*32;
        for (int e = tid; e < 64*CHUNKS; e += 256) {
            int r = e / CHUNKS, cch = e - r*CHUNKS;
            const u32* src = ((r < 32) ? Xhi : Xlo) + (prow + (r & 31))*516 + t0 + cch*4;
            cp16(sb + (u32)(st*STG + r*136 + cch*4)*4, src);
        }
        asm volatile("cp.async.commit_group;" ::: "memory");
    }

    uint4 ahA[4], alA[4], ahB[4], alB[4];
    LOADA(ahA, alA, 0, 0, 0);

    for (int ct = 0; ct < CT; ct++) {
        asm volatile("cp.async.wait_group 2;" ::: "memory");
        __syncthreads();
        if (ct + 3 < CT) {
            int stg = (ct + 3) & 3;
            size_t prow = (size_t)(b*CT + ct + 3)*32;
            for (int e = tid; e < 64*CHUNKS; e += 256) {
                int r = e / CHUNKS, cch = e - r*CHUNKS;
                const u32* src = ((r < 32) ? Xhi : Xlo) + (prow + (r & 31))*516 + t0 + cch*4;
                cp16(sb + (u32)(stg*STG + r*136 + cch*4)*4, src);
            }
        }
        asm volatile("cp.async.commit_group;" ::: "memory");

        const u32* Bst = (const u32*)smc + (ct & 3)*STG;
#pragma unroll
        for (int kp = 0; kp < KK; kp++) {
            int ccoff = kp + 1 - PAD;
#pragma unroll
            for (int k16 = 0; k16 < 4; k16++) {
                const int ui = kp*4 + k16;
                const int nu = ui + 1;
                if (nu < KK*4) {
                    if ((ui & 1) == 0) LOADA(ahB, alB, ct, (nu >> 2), (nu & 3));
                    else               LOADA(ahA, alA, ct, (nu >> 2), (nu & 3));
                } else {
                    if (ct + 1 < CT) {
                        if ((ui & 1) == 0) LOADA(ahB, alB, ct + 1, 0, 0);
                        else               LOADA(ahA, alA, ct + 1, 0, 0);
                    }
                }
                int rb = k16*8;
#pragma unroll
                for (int ni = 0; ni < 4; ni++) {
                    int cc = wn*32 + ni*8 + g + ccoff;
                    u32 bh0 = Bst[(rb+tq)*136 + cc];
                    u32 bh1 = Bst[(rb+tq+4)*136 + cc];
                    u32 bl0 = Bst[(32+rb+tq)*136 + cc];
                    u32 bl1 = Bst[(32+rb+tq+4)*136 + cc];
#pragma unroll
                    for (int mi = 0; mi < 4; mi++) {
                        if ((ui & 1) == 0) {
                            mma16(acc[mi][ni], (const u32*)&alA[mi], bh0, bh1);
                            mma16(acc[mi][ni], (const u32*)&ahA[mi], bl0, bl1);
                            mma16(acc[mi][ni], (const u32*)&ahA[mi], bh0, bh1);
                        } else {
                            mma16(acc[mi][ni], (const u32*)&alB[mi], bh0, bh1);
                            mma16(acc[mi][ni], (const u32*)&ahB[mi], bl0, bl1);
                            mma16(acc[mi][ni], (const u32*)&ahB[mi], bh0, bh1);
                        }
                    }
                }
            }
        }
    }
    __syncthreads();
    // epilogue
    if (PACK == 0) {
#pragma unroll
        for (int mi = 0; mi < 4; mi++) {
#pragma unroll
            for (int half = 0; half < 2; half++) {
                int o = oy*128 + wm*64 + mi*16 + g + half*8;
                float bi = bias[o];
                float* Yp; size_t rowb;
                if (o < Osplit) { Yp = Y0; rowb = ((size_t)b*Osplit + o)*T; }
                else            { Yp = Y1; rowb = ((size_t)b*Osplit + (o - Osplit))*T; }
#pragma unroll
                for (int ni = 0; ni < 4; ni++) {
                    int t = t0 + wn*32 + ni*8 + 2*tq;
                    float v0 = acc[mi][ni][half*2 + 0] + bi;
                    float v1 = acc[mi][ni][half*2 + 1] + bi;
                    if (relu) { v0 = fmaxf(v0, 0.f); v1 = fmaxf(v1, 0.f); }
                    if (maskOut) { v0 *= mrow[t]; v1 *= mrow[t+1]; }
                    *(float2*)&Yp[rowb + t] = make_float2(v0, v1);
                }
            }
        }
    } else {
        // packed panel output (always masked); channel pairs via shfl.xor 4
#pragma unroll
        for (int mi = 0; mi < 4; mi++) {
#pragma unroll
            for (int half = 0; half < 2; half++) {
                int o = oy*128 + wm*64 + mi*16 + g + half*8;
                float bi = bias[o];
                size_t pbase = ((size_t)(b*CTpan + (o >> 6))*32 + ((o & 63) >> 1))*516;
#pragma unroll
                for (int ni = 0; ni < 4; ni++) {
                    int t = t0 + wn*32 + ni*8 + 2*tq;
                    float v0 = acc[mi][ni][half*2 + 0] + bi;
                    float v1 = acc[mi][ni][half*2 + 1] + bi;
                    if (relu) { v0 = fmaxf(v0, 0.f); v1 = fmaxf(v1, 0.f); }
                    v0 *= mrow[t]; v1 *= mrow[t+1];
                    float p0 = __shfl_xor_sync(0xffffffffu, v0, 4);
                    float p1 = __shfl_xor_sync(0xffffffffu, v1, 4);
                    if (!(g & 1)) {
                        u32 h0, l0, h1, l1;
                        split2(v0, p0, h0, l0);
                        split2(v1, p1, h1, l1);
                        PanHi[pbase + t + 1] = h0; PanHi[pbase + t + 2] = h1;
                        PanLo[pbase + t + 1] = l0; PanLo[pbase + t + 2] = l1;
                    }
                }
            }
        }
    }
}

// ---------------- fused flash attention -> packed ctx panels -------------------
#define FSM_TOTAL 155936
__global__ __launch_bounds__(256, 1) void k_flash(
        const float* __restrict__ qkv,
        u32* __restrict__ PanHi, u32* __restrict__ PanLo,
        const float* __restrict__ rk_g, const float* __restrict__ rv_g) {
    extern __shared__ char fsm[];
    u64*   Qd   = (u64*)(fsm);                 // [128][67] dup'd q
    float* Ks   = (float*)(fsm + 68608);       // [64][68]
    float* Ps   = (float*)(fsm + 86016);       // [64][132]
    u64*   Vd   = (u64*)(fsm + 119808);        // [64][33]
    float* bnd  = (float*)(fsm + 136704);      // [128][10]
    float* bacc = (float*)(fsm + 141824);      // [128][10]
    float* rks  = (float*)(fsm + 146944);      // [9][68]
    float* rvs  = (float*)(fsm + 149392);      // [9][68]
    float* ms   = (float*)(fsm + 151840);      // [512]
    float* mtv  = (float*)(fsm + 153888);      // [128]
    float* mro  = (float*)(fsm + 154400);      // [128]
    float* ssum = (float*)(fsm + 154912);      // [128]
    float* scal = (float*)(fsm + 155424);      // [128]

    int lid = threadIdx.x;
    int t0 = blockIdx.x * 128;
    int bh = blockIdx.y, b = bh >> 3, h = bh & 7;
    const float* qb = qkv + ((size_t)b*1536 + h*DK)*T;
    const float* kb = qkv + ((size_t)b*1536 + 512 + h*DK)*T;
    const float* vb = qkv + ((size_t)b*1536 + 1024 + h*DK)*T;
    int txq = lid & 7,  tyq = lid >> 3;
    int txc = lid & 15, tyc = lid >> 4;

#pragma unroll
    for (int it = 0; it < 32; it++) {
        int e = lid + it*256;
        int tloc = e & 127, dd = e >> 7;
        float v = qb[(size_t)dd*T + t0 + tloc];
        Qd[tloc*67 + dd] = fpack2(v, v);
    }
    for (int e = lid; e < 9*64; e += 256) {
        rks[(e >> 6)*68 + (e & 63)] = rk_g[e];
        rvs[(e >> 6)*68 + (e & 63)] = rv_g[e];
    }
    for (int e = lid; e < T; e += 256) ms[e] = g_mask[b*T + e];
    if (lid < 128) {
        mtv[lid] = g_mask[b*T + t0 + lid];
        mro[lid] = -3.4e38f;
        ssum[lid] = 0.f;
    }
    for (int e = lid; e < 128*10; e += 256) bacc[e] = 0.f;
    __syncthreads();
    for (int e = lid; e < 128*9; e += 256) {
        int t = e / 9, dt = e - t*9;
        float dot = 0.f;
#pragma unroll
        for (int d = 0; d < 64; d++)
            dot += funpack2(Qd[t*67 + d]).x * rks[dt*68 + d];
        bnd[t*10 + dt] = dot;
    }

    u64 oacc[4][4];
#pragma unroll
    for (int i = 0; i < 4; i++)
#pragma unroll
        for (int j = 0; j < 4; j++) oacc[i][j] = 0ull;

    for (int s0 = 0; s0 < T; s0 += 64) {
        __syncthreads();
#pragma unroll
        for (int it = 0; it < 16; it++) {
            int e = lid + it*256;
            int dd = e >> 6, ss = e & 63;
            Ks[dd*68 + ss] = kb[(size_t)dd*T + s0 + ss];
        }
        __syncthreads();
        u64 sacc[4][4];
#pragma unroll
        for (int i = 0; i < 4; i++)
#pragma unroll
            for (int j = 0; j < 4; j++) sacc[i][j] = 0ull;
#pragma unroll 16
        for (int kk = 0; kk < 64; kk++) {
            ulonglong2 xa = *(const ulonglong2*)&Ks[kk*68 + txq*8];
            ulonglong2 xb = *(const ulonglong2*)&Ks[kk*68 + txq*8 + 4];
#pragma unroll
            for (int i = 0; i < 4; i++) {
                u64 w = Qd[(tyq*4+i)*67 + kk];
                sacc[i][0] = ffma2(w, xa.x, sacc[i][0]);
                sacc[i][1] = ffma2(w, xa.y, sacc[i][1]);
                sacc[i][2] = ffma2(w, xb.x, sacc[i][2]);
                sacc[i][3] = ffma2(w, xb.y, sacc[i][3]);
            }
        }
        float sv[4][8];
#pragma unroll
        for (int i = 0; i < 4; i++) {
            int tl = tyq*4 + i;
            float mt = mtv[tl];
            float rmax = -3.4e38f;
#pragma unroll
            for (int jp = 0; jp < 4; jp++) {
                float2 f = funpack2(sacc[i][jp]);
                sv[i][2*jp] = f.x; sv[i][2*jp+1] = f.y;
            }
#pragma unroll
            for (int j = 0; j < 8; j++) {
                int sg = s0 + txq*8 + j;
                float v = sv[i][j];
                int dtix = sg - (t0 + tl) + W;
                if ((unsigned)dtix < 9u) v += bnd[tl*10 + dtix];
                if (mt * ms[sg] == 0.f) v = -1e4f;
                sv[i][j] = v;
                rmax = fmaxf(rmax, v);
            }
#pragma unroll
            for (int o = 1; o <= 4; o <<= 1)
                rmax = fmaxf(rmax, __shfl_xor_sync(0xffffffffu, rmax, o));
            if (txq == 0) {
                float old = mro[tl];
                float nm = fmaxf(old, rmax);
                scal[tl] = expf(old - nm);
                mro[tl] = nm;
            }
        }
        __syncthreads();
#pragma unroll
        for (int i = 0; i < 4; i++) {
            int tl = tyq*4 + i;
            float nm = mro[tl];
            float cs = 0.f;
#pragma unroll
            for (int j = 0; j < 8; j++) {
                float e = expf(sv[i][j] - nm);
                cs += e;
                Ps[(txq*8 + j)*132 + tl] = e;
            }
#pragma unroll
            for (int o = 1; o <= 4; o <<= 1)
                cs += __shfl_xor_sync(0xffffffffu, cs, o);
            if (txq == 0) ssum[tl] = ssum[tl]*scal[tl] + cs;
        }
        __syncthreads();
        for (int e = lid; e < 128*9; e += 256) {
            int t = e / 9, dt = e - t*9;
            float v = bacc[t*10 + dt] * scal[t];
            int sg = t0 + t + dt - W;
            if (sg >= s0 && sg < s0 + 64) v += Ps[(sg - s0)*132 + t];
            bacc[t*10 + dt] = v;
        }
#pragma unroll
        for (int jp = 0; jp < 4; jp++) {
            int tp = txc*4 + jp;
            float se = scal[2*tp], so = scal[2*tp + 1];
#pragma unroll
            for (int i = 0; i < 4; i++) {
                float2 f = funpack2(oacc[i][jp]);
                oacc[i][jp] = fpack2(f.x*se, f.y*so);
            }
        }
#pragma unroll
        for (int sub = 0; sub < 2; sub++) {
            __syncthreads();
#pragma unroll
            for (int it = 0; it < 8; it++) {
                int e = lid + it*256;
                int dd = e >> 5, ss = e & 31;
                float v = vb[(size_t)dd*T + s0 + sub*32 + ss];
                Vd[dd*33 + ss] = fpack2(v, v);
            }
            __syncthreads();
#pragma unroll 8
            for (int kk = 0; kk < 32; kk++) {
                ulonglong2 xa = *(const ulonglong2*)&Ps[(sub*32+kk)*132 + txc*8];
                ulonglong2 xb = *(const ulonglong2*)&Ps[(sub*32+kk)*132 + txc*8 + 4];
#pragma unroll
                for (int i = 0; i < 4; i++) {
                    u64 w = Vd[(tyc*4+i)*33 + kk];
                    oacc[i][0] = ffma2(w, xa.x, oacc[i][0]);
                    oacc[i][1] = ffma2(w, xa.y, oacc[i][1]);
                    oacc[i][2] = ffma2(w, xb.x, oacc[i][2]);
                    oacc[i][3] = ffma2(w, xb.y, oacc[i][3]);
                }
            }
        }
    }
    __syncthreads();
    // epilogue: + band@rel_v, normalize, write packed panel (ct = h)
#pragma unroll
    for (int jp = 0; jp < 4; jp++) {
        int tp = txc*4 + jp;
        float inve = 1.f / ssum[2*tp];
        float invo = 1.f / ssum[2*tp + 1];
        float vals[4][2];
#pragma unroll
        for (int i = 0; i < 4; i++) {
            int d = tyc*4 + i;
            float be = 0.f, bo = 0.f;
#pragma unroll
            for (int dt = 0; dt < 9; dt++) {
                float rv = rvs[dt*68 + d];
                be += bacc[(2*tp)*10 + dt]   * rv;
                bo += bacc[(2*tp+1)*10 + dt] * rv;
            }
            float2 f = funpack2(oacc[i][jp]);
            vals[i][0] = (f.x + be)*inve;
            vals[i][1] = (f.y + bo)*invo;
        }
#pragma unroll
        for (int pp = 0; pp < 2; pp++) {
            int P = tyc*2 + pp;
            size_t pbase = ((size_t)(b*8 + h)*32 + P)*516 + t0 + 2*tp + 1;
            u32 h0, l0, h1, l1;
            split2(vals[2*pp][0], vals[2*pp+1][0], h0, l0);
            split2(vals[2*pp][1], vals[2*pp+1][1], h1, l1);
            PanHi[pbase]     = h0; PanLo[pbase]     = l0;
            PanHi[pbase + 1] = h1; PanLo[pbase + 1] = l1;
        }
    }
}

// ---------------- channel LayerNorm -------------------------------------------
__global__ void k_ln(float* __restrict__ hbuf, const float* __restrict__ yv,
                     const float* __restrict__ g, const float* __restrict__ bb,
                     int maskOut) {
    int tx = threadIdx.x, ty = threadIdx.y;
    int t = blockIdx.x*32 + tx, b = blockIdx.y;
    float s = 0.f, s2 = 0.f;
    for (int c = ty; c < C; c += 8) {
        size_t idx = ((size_t)b*C + c)*T + t;
        float v = hbuf[idx] + yv[idx];
        s += v; s2 += v*v;
    }
    __shared__ float rs[8][32], rs2[8][32];
    rs[ty][tx] = s; rs2[ty][tx] = s2;
    __syncthreads();
    if (ty == 0) {
        for (int j = 1; j < 8; j++) { s += rs[j][tx]; s2 += rs2[j][tx]; }
        float m = s / C;
        float var = s2 / C - m*m;
        rs[0][tx] = m;
        rs2[0][tx] = rsqrtf(var + 1e-5f);
    }
    __syncthreads();
    float m = rs[0][tx], r = rs2[0][tx];
    float mk = maskOut ? g_mask[b*T + t] : 1.f;
    for (int c = ty; c < C; c += 8) {
        size_t idx = ((size_t)b*C + c)*T + t;
        float v = hbuf[idx] + yv[idx];
        hbuf[idx] = ((v - m)*r*g[c] + bb[c]) * mk;
    }
}

// ---------------- launch -------------------------------------------------------
extern "C" void kernel_launch(void* const* d_in, const int* in_sizes, int n_in,
                              void* d_out, int out_size) {
    const int*   x    = (const int*)d_in[0];
    const int*   xlen = (const int*)d_in[1];
    const float* emb  = (const float*)d_in[2];
    const float* Wq = (const float*)d_in[3],  *bq = (const float*)d_in[4];
    const float* Wk = (const float*)d_in[5],  *bk = (const float*)d_in[6];
    const float* Wv = (const float*)d_in[7],  *bv = (const float*)d_in[8];
    const float* Wo = (const float*)d_in[9],  *bo = (const float*)d_in[10];
    const float* rel_k = (const float*)d_in[11], *rel_v = (const float*)d_in[12];
    const float* ln1g = (const float*)d_in[13], *ln1b = (const float*)d_in[14];
    const float* ln2g = (const float*)d_in[15], *ln2b = (const float*)d_in[16];
    const float* w1 = (const float*)d_in[17], *b1 = (const float*)d_in[18];
    const float* w2 = (const float*)d_in[19], *b2 = (const float*)d_in[20];
    const float* pw = (const float*)d_in[21], *pbv = (const float*)d_in[22];
    float* out = (float*)d_out;
    size_t SZ = (size_t)B*C*T;

    float *ph,*pqkv,*py,*pb3;
    u32 *x5h,*x5l,*x2h,*x2l,*wqh,*wql,*woh,*wol,*w1h,*w1l,*w2h,*w2l,*pjh,*pjl;
    cudaGetSymbolAddress((void**)&ph,   g_h);
    cudaGetSymbolAddress((void**)&pqkv, g_qkv);
    cudaGetSymbolAddress((void**)&py,   g_y);
    cudaGetSymbolAddress((void**)&pb3,  g_b3);
    cudaGetSymbolAddress((void**)&x5h,  g_px512_hi);
    cudaGetSymbolAddress((void**)&x5l,  g_px512_lo);
    cudaGetSymbolAddress((void**)&x2h,  g_px2048_hi);
    cudaGetSymbolAddress((void**)&x2l,  g_px2048_lo);
    cudaGetSymbolAddress((void**)&wqh,  g_wqkv_hi);
    cudaGetSymbolAddress((void**)&wql,  g_wqkv_lo);
    cudaGetSymbolAddress((void**)&woh,  g_wo_hi);
    cudaGetSymbolAddress((void**)&wol,  g_wo_lo);
    cudaGetSymbolAddress((void**)&w1h,  g_w1_hi);
    cudaGetSymbolAddress((void**)&w1l,  g_w1_lo);
    cudaGetSymbolAddress((void**)&w2h,  g_w2_hi);
    cudaGetSymbolAddress((void**)&w2l,  g_w2_lo);
    cudaGetSymbolAddress((void**)&pjh,  g_pj_hi);
    cudaGetSymbolAddress((void**)&pjl,  g_pj_lo);

    const int SMB = 64*136*4*4;   // 139264 bytes, 4-stage B pipeline
    static int attr_set = 0;
    if (!attr_set) {
        cudaFuncSetAttribute((void*)k_mma_f<1,128,0>, cudaFuncAttributeMaxDynamicSharedMemorySize, SMB);
        cudaFuncSetAttribute((void*)k_mma_f<3,128,0>, cudaFuncAttributeMaxDynamicSharedMemorySize, SMB);
        cudaFuncSetAttribute((void*)k_mma_f<3,128,1>, cudaFuncAttributeMaxDynamicSharedMemorySize, SMB);
        cudaFuncSetAttribute((void*)k_flash, cudaFuncAttributeMaxDynamicSharedMemorySize, FSM_TOTAL);
        attr_set = 1;
    }

    dim3 tb(32,8);
    k_zpad<<<32, 256>>>();
    k_embed<<<dim3(T/32, B), tb>>>(x, xlen, emb, out, out + 4*SZ);
    k_packwf<<<dim3(8, 32, 1), 256>>>(pw, 1.f, pjh, pjl, C, 1, 32, 8, 0);
    k_bias3<<<dim3(6, LYR), 256>>>(bq, bk, bv, pb3);

    for (int i = 0; i < LYR; i++) {
        k_packwf<<<dim3(4, 32, 1), 256>>>(Wq + (size_t)i*C*C, 0.125f, wqh, wql, C, 1, 32, 12, 0);
        k_packwf<<<dim3(4, 32, 1), 256>>>(Wk + (size_t)i*C*C, 1.f,    wqh, wql, C, 1, 32, 12, 4);
        k_packwf<<<dim3(4, 32, 1), 256>>>(Wv + (size_t)i*C*C, 1.f,    wqh, wql, C, 1, 32, 12, 8);
        k_packwf<<<dim3(4, 32, 1), 256>>>(Wo + (size_t)i*C*C, 1.f,    woh, wol, C, 1, 32, 4, 0);
        k_packwf<<<dim3(16, 32, 3), 256>>>(w1 + (size_t)i*DFF*C*3, 1.f, w1h, w1l, C*3, 3, 32, 16, 0);
        k_packwf<<<dim3(4, 128, 3), 256>>>(w2 + (size_t)i*C*DFF*3, 1.f, w2h, w2l, DFF*3, 3, 128, 4, 0);

        k_packx<<<dim3(8, 8, B), 256>>>(ph, x5h, x5l, C, 0);
        k_mma_f<1,128,0><<<dim3(4, 12, B), 256, SMB>>>(wqh, wql, x5h, x5l,
            pb3 + i*1536, pqkv, pqkv, 1536, 0, 0, 0, C, 0, 0);
        k_flash<<<dim3(T/128, B*H), 256, FSM_TOTAL>>>(pqkv, x5h, x5l,
            rel_k + (size_t)i*NREL*DK, rel_v + (size_t)i*NREL*DK);
        k_mma_f<1,128,0><<<dim3(4, 4, B), 256, SMB>>>(woh, wol, x5h, x5l,
            bo + i*C, py, py, C, 0, 0, 0, C, 0, 0);
        k_ln<<<dim3(T/32, B), tb>>>(ph, py, ln1g + i*C, ln1b + i*C, 0);

        k_packx<<<dim3(8, 8, B), 256>>>(ph, x5h, x5l, C, 1);
        k_mma_f<3,128,1><<<dim3(4, 16, B), 256, SMB>>>(w1h, w1l, x5h, x5l,
            b1 + i*DFF, 0, 0, 0, x2h, x2l, 32, C, 1, 0);
        k_mma_f<3,128,0><<<dim3(4, 4, B), 256, SMB>>>(w2h, w2l, x2h, x2l,
            b2 + i*C, py, py, C, 0, 0, 0, DFF, 0, 1);
        k_ln<<<dim3(T/32, B), tb>>>(ph, py, ln2g + i*C, ln2b + i*C, 1);
    }

    k_copy4<<<(B*C*T)/1024, 256>>>((const float4*)ph, (float4*)(out + SZ));
    k_packx<<<dim3(8, 8, B), 256>>>(ph, x5h, x5l, C, 0);
    k_mma_f<1,128,0><<<dim3(4, 8, B), 256, SMB>>>(pjh, pjl, x5h, x5l, pbv,
        out + 2*SZ, out + 3*SZ, 512, 0, 0, 0, C, 0, 1);
}

// round 14
// speedup vs baseline: 1.1407x; 1.0660x over previous
#include <cuda_runtime.h>
#include <math.h>

#define B 8
#define T 512
#define C 512
#define DFF 2048
#define H 8
#define LYR 6
#define W 4
#define DK 64
#define NREL 9

typedef unsigned long long u64;
typedef unsigned int u32;

// ---------------- scratch ----------------------------------------------------
__device__ float g_h[B*C*T];
__device__ float g_qkv[B*3*C*T];
__device__ float g_y[B*C*T];
__device__ float g_mask[B*T];
__device__ float g_b3[LYR*3*C];
// activation panels, pair-major: [b][ct][pair 32][516], bf16x2 hi/lo
__device__ u32 g_px512_hi[B*8*32*516],   g_px512_lo[B*8*32*516];
__device__ u32 g_px2048_hi[B*32*32*516], g_px2048_lo[B*32*32*516];
// weight fragment arrays (per-layer reused => L2-resident)
__device__ u32 g_wqkv_hi[32*12*1024],  g_wqkv_lo[32*12*1024];
__device__ u32 g_wo_hi[32*4*1024],     g_wo_lo[32*4*1024];
__device__ u32 g_w1_hi[3*32*16*1024],  g_w1_lo[3*32*16*1024];
__device__ u32 g_w2_hi[3*128*4*1024],  g_w2_lo[3*128*4*1024];
__device__ u32 g_pj_hi[32*8*1024],     g_pj_lo[32*8*1024];

// ---------------- helpers ------------------------------------------------------
__device__ __forceinline__ u64 ffma2(u64 a, u64 b, u64 c) {
    u64 d; asm("fma.rn.f32x2 %0, %1, %2, %3;" : "=l"(d) : "l"(a), "l"(b), "l"(c));
    return d;
}
__device__ __forceinline__ u64 fpack2(float lo, float hi) {
    u64 d; asm("mov.b64 %0, {%1, %2};" : "=l"(d) : "f"(lo), "f"(hi));
    return d;
}
__device__ __forceinline__ float2 funpack2(u64 v) {
    float2 r; asm("mov.b64 {%0, %1}, %2;" : "=f"(r.x), "=f"(r.y) : "l"(v));
    return r;
}
__device__ __forceinline__ u32 bf2(float h, float l) {
    u32 r; asm("cvt.rn.bf16x2.f32 %0, %1, %2;" : "=r"(r) : "f"(h), "f"(l));
    return r;
}
__device__ __forceinline__ void split2(float f0, float f1, u32& hv, u32& lv) {
    hv = bf2(f1, f0);
    float r0 = f0 - __uint_as_float(hv << 16);
    float r1 = f1 - __uint_as_float(hv & 0xffff0000u);
    lv = bf2(r1, r0);
}
__device__ __forceinline__ void mma16(float* d, const u32* a, u32 b0, u32 b1) {
    asm("mma.sync.aligned.m16n8k16.row.col.f32.bf16.bf16.f32 "
        "{%0,%1,%2,%3}, {%4,%5,%6,%7}, {%8,%9}, {%0,%1,%2,%3};"
        : "+f"(d[0]), "+f"(d[1]), "+f"(d[2]), "+f"(d[3])
        : "r"(a[0]), "r"(a[1]), "r"(a[2]), "r"(a[3]), "r"(b0), "r"(b1));
}
__device__ __forceinline__ u32 smem_u32(const void* p) {
    u32 a; asm("{ .reg .u64 t; cvta.to.shared.u64 t, %1; cvt.u32.u64 %0, t; }"
               : "=r"(a) : "l"(p));
    return a;
}
__device__ __forceinline__ void cp16(u32 dst, const void* src) {
    asm volatile("{ .reg .u64 g; cvta.to.global.u64 g, %1; "
                 "cp.async.cg.shared.global [%0], [g], 16; }"
                 :: "r"(dst), "l"(src) : "memory");
}

// ---------------- pad zeroing for the x2048 panel -------------------------------
__global__ void k_zpad() {
    int r = blockIdx.x*256 + threadIdx.x;
    if (r >= 8192) return;
    size_t base = (size_t)r * 516;
    g_px2048_hi[base] = 0u;     g_px2048_lo[base] = 0u;
    g_px2048_hi[base+513] = 0u; g_px2048_lo[base+513] = 0u;
    g_px2048_hi[base+514] = 0u; g_px2048_lo[base+514] = 0u;
    g_px2048_hi[base+515] = 0u; g_px2048_lo[base+515] = 0u;
}

// ---------------- embedding + mask -------------------------------------------
__global__ void k_embed(const int* __restrict__ x, const int* __restrict__ xlen,
                        const float* __restrict__ emb,
                        float* __restrict__ out_xemb, float* __restrict__ out_mask) {
    int b = blockIdx.y;
    int t = blockIdx.x * 32 + threadIdx.x;
    int xi = x[b*T + t];
    float mk = (t < xlen[b]) ? 1.f : 0.f;
    const float SQ = 22.627416997969522f;
    for (int c = threadIdx.y; c < C; c += 8) {
        float v = emb[xi*C + c] * SQ;
        out_xemb[((size_t)b*C + c)*T + t] = v;
        g_h[((size_t)b*C + c)*T + t] = v * mk;
    }
    if (threadIdx.y == 0) {
        g_mask[b*T + t] = mk;
        out_mask[b*T + t] = mk;
    }
}

__global__ void k_copy4(const float4* __restrict__ src, float4* __restrict__ dst) {
    int i = blockIdx.x * 256 + threadIdx.x;
    dst[i] = src[i];
}

__global__ void k_bias3(const float* __restrict__ bq, const float* __restrict__ bk,
                        const float* __restrict__ bv, float* __restrict__ b3) {
    int l = blockIdx.y;
    int i = blockIdx.x*256 + threadIdx.x;
    float v;
    if (i < 512)       v = bq[l*C + i] * 0.125f;
    else if (i < 1024) v = bk[l*C + i - 512];
    else               v = bv[l*C + i - 1024];
    b3[l*1536 + i] = v;
}

// ---------------- weight pack -> per-lane mma fragment order -------------------
__global__ void k_packwf(const float* __restrict__ Wm, float scale,
                         u32* __restrict__ hi, u32* __restrict__ lo,
                         int ostride, int KKf, int CT16, int OT, int otOff) {
    int ot = blockIdx.x, c16 = blockIdx.y, kp = blockIdx.z;
    int tid = threadIdx.x, s = tid >> 5, l = tid & 31;
    int g = l >> 2, tq = l & 3;
    int wm = s >> 2, mi = s & 3;
    int obase = ot*128 + wm*64 + mi*16 + g;
    u32 rh[4], rl[4];
#pragma unroll
    for (int r = 0; r < 4; r++) {
        int o = obase + (r & 1)*8;
        int pair = (r < 2) ? tq : tq + 4;
        int ce = c16*16 + 2*pair;
        float f0 = Wm[(size_t)o*ostride + (size_t)ce*KKf + kp] * scale;
        float f1 = Wm[(size_t)o*ostride + (size_t)(ce+1)*KKf + kp] * scale;
        split2(f0, f1, rh[r], rl[r]);
    }
    size_t base = ((size_t)((kp*CT16 + c16)*OT + otOff + ot))*1024 + (s*32 + l)*4;
    *(uint4*)&hi[base] = make_uint4(rh[0], rh[1], rh[2], rh[3]);
    *(uint4*)&lo[base] = make_uint4(rl[0], rl[1], rl[2], rl[3]);
}

// ---------------- activation pack: f32 [b][c][t] -> pair-major padded panels ----
__global__ void k_packx(const float* __restrict__ X, u32* __restrict__ Phi,
                        u32* __restrict__ Plo, int Cin, int useMask) {
    __shared__ float tile[64][65];
    int t0 = blockIdx.x*64, ct = blockIdx.y, b = blockIdx.z;
    int CT = gridDim.y;
    int tid = threadIdx.x;
    int tx = tid & 63, ty = tid >> 6;
    float mk = useMask ? g_mask[b*T + t0 + tx] : 1.f;
#pragma unroll
    for (int i = 0; i < 16; i++) {
        int cc = ty + i*4;
        tile[cc][tx] = X[((size_t)b*Cin + ct*64 + cc)*T + t0 + tx] * mk;
    }
    __syncthreads();
    size_t base = (size_t)(b*CT + ct)*32*516;
#pragma unroll
    for (int i = 0; i < 8; i++) {
        int e = tid + i*256;
        int p = e >> 6, tt = e & 63;
        u32 hv, lv; split2(tile[2*p][tt], tile[2*p+1][tt], hv, lv);
        Phi[base + (size_t)p*516 + t0 + tt + 1] = hv;
        Plo[base + (size_t)p*516 + t0 + tt + 1] = lv;
    }
    if (t0 == 0 && tid < 32) {
        Phi[base + (size_t)tid*516] = 0u; Plo[base + (size_t)tid*516] = 0u;
    }
    if (t0 == T-64 && tid < 96) {
        int p = tid/3, j = 513 + tid%3;
        Phi[base + (size_t)p*516 + j] = 0u; Plo[base + (size_t)p*516 + j] = 0u;
    }
}

// ---------------- fragment-direct bf16 mma GEMM/conv ---------------------------
#define LOADA(AH, AL, ct_, kp_, k16_) do { \
    size_t ab_ = ((size_t)(((kp_)*CT16 + (ct_)*4 + (k16_))*OT + oy)) << 8; \
    const uint4* Abh_ = (const uint4*)Whi + ab_; \
    const uint4* Abl_ = (const uint4*)Wlo + ab_; \
    _Pragma("unroll") \
    for (int mi_ = 0; mi_ < 4; mi_++) { \
        int s_ = (wm*4 + mi_)*32 + lane; \
        (AH)[mi_] = Abh_[s_]; (AL)[mi_] = Abl_[s_]; \
    } \
} while (0)

template<int KK, int NT, int PACK>
__global__ __launch_bounds__(256, 1) void k_mma_f(
        const u32* __restrict__ Whi, const u32* __restrict__ Wlo,
        const u32* __restrict__ Xhi, const u32* __restrict__ Xlo,
        const float* __restrict__ bias,
        float* __restrict__ Y0, float* __restrict__ Y1, int Osplit,
        u32* __restrict__ PanHi, u32* __restrict__ PanLo, int CTpan,
        int Cin, int relu, int maskOut) {
    extern __shared__ char smc[];
    const int STG = 64*136;
    const int CHUNKS = 33;
    const int PAD = (KK - 1) / 2;
    u32 sb = smem_u32(smc);
    int tid = threadIdx.x, warp = tid >> 5, lane = tid & 31;
    int g = lane >> 2, tq = lane & 3;
    int wm = warp >> 2, wn = warp & 3;
    int t0 = blockIdx.x*NT, oy = blockIdx.y, b = blockIdx.z;
    int OT = gridDim.y;
    int CT = Cin >> 6, CT16 = Cin >> 4;
    const float* mrow = g_mask + b*T;

    float acc[4][4][4];
#pragma unroll
    for (int mi = 0; mi < 4; mi++)
#pragma unroll
        for (int ni = 0; ni < 4; ni++)
#pragma unroll
            for (int q = 0; q < 4; q++) acc[mi][ni][q] = 0.f;

#pragma unroll
    for (int st = 0; st < 3; st++) {
        size_t prow = (size_t)(b*CT + st)*32;
        for (int e = tid; e < 64*CHUNKS; e += 256) {
            int r = e / CHUNKS, cch = e - r*CHUNKS;
            const u32* src = ((r < 32) ? Xhi : Xlo) + (prow + (r & 31))*516 + t0 + cch*4;
            cp16(sb + (u32)(st*STG + r*136 + cch*4)*4, src);
        }
        asm volatile("cp.async.commit_group;" ::: "memory");
    }

    uint4 ahA[4], alA[4], ahB[4], alB[4];
    LOADA(ahA, alA, 0, 0, 0);

    for (int ct = 0; ct < CT; ct++) {
        asm volatile("cp.async.wait_group 2;" ::: "memory");
        __syncthreads();
        if (ct + 3 < CT) {
            int stg = (ct + 3) & 3;
            size_t prow = (size_t)(b*CT + ct + 3)*32;
            for (int e = tid; e < 64*CHUNKS; e += 256) {
                int r = e / CHUNKS, cch = e - r*CHUNKS;
                const u32* src = ((r < 32) ? Xhi : Xlo) + (prow + (r & 31))*516 + t0 + cch*4;
                cp16(sb + (u32)(stg*STG + r*136 + cch*4)*4, src);
            }
        }
        asm volatile("cp.async.commit_group;" ::: "memory");

        const u32* Bst = (const u32*)smc + (ct & 3)*STG;
#pragma unroll
        for (int kp = 0; kp < KK; kp++) {
            int ccoff = kp + 1 - PAD;
#pragma unroll
            for (int k16 = 0; k16 < 4; k16++) {
                const int ui = kp*4 + k16;
                const int nu = ui + 1;
                if (nu < KK*4) {
                    if ((ui & 1) == 0) LOADA(ahB, alB, ct, (nu >> 2), (nu & 3));
                    else               LOADA(ahA, alA, ct, (nu >> 2), (nu & 3));
                } else {
                    if (ct + 1 < CT) {
                        if ((ui & 1) == 0) LOADA(ahB, alB, ct + 1, 0, 0);
                        else               LOADA(ahA, alA, ct + 1, 0, 0);
                    }
                }
                int rb = k16*8;
#pragma unroll
                for (int ni = 0; ni < 4; ni++) {
                    int cc = wn*32 + ni*8 + g + ccoff;
                    u32 bh0 = Bst[(rb+tq)*136 + cc];
                    u32 bh1 = Bst[(rb+tq+4)*136 + cc];
                    u32 bl0 = Bst[(32+rb+tq)*136 + cc];
                    u32 bl1 = Bst[(32+rb+tq+4)*136 + cc];
#pragma unroll
                    for (int mi = 0; mi < 4; mi++) {
                        if ((ui & 1) == 0) {
                            mma16(acc[mi][ni], (const u32*)&alA[mi], bh0, bh1);
                            mma16(acc[mi][ni], (const u32*)&ahA[mi], bl0, bl1);
                            mma16(acc[mi][ni], (const u32*)&ahA[mi], bh0, bh1);
                        } else {
                            mma16(acc[mi][ni], (const u32*)&alB[mi], bh0, bh1);
                            mma16(acc[mi][ni], (const u32*)&ahB[mi], bl0, bl1);
                            mma16(acc[mi][ni], (const u32*)&ahB[mi], bh0, bh1);
                        }
                    }
                }
            }
        }
    }
    __syncthreads();
    if (PACK == 0) {
#pragma unroll
        for (int mi = 0; mi < 4; mi++) {
#pragma unroll
            for (int half = 0; half < 2; half++) {
                int o = oy*128 + wm*64 + mi*16 + g + half*8;
                float bi = bias[o];
                float* Yp; size_t rowb;
                if (o < Osplit) { Yp = Y0; rowb = ((size_t)b*Osplit + o)*T; }
                else            { Yp = Y1; rowb = ((size_t)b*Osplit + (o - Osplit))*T; }
#pragma unroll
                for (int ni = 0; ni < 4; ni++) {
                    int t = t0 + wn*32 + ni*8 + 2*tq;
                    float v0 = acc[mi][ni][half*2 + 0] + bi;
                    float v1 = acc[mi][ni][half*2 + 1] + bi;
                    if (relu) { v0 = fmaxf(v0, 0.f); v1 = fmaxf(v1, 0.f); }
                    if (maskOut) { v0 *= mrow[t]; v1 *= mrow[t+1]; }
                    *(float2*)&Yp[rowb + t] = make_float2(v0, v1);
                }
            }
        }
    } else {
#pragma unroll
        for (int mi = 0; mi < 4; mi++) {
#pragma unroll
            for (int half = 0; half < 2; half++) {
                int o = oy*128 + wm*64 + mi*16 + g + half*8;
                float bi = bias[o];
                size_t pbase = ((size_t)(b*CTpan + (o >> 6))*32 + ((o & 63) >> 1))*516;
#pragma unroll
                for (int ni = 0; ni < 4; ni++) {
                    int t = t0 + wn*32 + ni*8 + 2*tq;
                    float v0 = acc[mi][ni][half*2 + 0] + bi;
                    float v1 = acc[mi][ni][half*2 + 1] + bi;
                    if (relu) { v0 = fmaxf(v0, 0.f); v1 = fmaxf(v1, 0.f); }
                    v0 *= mrow[t]; v1 *= mrow[t+1];
                    float p0 = __shfl_xor_sync(0xffffffffu, v0, 4);
                    float p1 = __shfl_xor_sync(0xffffffffu, v1, 4);
                    if (!(g & 1)) {
                        u32 h0, l0, h1, l1;
                        split2(v0, p0, h0, l0);
                        split2(v1, p1, h1, l1);
                        PanHi[pbase + t + 1] = h0; PanHi[pbase + t + 2] = h1;
                        PanLo[pbase + t + 1] = l0; PanLo[pbase + t + 2] = l1;
                    }
                }
            }
        }
    }
}

// ---------------- fused flash attention -> packed ctx panels -------------------
// smem trimmed to ~105 KB (f32 Q, V overlaid on K) => 2 CTAs/SM.
#define OFF_Q   0
#define OFF_KV  34816
#define OFF_PS  52224
#define OFF_BND 86016
#define OFF_BAC 91136
#define OFF_RKS 96256
#define OFF_RVS 98704
#define OFF_MS  101152
#define OFF_MTV 103200
#define OFF_MRO 103712
#define OFF_SSM 104224
#define OFF_SCL 104736
#define FSM_TOTAL 105248
__global__ __launch_bounds__(256, 2) void k_flash(
        const float* __restrict__ qkv,
        u32* __restrict__ PanHi, u32* __restrict__ PanLo,
        const float* __restrict__ rk_g, const float* __restrict__ rv_g) {
    extern __shared__ char fsm[];
    float* Qs   = (float*)(fsm + OFF_Q);     // [128][68] plain f32
    float* Ks   = (float*)(fsm + OFF_KV);    // [64][68]
    u64*   Vd   = (u64*)(fsm + OFF_KV);      // [64][33] overlaid
    float* Ps   = (float*)(fsm + OFF_PS);    // [64][132]
    float* bnd  = (float*)(fsm + OFF_BND);   // [128][10]
    float* bacc = (float*)(fsm + OFF_BAC);   // [128][10]
    float* rks  = (float*)(fsm + OFF_RKS);   // [9][68]
    float* rvs  = (float*)(fsm + OFF_RVS);   // [9][68]
    float* ms   = (float*)(fsm + OFF_MS);    // [512]
    float* mtv  = (float*)(fsm + OFF_MTV);   // [128]
    float* mro  = (float*)(fsm + OFF_MRO);   // [128]
    float* ssum = (float*)(fsm + OFF_SSM);   // [128]
    float* scal = (float*)(fsm + OFF_SCL);   // [128]

    int lid = threadIdx.x;
    int t0 = blockIdx.x * 128;
    int bh = blockIdx.y, b = bh >> 3, h = bh & 7;
    const float* qb = qkv + ((size_t)b*1536 + h*DK)*T;
    const float* kb = qkv + ((size_t)b*1536 + 512 + h*DK)*T;
    const float* vb = qkv + ((size_t)b*1536 + 1024 + h*DK)*T;
    int txq = lid & 7,  tyq = lid >> 3;
    int txc = lid & 15, tyc = lid >> 4;

#pragma unroll
    for (int it = 0; it < 32; it++) {
        int e = lid + it*256;
        int tloc = e & 127, dd = e >> 7;
        Qs[tloc*68 + dd] = qb[(size_t)dd*T + t0 + tloc];
    }
    for (int e = lid; e < 9*64; e += 256) {
        rks[(e >> 6)*68 + (e & 63)] = rk_g[e];
        rvs[(e >> 6)*68 + (e & 63)] = rv_g[e];
    }
    for (int e = lid; e < T; e += 256) ms[e] = g_mask[b*T + e];
    if (lid < 128) {
        mtv[lid] = g_mask[b*T + t0 + lid];
        mro[lid] = -3.4e38f;
        ssum[lid] = 0.f;
    }
    for (int e = lid; e < 128*10; e += 256) bacc[e] = 0.f;
    __syncthreads();
    for (int e = lid; e < 128*9; e += 256) {
        int t = e / 9, dt = e - t*9;
        float dot = 0.f;
#pragma unroll
        for (int d = 0; d < 64; d++)
            dot += Qs[t*68 + d] * rks[dt*68 + d];
        bnd[t*10 + dt] = dot;
    }

    u64 oacc[4][4];
#pragma unroll
    for (int i = 0; i < 4; i++)
#pragma unroll
        for (int j = 0; j < 4; j++) oacc[i][j] = 0ull;

    for (int s0 = 0; s0 < T; s0 += 64) {
        __syncthreads();
#pragma unroll
        for (int it = 0; it < 16; it++) {
            int e = lid + it*256;
            int dd = e >> 6, ss = e & 63;
            Ks[dd*68 + ss] = kb[(size_t)dd*T + s0 + ss];
        }
        __syncthreads();
        u64 sacc[4][4];
#pragma unroll
        for (int i = 0; i < 4; i++)
#pragma unroll
            for (int j = 0; j < 4; j++) sacc[i][j] = 0ull;
#pragma unroll 16
        for (int kk = 0; kk < 64; kk++) {
            ulonglong2 xa = *(const ulonglong2*)&Ks[kk*68 + txq*8];
            ulonglong2 xb = *(const ulonglong2*)&Ks[kk*68 + txq*8 + 4];
#pragma unroll
            for (int i = 0; i < 4; i++) {
                float qv = Qs[(tyq*4+i)*68 + kk];
                u64 w = fpack2(qv, qv);
                sacc[i][0] = ffma2(w, xa.x, sacc[i][0]);
                sacc[i][1] = ffma2(w, xa.y, sacc[i][1]);
                sacc[i][2] = ffma2(w, xb.x, sacc[i][2]);
                sacc[i][3] = ffma2(w, xb.y, sacc[i][3]);
            }
        }
        float sv[4][8];
#pragma unroll
        for (int i = 0; i < 4; i++) {
            int tl = tyq*4 + i;
            float mt = mtv[tl];
            float rmax = -3.4e38f;
#pragma unroll
            for (int jp = 0; jp < 4; jp++) {
                float2 f = funpack2(sacc[i][jp]);
                sv[i][2*jp] = f.x; sv[i][2*jp+1] = f.y;
            }
#pragma unroll
            for (int j = 0; j < 8; j++) {
                int sg = s0 + txq*8 + j;
                float v = sv[i][j];
                int dtix = sg - (t0 + tl) + W;
                if ((unsigned)dtix < 9u) v += bnd[tl*10 + dtix];
                if (mt * ms[sg] == 0.f) v = -1e4f;
                sv[i][j] = v;
                rmax = fmaxf(rmax, v);
            }
#pragma unroll
            for (int o = 1; o <= 4; o <<= 1)
                rmax = fmaxf(rmax, __shfl_xor_sync(0xffffffffu, rmax, o));
            if (txq == 0) {
                float old = mro[tl];
                float nm = fmaxf(old, rmax);
                scal[tl] = expf(old - nm);
                mro[tl] = nm;
            }
        }
        __syncthreads();
#pragma unroll
        for (int i = 0; i < 4; i++) {
            int tl = tyq*4 + i;
            float nm = mro[tl];
            float cs = 0.f;
#pragma unroll
            for (int j = 0; j < 8; j++) {
                float e = expf(sv[i][j] - nm);
                cs += e;
                Ps[(txq*8 + j)*132 + tl] = e;
            }
#pragma unroll
            for (int o = 1; o <= 4; o <<= 1)
                cs += __shfl_xor_sync(0xffffffffu, cs, o);
            if (txq == 0) ssum[tl] = ssum[tl]*scal[tl] + cs;
        }
        __syncthreads();
        for (int e = lid; e < 128*9; e += 256) {
            int t = e / 9, dt = e - t*9;
            float v = bacc[t*10 + dt] * scal[t];
            int sg = t0 + t + dt - W;
            if (sg >= s0 && sg < s0 + 64) v += Ps[(sg - s0)*132 + t];
            bacc[t*10 + dt] = v;
        }
#pragma unroll
        for (int jp = 0; jp < 4; jp++) {
            int tp = txc*4 + jp;
            float se = scal[2*tp], so = scal[2*tp + 1];
#pragma unroll
            for (int i = 0; i < 4; i++) {
                float2 f = funpack2(oacc[i][jp]);
                oacc[i][jp] = fpack2(f.x*se, f.y*so);
            }
        }
#pragma unroll
        for (int sub = 0; sub < 2; sub++) {
            __syncthreads();
#pragma unroll
            for (int it = 0; it < 8; it++) {
                int e = lid + it*256;
                int dd = e >> 5, ss = e & 31;
                float v = vb[(size_t)dd*T + s0 + sub*32 + ss];
                Vd[dd*33 + ss] = fpack2(v, v);
            }
            __syncthreads();
#pragma unroll 8
            for (int kk = 0; kk < 32; kk++) {
                ulonglong2 xa = *(const ulonglong2*)&Ps[(sub*32+kk)*132 + txc*8];
                ulonglong2 xb = *(const ulonglong2*)&Ps[(sub*32+kk)*132 + txc*8 + 4];
#pragma unroll
                for (int i = 0; i < 4; i++) {
                    u64 w = Vd[(tyc*4+i)*33 + kk];
                    oacc[i][0] = ffma2(w, xa.x, oacc[i][0]);
                    oacc[i][1] = ffma2(w, xa.y, oacc[i][1]);
                    oacc[i][2] = ffma2(w, xb.x, oacc[i][2]);
                    oacc[i][3] = ffma2(w, xb.y, oacc[i][3]);
                }
            }
        }
    }
    __syncthreads();
#pragma unroll
    for (int jp = 0; jp < 4; jp++) {
        int tp = txc*4 + jp;
        float inve = 1.f / ssum[2*tp];
        float invo = 1.f / ssum[2*tp + 1];
        float vals[4][2];
#pragma unroll
        for (int i = 0; i < 4; i++) {
            int d = tyc*4 + i;
            float be = 0.f, bo = 0.f;
#pragma unroll
            for (int dt = 0; dt < 9; dt++) {
                float rv = rvs[dt*68 + d];
                be += bacc[(2*tp)*10 + dt]   * rv;
                bo += bacc[(2*tp+1)*10 + dt] * rv;
            }
            float2 f = funpack2(oacc[i][jp]);
            vals[i][0] = (f.x + be)*inve;
            vals[i][1] = (f.y + bo)*invo;
        }
#pragma unroll
        for (int pp = 0; pp < 2; pp++) {
            int P = tyc*2 + pp;
            size_t pbase = ((size_t)(b*8 + h)*32 + P)*516 + t0 + 2*tp + 1;
            u32 h0, l0, h1, l1;
            split2(vals[2*pp][0], vals[2*pp+1][0], h0, l0);
            split2(vals[2*pp][1], vals[2*pp+1][1], h1, l1);
            PanHi[pbase]     = h0; PanLo[pbase]     = l0;
            PanHi[pbase + 1] = h1; PanLo[pbase + 1] = l1;
        }
    }
}

// ---------------- channel LayerNorm (256 blocks: 16t x 16c threads) -------------
__global__ void k_ln(float* __restrict__ hbuf, const float* __restrict__ yv,
                     const float* __restrict__ g, const float* __restrict__ bb,
                     int maskOut) {
    int tx = threadIdx.x, ty = threadIdx.y;
    int t = blockIdx.x*16 + tx, b = blockIdx.y;
    float s = 0.f, s2 = 0.f;
    for (int c = ty; c < C; c += 16) {
        size_t idx = ((size_t)b*C + c)*T + t;
        float v = hbuf[idx] + yv[idx];
        s += v; s2 += v*v;
    }
    __shared__ float rs[16][17], rs2[16][17];
    rs[ty][tx] = s; rs2[ty][tx] = s2;
    __syncthreads();
    if (ty == 0) {
        for (int j = 1; j < 16; j++) { s += rs[j][tx]; s2 += rs2[j][tx]; }
        float m = s / C;
        float var = s2 / C - m*m;
        rs[0][tx] = m;
        rs2[0][tx] = rsqrtf(var + 1e-5f);
    }
    __syncthreads();
    float m = rs[0][tx], r = rs2[0][tx];
    float mk = maskOut ? g_mask[b*T + t] : 1.f;
    for (int c = ty; c < C; c += 16) {
        size_t idx = ((size_t)b*C + c)*T + t;
        float v = hbuf[idx] + yv[idx];
        hbuf[idx] = ((v - m)*r*g[c] + bb[c]) * mk;
    }
}

// ---------------- launch -------------------------------------------------------
extern "C" void kernel_launch(void* const* d_in, const int* in_sizes, int n_in,
                              void* d_out, int out_size) {
    const int*   x    = (const int*)d_in[0];
    const int*   xlen = (const int*)d_in[1];
    const float* emb  = (const float*)d_in[2];
    const float* Wq = (const float*)d_in[3],  *bq = (const float*)d_in[4];
    const float* Wk = (const float*)d_in[5],  *bk = (const float*)d_in[6];
    const float* Wv = (const float*)d_in[7],  *bv = (const float*)d_in[8];
    const float* Wo = (const float*)d_in[9],  *bo = (const float*)d_in[10];
    const float* rel_k = (const float*)d_in[11], *rel_v = (const float*)d_in[12];
    const float* ln1g = (const float*)d_in[13], *ln1b = (const float*)d_in[14];
    const float* ln2g = (const float*)d_in[15], *ln2b = (const float*)d_in[16];
    const float* w1 = (const float*)d_in[17], *b1 = (const float*)d_in[18];
    const float* w2 = (const float*)d_in[19], *b2 = (const float*)d_in[20];
    const float* pw = (const float*)d_in[21], *pbv = (const float*)d_in[22];
    float* out = (float*)d_out;
    size_t SZ = (size_t)B*C*T;

    float *ph,*pqkv,*py,*pb3;
    u32 *x5h,*x5l,*x2h,*x2l,*wqh,*wql,*woh,*wol,*w1h,*w1l,*w2h,*w2l,*pjh,*pjl;
    cudaGetSymbolAddress((void**)&ph,   g_h);
    cudaGetSymbolAddress((void**)&pqkv, g_qkv);
    cudaGetSymbolAddress((void**)&py,   g_y);
    cudaGetSymbolAddress((void**)&pb3,  g_b3);
    cudaGetSymbolAddress((void**)&x5h,  g_px512_hi);
    cudaGetSymbolAddress((void**)&x5l,  g_px512_lo);
    cudaGetSymbolAddress((void**)&x2h,  g_px2048_hi);
    cudaGetSymbolAddress((void**)&x2l,  g_px2048_lo);
    cudaGetSymbolAddress((void**)&wqh,  g_wqkv_hi);
    cudaGetSymbolAddress((void**)&wql,  g_wqkv_lo);
    cudaGetSymbolAddress((void**)&woh,  g_wo_hi);
    cudaGetSymbolAddress((void**)&wol,  g_wo_lo);
    cudaGetSymbolAddress((void**)&w1h,  g_w1_hi);
    cudaGetSymbolAddress((void**)&w1l,  g_w1_lo);
    cudaGetSymbolAddress((void**)&w2h,  g_w2_hi);
    cudaGetSymbolAddress((void**)&w2l,  g_w2_lo);
    cudaGetSymbolAddress((void**)&pjh,  g_pj_hi);
    cudaGetSymbolAddress((void**)&pjl,  g_pj_lo);

    const int SMB = 64*136*4*4;
    static int attr_set = 0;
    if (!attr_set) {
        cudaFuncSetAttribute((void*)k_mma_f<1,128,0>, cudaFuncAttributeMaxDynamicSharedMemorySize, SMB);
        cudaFuncSetAttribute((void*)k_mma_f<3,128,0>, cudaFuncAttributeMaxDynamicSharedMemorySize, SMB);
        cudaFuncSetAttribute((void*)k_mma_f<3,128,1>, cudaFuncAttributeMaxDynamicSharedMemorySize, SMB);
        cudaFuncSetAttribute((void*)k_flash, cudaFuncAttributeMaxDynamicSharedMemorySize, FSM_TOTAL);
        attr_set = 1;
    }

    dim3 tb(32,8);
    k_zpad<<<32, 256>>>();
    k_embed<<<dim3(T/32, B), tb>>>(x, xlen, emb, out, out + 4*SZ);
    k_packwf<<<dim3(8, 32, 1), 256>>>(pw, 1.f, pjh, pjl, C, 1, 32, 8, 0);
    k_bias3<<<dim3(6, LYR), 256>>>(bq, bk, bv, pb3);

    for (int i = 0; i < LYR; i++) {
        k_packwf<<<dim3(4, 32, 1), 256>>>(Wq + (size_t)i*C*C, 0.125f, wqh, wql, C, 1, 32, 12, 0);
        k_packwf<<<dim3(4, 32, 1), 256>>>(Wk + (size_t)i*C*C, 1.f,    wqh, wql, C, 1, 32, 12, 4);
        k_packwf<<<dim3(4, 32, 1), 256>>>(Wv + (size_t)i*C*C, 1.f,    wqh, wql, C, 1, 32, 12, 8);
        k_packwf<<<dim3(4, 32, 1), 256>>>(Wo + (size_t)i*C*C, 1.f,    woh, wol, C, 1, 32, 4, 0);
        k_packwf<<<dim3(16, 32, 3), 256>>>(w1 + (size_t)i*DFF*C*3, 1.f, w1h, w1l, C*3, 3, 32, 16, 0);
        k_packwf<<<dim3(4, 128, 3), 256>>>(w2 + (size_t)i*C*DFF*3, 1.f, w2h, w2l, DFF*3, 3, 128, 4, 0);

        k_packx<<<dim3(8, 8, B), 256>>>(ph, x5h, x5l, C, 0);
        k_mma_f<1,128,0><<<dim3(4, 12, B), 256, SMB>>>(wqh, wql, x5h, x5l,
            pb3 + i*1536, pqkv, pqkv, 1536, 0, 0, 0, C, 0, 0);
        k_flash<<<dim3(T/128, B*H), 256, FSM_TOTAL>>>(pqkv, x5h, x5l,
            rel_k + (size_t)i*NREL*DK, rel_v + (size_t)i*NREL*DK);
        k_mma_f<1,128,0><<<dim3(4, 4, B), 256, SMB>>>(woh, wol, x5h, x5l,
            bo + i*C, py, py, C, 0, 0, 0, C, 0, 0);
        k_ln<<<dim3(T/16, B), dim3(16,16)>>>(ph, py, ln1g + i*C, ln1b + i*C, 0);

        k_packx<<<dim3(8, 8, B), 256>>>(ph, x5h, x5l, C, 1);
        k_mma_f<3,128,1><<<dim3(4, 16, B), 256, SMB>>>(w1h, w1l, x5h, x5l,
            b1 + i*DFF, 0, 0, 0, x2h, x2l, 32, C, 1, 0);
        k_mma_f<3,128,0><<<dim3(4, 4, B), 256, SMB>>>(w2h, w2l, x2h, x2l,
            b2 + i*C, py, py, C, 0, 0, 0, DFF, 0, 1);
        k_ln<<<dim3(T/16, B), dim3(16,16)>>>(ph, py, ln2g + i*C, ln2b + i*C, 1);
    }

    k_copy4<<<(B*C*T)/1024, 256>>>((const float4*)ph, (float4*)(out + SZ));
    k_packx<<<dim3(8, 8, B), 256>>>(ph, x5h, x5l, C, 0);
    k_mma_f<1,128,0><<<dim3(4, 8, B), 256, SMB>>>(pjh, pjl, x5h, x5l, pbv,
        out + 2*SZ, out + 3*SZ, 512, 0, 0, 0, C, 0, 1);
}

// round 15
// speedup vs baseline: 1.1561x; 1.0134x over previous
#include <cuda_runtime.h>
#include <math.h>

#define B 8
#define T 512
#define C 512
#define DFF 2048
#define H 8
#define LYR 6
#define W 4
#define DK 64
#define NREL 9

typedef unsigned long long u64;
typedef unsigned int u32;

// ---------------- scratch ----------------------------------------------------
__device__ float g_h[B*C*T];
__device__ float g_qkv[B*3*C*T];
__device__ float g_y[B*C*T];
__device__ float g_mask[B*T];
__device__ float g_b3[LYR*3*C];
// activation panels, pair-major: [b][ct][pair 32][516], bf16x2 hi/lo
__device__ u32 g_px512_hi[B*8*32*516],   g_px512_lo[B*8*32*516];
__device__ u32 g_px2048_hi[B*32*32*516], g_px2048_lo[B*32*32*516];
// weight fragment arrays (per-layer reused => L2-resident)
__device__ u32 g_wqkv_hi[32*12*1024],  g_wqkv_lo[32*12*1024];
__device__ u32 g_wo_hi[32*4*1024],     g_wo_lo[32*4*1024];
__device__ u32 g_w1_hi[3*32*16*1024],  g_w1_lo[3*32*16*1024];
__device__ u32 g_w2_hi[3*128*4*1024],  g_w2_lo[3*128*4*1024];
__device__ u32 g_pj_hi[32*8*1024],     g_pj_lo[32*8*1024];

// ---------------- helpers ------------------------------------------------------
__device__ __forceinline__ u64 ffma2(u64 a, u64 b, u64 c) {
    u64 d; asm("fma.rn.f32x2 %0, %1, %2, %3;" : "=l"(d) : "l"(a), "l"(b), "l"(c));
    return d;
}
__device__ __forceinline__ u64 fpack2(float lo, float hi) {
    u64 d; asm("mov.b64 %0, {%1, %2};" : "=l"(d) : "f"(lo), "f"(hi));
    return d;
}
__device__ __forceinline__ float2 funpack2(u64 v) {
    float2 r; asm("mov.b64 {%0, %1}, %2;" : "=f"(r.x), "=f"(r.y) : "l"(v));
    return r;
}
__device__ __forceinline__ u32 bf2(float h, float l) {
    u32 r; asm("cvt.rn.bf16x2.f32 %0, %1, %2;" : "=r"(r) : "f"(h), "f"(l));
    return r;
}
__device__ __forceinline__ void split2(float f0, float f1, u32& hv, u32& lv) {
    hv = bf2(f1, f0);
    float r0 = f0 - __uint_as_float(hv << 16);
    float r1 = f1 - __uint_as_float(hv & 0xffff0000u);
    lv = bf2(r1, r0);
}
__device__ __forceinline__ void mma16(float* d, const u32* a, u32 b0, u32 b1) {
    asm("mma.sync.aligned.m16n8k16.row.col.f32.bf16.bf16.f32 "
        "{%0,%1,%2,%3}, {%4,%5,%6,%7}, {%8,%9}, {%0,%1,%2,%3};"
        : "+f"(d[0]), "+f"(d[1]), "+f"(d[2]), "+f"(d[3])
        : "r"(a[0]), "r"(a[1]), "r"(a[2]), "r"(a[3]), "r"(b0), "r"(b1));
}
__device__ __forceinline__ u32 smem_u32(const void* p) {
    u32 a; asm("{ .reg .u64 t; cvta.to.shared.u64 t, %1; cvt.u32.u64 %0, t; }"
               : "=r"(a) : "l"(p));
    return a;
}
__device__ __forceinline__ void cp16(u32 dst, const void* src) {
    asm volatile("{ .reg .u64 g; cvta.to.global.u64 g, %1; "
                 "cp.async.cg.shared.global [%0], [g], 16; }"
                 :: "r"(dst), "l"(src) : "memory");
}

// ---------------- pad zeroing for both panels -----------------------------------
__global__ void k_zpad() {
    int r = blockIdx.x*256 + threadIdx.x;   // 2048 (x512) + 8192 (x2048)
    u32 *hi, *lo; int row;
    if (r < 2048)       { hi = g_px512_hi;  lo = g_px512_lo;  row = r; }
    else if (r < 10240) { hi = g_px2048_hi; lo = g_px2048_lo; row = r - 2048; }
    else return;
    size_t base = (size_t)row * 516;
    hi[base] = 0u;     lo[base] = 0u;
    hi[base+513] = 0u; lo[base+513] = 0u;
    hi[base+514] = 0u; lo[base+514] = 0u;
    hi[base+515] = 0u; lo[base+515] = 0u;
}

// ---------------- embedding + mask + qkv-input panel ----------------------------
__global__ void k_embed(const int* __restrict__ x, const int* __restrict__ xlen,
                        const float* __restrict__ emb,
                        float* __restrict__ out_xemb, float* __restrict__ out_mask) {
    int b = blockIdx.y;
    int t = blockIdx.x * 32 + threadIdx.x;
    int xi = x[b*T + t];
    float mk = (t < xlen[b]) ? 1.f : 0.f;
    const float SQ = 22.627416997969522f;
    for (int p = threadIdx.y; p < 256; p += 8) {
        int c0 = 2*p;
        float v0 = emb[xi*C + c0] * SQ;
        float v1 = emb[xi*C + c0 + 1] * SQ;
        out_xemb[((size_t)b*C + c0)*T + t] = v0;
        out_xemb[((size_t)b*C + c0 + 1)*T + t] = v1;
        float h0 = v0*mk, h1 = v1*mk;
        g_h[((size_t)b*C + c0)*T + t] = h0;
        g_h[((size_t)b*C + c0 + 1)*T + t] = h1;
        u32 hv, lv; split2(h0, h1, hv, lv);
        size_t pb = ((size_t)(b*8 + (p >> 5))*32 + (p & 31))*516 + t + 1;
        g_px512_hi[pb] = hv; g_px512_lo[pb] = lv;
    }
    if (threadIdx.y == 0) {
        g_mask[b*T + t] = mk;
        out_mask[b*T + t] = mk;
    }
}

__global__ void k_copy4(const float4* __restrict__ src, float4* __restrict__ dst) {
    int i = blockIdx.x * 256 + threadIdx.x;
    dst[i] = src[i];
}

__global__ void k_bias3(const float* __restrict__ bq, const float* __restrict__ bk,
                        const float* __restrict__ bv, float* __restrict__ b3) {
    int l = blockIdx.y;
    int i = blockIdx.x*256 + threadIdx.x;
    float v;
    if (i < 512)       v = bq[l*C + i] * 0.125f;
    else if (i < 1024) v = bk[l*C + i - 512];
    else               v = bv[l*C + i - 1024];
    b3[l*1536 + i] = v;
}

// ---------------- generic weight pack (proj only) -------------------------------
__global__ void k_packwf(const float* __restrict__ Wm, float scale,
                         u32* __restrict__ hi, u32* __restrict__ lo,
                         int ostride, int KKf, int CT16, int OT, int otOff) {
    int ot = blockIdx.x, c16 = blockIdx.y, kp = blockIdx.z;
    int tid = threadIdx.x, s = tid >> 5, l = tid & 31;
    int g = l >> 2, tq = l & 3;
    int wm = s >> 2, mi = s & 3;
    int obase = ot*128 + wm*64 + mi*16 + g;
    u32 rh[4], rl[4];
#pragma unroll
    for (int r = 0; r < 4; r++) {
        int o = obase + (r & 1)*8;
        int pair = (r < 2) ? tq : tq + 4;
        int ce = c16*16 + 2*pair;
        float f0 = Wm[(size_t)o*ostride + (size_t)ce*KKf + kp] * scale;
        float f1 = Wm[(size_t)o*ostride + (size_t)(ce+1)*KKf + kp] * scale;
        split2(f0, f1, rh[r], rl[r]);
    }
    size_t base = ((size_t)((kp*CT16 + c16)*OT + otOff + ot))*1024 + (s*32 + l)*4;
    *(uint4*)&hi[base] = make_uint4(rh[0], rh[1], rh[2], rh[3]);
    *(uint4*)&lo[base] = make_uint4(rl[0], rl[1], rl[2], rl[3]);
}

// ---------------- merged per-layer weight pack (q,k,v,o,w1,w2 in one launch) ----
__global__ void k_packall(const float* __restrict__ Wq, const float* __restrict__ Wk,
                          const float* __restrict__ Wv, const float* __restrict__ Wo,
                          const float* __restrict__ w1, const float* __restrict__ w2,
                          u32* __restrict__ qh, u32* __restrict__ ql,
                          u32* __restrict__ oh, u32* __restrict__ ol,
                          u32* __restrict__ w1h, u32* __restrict__ w1l,
                          u32* __restrict__ w2h, u32* __restrict__ w2l) {
    int bx = blockIdx.x;
    const float* Wm; float scale = 1.f;
    u32 *hi, *lo;
    int ostride, KKf, CT16, OT, otOff, ot, c16, kp;
    if (bx < 512) {
        int m = bx >> 7, r = bx & 127;
        ot = r & 3; c16 = r >> 2; kp = 0;
        ostride = C; KKf = 1; CT16 = 32;
        if (m == 0)      { Wm = Wq; scale = 0.125f; hi = qh; lo = ql; OT = 12; otOff = 0; }
        else if (m == 1) { Wm = Wk; hi = qh; lo = ql; OT = 12; otOff = 4; }
        else if (m == 2) { Wm = Wv; hi = qh; lo = ql; OT = 12; otOff = 8; }
        else             { Wm = Wo; hi = oh; lo = ol; OT = 4;  otOff = 0; }
    } else if (bx < 2048) {
        int r = bx - 512;
        ot = r & 15; c16 = (r >> 4) & 31; kp = r >> 9;
        Wm = w1; hi = w1h; lo = w1l; ostride = C*3; KKf = 3; CT16 = 32; OT = 16; otOff = 0;
    } else {
        int r = bx - 2048;
        ot = r & 3; c16 = (r >> 2) & 127; kp = r >> 9;
        Wm = w2; hi = w2h; lo = w2l; ostride = DFF*3; KKf = 3; CT16 = 128; OT = 4; otOff = 0;
    }
    int tid = threadIdx.x, s = tid >> 5, l = tid & 31;
    int g = l >> 2, tq = l & 3;
    int wm = s >> 2, mi = s & 3;
    int obase = ot*128 + wm*64 + mi*16 + g;
    u32 rh[4], rl[4];
#pragma unroll
    for (int r = 0; r < 4; r++) {
        int o = obase + (r & 1)*8;
        int pair = (r < 2) ? tq : tq + 4;
        int ce = c16*16 + 2*pair;
        float f0 = Wm[(size_t)o*ostride + (size_t)ce*KKf + kp] * scale;
        float f1 = Wm[(size_t)o*ostride + (size_t)(ce+1)*KKf + kp] * scale;
        split2(f0, f1, rh[r], rl[r]);
    }
    size_t base = ((size_t)((kp*CT16 + c16)*OT + otOff + ot))*1024 + (s*32 + l)*4;
    *(uint4*)&hi[base] = make_uint4(rh[0], rh[1], rh[2], rh[3]);
    *(uint4*)&lo[base] = make_uint4(rl[0], rl[1], rl[2], rl[3]);
}

// ---------------- fragment-direct bf16 mma GEMM/conv ---------------------------
#define LOADA(AH, AL, ct_, kp_, k16_) do { \
    size_t ab_ = ((size_t)(((kp_)*CT16 + (ct_)*4 + (k16_))*OT + oy)) << 8; \
    const uint4* Abh_ = (const uint4*)Whi + ab_; \
    const uint4* Abl_ = (const uint4*)Wlo + ab_; \
    _Pragma("unroll") \
    for (int mi_ = 0; mi_ < 4; mi_++) { \
        int s_ = (wm*4 + mi_)*32 + lane; \
        (AH)[mi_] = Abh_[s_]; (AL)[mi_] = Abl_[s_]; \
    } \
} while (0)

template<int KK, int NT, int PACK>
__global__ __launch_bounds__(256, 1) void k_mma_f(
        const u32* __restrict__ Whi, const u32* __restrict__ Wlo,
        const u32* __restrict__ Xhi, const u32* __restrict__ Xlo,
        const float* __restrict__ bias,
        float* __restrict__ Y0, float* __restrict__ Y1, int Osplit,
        u32* __restrict__ PanHi, u32* __restrict__ PanLo, int CTpan,
        int Cin, int relu, int maskOut) {
    extern __shared__ char smc[];
    const int STG = 64*136;
    const int CHUNKS = 33;
    const int PAD = (KK - 1) / 2;
    u32 sb = smem_u32(smc);
    int tid = threadIdx.x, warp = tid >> 5, lane = tid & 31;
    int g = lane >> 2, tq = lane & 3;
    int wm = warp >> 2, wn = warp & 3;
    int t0 = blockIdx.x*NT, oy = blockIdx.y, b = blockIdx.z;
    int OT = gridDim.y;
    int CT = Cin >> 6, CT16 = Cin >> 4;
    const float* mrow = g_mask + b*T;

    float acc[4][4][4];
#pragma unroll
    for (int mi = 0; mi < 4; mi++)
#pragma unroll
        for (int ni = 0; ni < 4; ni++)
#pragma unroll
            for (int q = 0; q < 4; q++) acc[mi][ni][q] = 0.f;

#pragma unroll
    for (int st = 0; st < 3; st++) {
        size_t prow = (size_t)(b*CT + st)*32;
        for (int e = tid; e < 64*CHUNKS; e += 256) {
            int r = e / CHUNKS, cch = e - r*CHUNKS;
            const u32* src = ((r < 32) ? Xhi : Xlo) + (prow + (r & 31))*516 + t0 + cch*4;
            cp16(sb + (u32)(st*STG + r*136 + cch*4)*4, src);
        }
        asm volatile("cp.async.commit_group;" ::: "memory");
    }

    uint4 ahA[4], alA[4], ahB[4], alB[4];
    LOADA(ahA, alA, 0, 0, 0);

    for (int ct = 0; ct < CT; ct++) {
        asm volatile("cp.async.wait_group 2;" ::: "memory");
        __syncthreads();
        if (ct + 3 < CT) {
            int stg = (ct + 3) & 3;
            size_t prow = (size_t)(b*CT + ct + 3)*32;
            for (int e = tid; e < 64*CHUNKS; e += 256) {
                int r = e / CHUNKS, cch = e - r*CHUNKS;
                const u32* src = ((r < 32) ? Xhi : Xlo) + (prow + (r & 31))*516 + t0 + cch*4;
                cp16(sb + (u32)(stg*STG + r*136 + cch*4)*4, src);
            }
        }
        asm volatile("cp.async.commit_group;" ::: "memory");

        const u32* Bst = (const u32*)smc + (ct & 3)*STG;
#pragma unroll
        for (int kp = 0; kp < KK; kp++) {
            int ccoff = kp + 1 - PAD;
#pragma unroll
            for (int k16 = 0; k16 < 4; k16++) {
                const int ui = kp*4 + k16;
                const int nu = ui + 1;
                if (nu < KK*4) {
                    if ((ui & 1) == 0) LOADA(ahB, alB, ct, (nu >> 2), (nu & 3));
                    else               LOADA(ahA, alA, ct, (nu >> 2), (nu & 3));
                } else {
                    if (ct + 1 < CT) {
                        if ((ui & 1) == 0) LOADA(ahB, alB, ct + 1, 0, 0);
                        else               LOADA(ahA, alA, ct + 1, 0, 0);
                    }
                }
                int rb = k16*8;
#pragma unroll
                for (int ni = 0; ni < 4; ni++) {
                    int cc = wn*32 + ni*8 + g + ccoff;
                    u32 bh0 = Bst[(rb+tq)*136 + cc];
                    u32 bh1 = Bst[(rb+tq+4)*136 + cc];
                    u32 bl0 = Bst[(32+rb+tq)*136 + cc];
                    u32 bl1 = Bst[(32+rb+tq+4)*136 + cc];
#pragma unroll
                    for (int mi = 0; mi < 4; mi++) {
                        if ((ui & 1) == 0) {
                            mma16(acc[mi][ni], (const u32*)&alA[mi], bh0, bh1);
                            mma16(acc[mi][ni], (const u32*)&ahA[mi], bl0, bl1);
                            mma16(acc[mi][ni], (const u32*)&ahA[mi], bh0, bh1);
                        } else {
                            mma16(acc[mi][ni], (const u32*)&alB[mi], bh0, bh1);
                            mma16(acc[mi][ni], (const u32*)&ahB[mi], bl0, bl1);
                            mma16(acc[mi][ni], (const u32*)&ahB[mi], bh0, bh1);
                        }
                    }
                }
            }
        }
    }
    __syncthreads();
    if (PACK == 0) {
#pragma unroll
        for (int mi = 0; mi < 4; mi++) {
#pragma unroll
            for (int half = 0; half < 2; half++) {
                int o = oy*128 + wm*64 + mi*16 + g + half*8;
                float bi = bias[o];
                float* Yp; size_t rowb;
                if (o < Osplit) { Yp = Y0; rowb = ((size_t)b*Osplit + o)*T; }
                else            { Yp = Y1; rowb = ((size_t)b*Osplit + (o - Osplit))*T; }
#pragma unroll
                for (int ni = 0; ni < 4; ni++) {
                    int t = t0 + wn*32 + ni*8 + 2*tq;
                    float v0 = acc[mi][ni][half*2 + 0] + bi;
                    float v1 = acc[mi][ni][half*2 + 1] + bi;
                    if (relu) { v0 = fmaxf(v0, 0.f); v1 = fmaxf(v1, 0.f); }
                    if (maskOut) { v0 *= mrow[t]; v1 *= mrow[t+1]; }
                    *(float2*)&Yp[rowb + t] = make_float2(v0, v1);
                }
            }
        }
    } else {
#pragma unroll
        for (int mi = 0; mi < 4; mi++) {
#pragma unroll
            for (int half = 0; half < 2; half++) {
                int o = oy*128 + wm*64 + mi*16 + g + half*8;
                float bi = bias[o];
                size_t pbase = ((size_t)(b*CTpan + (o >> 6))*32 + ((o & 63) >> 1))*516;
#pragma unroll
                for (int ni = 0; ni < 4; ni++) {
                    int t = t0 + wn*32 + ni*8 + 2*tq;
                    float v0 = acc[mi][ni][half*2 + 0] + bi;
                    float v1 = acc[mi][ni][half*2 + 1] + bi;
                    if (relu) { v0 = fmaxf(v0, 0.f); v1 = fmaxf(v1, 0.f); }
                    v0 *= mrow[t]; v1 *= mrow[t+1];
                    float p0 = __shfl_xor_sync(0xffffffffu, v0, 4);
                    float p1 = __shfl_xor_sync(0xffffffffu, v1, 4);
                    if (!(g & 1)) {
                        u32 h0, l0, h1, l1;
                        split2(v0, p0, h0, l0);
                        split2(v1, p1, h1, l1);
                        PanHi[pbase + t + 1] = h0; PanHi[pbase + t + 2] = h1;
                        PanLo[pbase + t + 1] = l0; PanLo[pbase + t + 2] = l1;
                    }
                }
            }
        }
    }
}

// ---------------- fused flash attention -> packed ctx panels -------------------
#define OFF_Q   0
#define OFF_KV  34816
#define OFF_PS  52224
#define OFF_BND 86016
#define OFF_BAC 91136
#define OFF_RKS 96256
#define OFF_RVS 98704
#define OFF_MS  101152
#define OFF_MTV 103200
#define OFF_MRO 103712
#define OFF_SSM 104224
#define OFF_SCL 104736
#define FSM_TOTAL 105248
__global__ __launch_bounds__(256, 2) void k_flash(
        const float* __restrict__ qkv,
        u32* __restrict__ PanHi, u32* __restrict__ PanLo,
        const float* __restrict__ rk_g, const float* __restrict__ rv_g) {
    extern __shared__ char fsm[];
    float* Qs   = (float*)(fsm + OFF_Q);
    float* Ks   = (float*)(fsm + OFF_KV);
    u64*   Vd   = (u64*)(fsm + OFF_KV);
    float* Ps   = (float*)(fsm + OFF_PS);
    float* bnd  = (float*)(fsm + OFF_BND);
    float* bacc = (float*)(fsm + OFF_BAC);
    float* rks  = (float*)(fsm + OFF_RKS);
    float* rvs  = (float*)(fsm + OFF_RVS);
    float* ms   = (float*)(fsm + OFF_MS);
    float* mtv  = (float*)(fsm + OFF_MTV);
    float* mro  = (float*)(fsm + OFF_MRO);
    float* ssum = (float*)(fsm + OFF_SSM);
    float* scal = (float*)(fsm + OFF_SCL);

    int lid = threadIdx.x;
    int t0 = blockIdx.x * 128;
    int bh = blockIdx.y, b = bh >> 3, h = bh & 7;
    const float* qb = qkv + ((size_t)b*1536 + h*DK)*T;
    const float* kb = qkv + ((size_t)b*1536 + 512 + h*DK)*T;
    const float* vb = qkv + ((size_t)b*1536 + 1024 + h*DK)*T;
    int txq = lid & 7,  tyq = lid >> 3;
    int txc = lid & 15, tyc = lid >> 4;

#pragma unroll
    for (int it = 0; it < 32; it++) {
        int e = lid + it*256;
        int tloc = e & 127, dd = e >> 7;
        Qs[tloc*68 + dd] = qb[(size_t)dd*T + t0 + tloc];
    }
    for (int e = lid; e < 9*64; e += 256) {
        rks[(e >> 6)*68 + (e & 63)] = rk_g[e];
        rvs[(e >> 6)*68 + (e & 63)] = rv_g[e];
    }
    for (int e = lid; e < T; e += 256) ms[e] = g_mask[b*T + e];
    if (lid < 128) {
        mtv[lid] = g_mask[b*T + t0 + lid];
        mro[lid] = -3.4e38f;
        ssum[lid] = 0.f;
    }
    for (int e = lid; e < 128*10; e += 256) bacc[e] = 0.f;
    __syncthreads();
    for (int e = lid; e < 128*9; e += 256) {
        int t = e / 9, dt = e - t*9;
        float dot = 0.f;
#pragma unroll
        for (int d = 0; d < 64; d++)
            dot += Qs[t*68 + d] * rks[dt*68 + d];
        bnd[t*10 + dt] = dot;
    }

    u64 oacc[4][4];
#pragma unroll
    for (int i = 0; i < 4; i++)
#pragma unroll
        for (int j = 0; j < 4; j++) oacc[i][j] = 0ull;

    for (int s0 = 0; s0 < T; s0 += 64) {
        __syncthreads();
#pragma unroll
        for (int it = 0; it < 16; it++) {
            int e = lid + it*256;
            int dd = e >> 6, ss = e & 63;
            Ks[dd*68 + ss] = kb[(size_t)dd*T + s0 + ss];
        }
        __syncthreads();
        u64 sacc[4][4];
#pragma unroll
        for (int i = 0; i < 4; i++)
#pragma unroll
            for (int j = 0; j < 4; j++) sacc[i][j] = 0ull;
#pragma unroll 16
        for (int kk = 0; kk < 64; kk++) {
            ulonglong2 xa = *(const ulonglong2*)&Ks[kk*68 + txq*8];
            ulonglong2 xb = *(const ulonglong2*)&Ks[kk*68 + txq*8 + 4];
#pragma unroll
            for (int i = 0; i < 4; i++) {
                float qv = Qs[(tyq*4+i)*68 + kk];
                u64 w = fpack2(qv, qv);
                sacc[i][0] = ffma2(w, xa.x, sacc[i][0]);
                sacc[i][1] = ffma2(w, xa.y, sacc[i][1]);
                sacc[i][2] = ffma2(w, xb.x, sacc[i][2]);
                sacc[i][3] = ffma2(w, xb.y, sacc[i][3]);
            }
        }
        float sv[4][8];
#pragma unroll
        for (int i = 0; i < 4; i++) {
            int tl = tyq*4 + i;
            float mt = mtv[tl];
            float rmax = -3.4e38f;
#pragma unroll
            for (int jp = 0; jp < 4; jp++) {
                float2 f = funpack2(sacc[i][jp]);
                sv[i][2*jp] = f.x; sv[i][2*jp+1] = f.y;
            }
#pragma unroll
            for (int j = 0; j < 8; j++) {
                int sg = s0 + txq*8 + j;
                float v = sv[i][j];
                int dtix = sg - (t0 + tl) + W;
                if ((unsigned)dtix < 9u) v += bnd[tl*10 + dtix];
                if (mt * ms[sg] == 0.f) v = -1e4f;
                sv[i][j] = v;
                rmax = fmaxf(rmax, v);
            }
#pragma unroll
            for (int o = 1; o <= 4; o <<= 1)
                rmax = fmaxf(rmax, __shfl_xor_sync(0xffffffffu, rmax, o));
            if (txq == 0) {
                float old = mro[tl];
                float nm = fmaxf(old, rmax);
                scal[tl] = expf(old - nm);
                mro[tl] = nm;
            }
        }
        __syncthreads();
#pragma unroll
        for (int i = 0; i < 4; i++) {
            int tl = tyq*4 + i;
            float nm = mro[tl];
            float cs = 0.f;
#pragma unroll
            for (int j = 0; j < 8; j++) {
                float e = expf(sv[i][j] - nm);
                cs += e;
                Ps[(txq*8 + j)*132 + tl] = e;
            }
#pragma unroll
            for (int o = 1; o <= 4; o <<= 1)
                cs += __shfl_xor_sync(0xffffffffu, cs, o);
            if (txq == 0) ssum[tl] = ssum[tl]*scal[tl] + cs;
        }
        __syncthreads();
        for (int e = lid; e < 128*9; e += 256) {
            int t = e / 9, dt = e - t*9;
            float v = bacc[t*10 + dt] * scal[t];
            int sg = t0 + t + dt - W;
            if (sg >= s0 && sg < s0 + 64) v += Ps[(sg - s0)*132 + t];
            bacc[t*10 + dt] = v;
        }
#pragma unroll
        for (int jp = 0; jp < 4; jp++) {
            int tp = txc*4 + jp;
            float se = scal[2*tp], so = scal[2*tp + 1];
#pragma unroll
            for (int i = 0; i < 4; i++) {
                float2 f = funpack2(oacc[i][jp]);
                oacc[i][jp] = fpack2(f.x*se, f.y*so);
            }
        }
#pragma unroll
        for (int sub = 0; sub < 2; sub++) {
            __syncthreads();
#pragma unroll
            for (int it = 0; it < 8; it++) {
                int e = lid + it*256;
                int dd = e >> 5, ss = e & 31;
                float v = vb[(size_t)dd*T + s0 + sub*32 + ss];
                Vd[dd*33 + ss] = fpack2(v, v);
            }
            __syncthreads();
#pragma unroll 8
            for (int kk = 0; kk < 32; kk++) {
                ulonglong2 xa = *(const ulonglong2*)&Ps[(sub*32+kk)*132 + txc*8];
                ulonglong2 xb = *(const ulonglong2*)&Ps[(sub*32+kk)*132 + txc*8 + 4];
#pragma unroll
                for (int i = 0; i < 4; i++) {
                    u64 w = Vd[(tyc*4+i)*33 + kk];
                    oacc[i][0] = ffma2(w, xa.x, oacc[i][0]);
                    oacc[i][1] = ffma2(w, xa.y, oacc[i][1]);
                    oacc[i][2] = ffma2(w, xb.x, oacc[i][2]);
                    oacc[i][3] = ffma2(w, xb.y, oacc[i][3]);
                }
            }
        }
    }
    __syncthreads();
#pragma unroll
    for (int jp = 0; jp < 4; jp++) {
        int tp = txc*4 + jp;
        float inve = 1.f / ssum[2*tp];
        float invo = 1.f / ssum[2*tp + 1];
        float vals[4][2];
#pragma unroll
        for (int i = 0; i < 4; i++) {
            int d = tyc*4 + i;
            float be = 0.f, bo = 0.f;
#pragma unroll
            for (int dt = 0; dt < 9; dt++) {
                float rv = rvs[dt*68 + d];
                be += bacc[(2*tp)*10 + dt]   * rv;
                bo += bacc[(2*tp+1)*10 + dt] * rv;
            }
            float2 f = funpack2(oacc[i][jp]);
            vals[i][0] = (f.x + be)*inve;
            vals[i][1] = (f.y + bo)*invo;
        }
#pragma unroll
        for (int pp = 0; pp < 2; pp++) {
            int P = tyc*2 + pp;
            size_t pbase = ((size_t)(b*8 + h)*32 + P)*516 + t0 + 2*tp + 1;
            u32 h0, l0, h1, l1;
            split2(vals[2*pp][0], vals[2*pp+1][0], h0, l0);
            split2(vals[2*pp][1], vals[2*pp+1][1], h1, l1);
            PanHi[pbase]     = h0; PanLo[pbase]     = l0;
            PanHi[pbase + 1] = h1; PanLo[pbase + 1] = l1;
        }
    }
}

// ---------------- channel LayerNorm + packed panel output ----------------------
// 16t x 16 threads, in-thread channel pairs. Panel always masked.
__global__ void k_ln(float* __restrict__ hbuf, const float* __restrict__ yv,
                     const float* __restrict__ g, const float* __restrict__ bb,
                     u32* __restrict__ PanHi, u32* __restrict__ PanLo,
                     int maskOut) {
    int tx = threadIdx.x, ty = threadIdx.y;
    int t = blockIdx.x*16 + tx, b = blockIdx.y;
    float s = 0.f, s2 = 0.f;
    for (int p = ty; p < 256; p += 16) {
        size_t idx = ((size_t)b*C + 2*p)*T + t;
        float v0 = hbuf[idx] + yv[idx];
        float v1 = hbuf[idx + T] + yv[idx + T];
        s += v0 + v1; s2 += v0*v0 + v1*v1;
    }
    __shared__ float rs[16][17], rs2[16][17];
    rs[ty][tx] = s; rs2[ty][tx] = s2;
    __syncthreads();
    if (ty == 0) {
        for (int j = 1; j < 16; j++) { s += rs[j][tx]; s2 += rs2[j][tx]; }
        float m = s / C;
        float var = s2 / C - m*m;
        rs[0][tx] = m;
        rs2[0][tx] = rsqrtf(var + 1e-5f);
    }
    __syncthreads();
    float m = rs[0][tx], r = rs2[0][tx];
    float mk = g_mask[b*T + t];
    float fm = maskOut ? mk : 1.f;
    for (int p = ty; p < 256; p += 16) {
        size_t idx = ((size_t)b*C + 2*p)*T + t;
        float v0 = hbuf[idx] + yv[idx];
        float v1 = hbuf[idx + T] + yv[idx + T];
        v0 = (v0 - m)*r*g[2*p]   + bb[2*p];
        v1 = (v1 - m)*r*g[2*p+1] + bb[2*p+1];
        hbuf[idx]     = v0 * fm;
        hbuf[idx + T] = v1 * fm;
        u32 hv, lv; split2(v0*mk, v1*mk, hv, lv);
        size_t pb = ((size_t)(b*8 + (p >> 5))*32 + (p & 31))*516 + t + 1;
        PanHi[pb] = hv; PanLo[pb] = lv;
    }
}

// ---------------- launch -------------------------------------------------------
extern "C" void kernel_launch(void* const* d_in, const int* in_sizes, int n_in,
                              void* d_out, int out_size) {
    const int*   x    = (const int*)d_in[0];
    const int*   xlen = (const int*)d_in[1];
    const float* emb  = (const float*)d_in[2];
    const float* Wq = (const float*)d_in[3],  *bq = (const float*)d_in[4];
    const float* Wk = (const float*)d_in[5],  *bk = (const float*)d_in[6];
    const float* Wv = (const float*)d_in[7],  *bv = (const float*)d_in[8];
    const float* Wo = (const float*)d_in[9],  *bo = (const float*)d_in[10];
    const float* rel_k = (const float*)d_in[11], *rel_v = (const float*)d_in[12];
    const float* ln1g = (const float*)d_in[13], *ln1b = (const float*)d_in[14];
    const float* ln2g = (const float*)d_in[15], *ln2b = (const float*)d_in[16];
    const float* w1 = (const float*)d_in[17], *b1 = (const float*)d_in[18];
    const float* w2 = (const float*)d_in[19], *b2 = (const float*)d_in[20];
    const float* pw = (const float*)d_in[21], *pbv = (const float*)d_in[22];
    float* out = (float*)d_out;
    size_t SZ = (size_t)B*C*T;

    float *ph,*pqkv,*py,*pb3;
    u32 *x5h,*x5l,*x2h,*x2l,*wqh,*wql,*woh,*wol,*w1h,*w1l,*w2h,*w2l,*pjh,*pjl;
    cudaGetSymbolAddress((void**)&ph,   g_h);
    cudaGetSymbolAddress((void**)&pqkv, g_qkv);
    cudaGetSymbolAddress((void**)&py,   g_y);
    cudaGetSymbolAddress((void**)&pb3,  g_b3);
    cudaGetSymbolAddress((void**)&x5h,  g_px512_hi);
    cudaGetSymbolAddress((void**)&x5l,  g_px512_lo);
    cudaGetSymbolAddress((void**)&x2h,  g_px2048_hi);
    cudaGetSymbolAddress((void**)&x2l,  g_px2048_lo);
    cudaGetSymbolAddress((void**)&wqh,  g_wqkv_hi);
    cudaGetSymbolAddress((void**)&wql,  g_wqkv_lo);
    cudaGetSymbolAddress((void**)&woh,  g_wo_hi);
    cudaGetSymbolAddress((void**)&wol,  g_wo_lo);
    cudaGetSymbolAddress((void**)&w1h,  g_w1_hi);
    cudaGetSymbolAddress((void**)&w1l,  g_w1_lo);
    cudaGetSymbolAddress((void**)&w2h,  g_w2_hi);
    cudaGetSymbolAddress((void**)&w2l,  g_w2_lo);
    cudaGetSymbolAddress((void**)&pjh,  g_pj_hi);
    cudaGetSymbolAddress((void**)&pjl,  g_pj_lo);

    const int SMB = 64*136*4*4;
    static int attr_set = 0;
    if (!attr_set) {
        cudaFuncSetAttribute((void*)k_mma_f<1,128,0>, cudaFuncAttributeMaxDynamicSharedMemorySize, SMB);
        cudaFuncSetAttribute((void*)k_mma_f<3,128,0>, cudaFuncAttributeMaxDynamicSharedMemorySize, SMB);
        cudaFuncSetAttribute((void*)k_mma_f<3,128,1>, cudaFuncAttributeMaxDynamicSharedMemorySize, SMB);
        cudaFuncSetAttribute((void*)k_flash, cudaFuncAttributeMaxDynamicSharedMemorySize, FSM_TOTAL);
        attr_set = 1;
    }

    dim3 tb(32,8);
    k_zpad<<<40, 256>>>();
    k_embed<<<dim3(T/32, B), tb>>>(x, xlen, emb, out, out + 4*SZ);
    k_packwf<<<dim3(8, 32, 1), 256>>>(pw, 1.f, pjh, pjl, C, 1, 32, 8, 0);
    k_bias3<<<dim3(6, LYR), 256>>>(bq, bk, bv, pb3);

    for (int i = 0; i < LYR; i++) {
        k_packall<<<3584, 256>>>(Wq + (size_t)i*C*C, Wk + (size_t)i*C*C,
                                 Wv + (size_t)i*C*C, Wo + (size_t)i*C*C,
                                 w1 + (size_t)i*DFF*C*3, w2 + (size_t)i*C*DFF*3,
                                 wqh, wql, woh, wol, w1h, w1l, w2h, w2l);

        k_mma_f<1,128,0><<<dim3(4, 12, B), 256, SMB>>>(wqh, wql, x5h, x5l,
            pb3 + i*1536, pqkv, pqkv, 1536, 0, 0, 0, C, 0, 0);
        k_flash<<<dim3(T/128, B*H), 256, FSM_TOTAL>>>(pqkv, x5h, x5l,
            rel_k + (size_t)i*NREL*DK, rel_v + (size_t)i*NREL*DK);
        k_mma_f<1,128,0><<<dim3(4, 4, B), 256, SMB>>>(woh, wol, x5h, x5l,
            bo + i*C, py, py, C, 0, 0, 0, C, 0, 0);
        k_ln<<<dim3(T/16, B), dim3(16,16)>>>(ph, py, ln1g + i*C, ln1b + i*C, x5h, x5l, 0);

        k_mma_f<3,128,1><<<dim3(4, 16, B), 256, SMB>>>(w1h, w1l, x5h, x5l,
            b1 + i*DFF, 0, 0, 0, x2h, x2l, 32, C, 1, 0);
        k_mma_f<3,128,0><<<dim3(4, 4, B), 256, SMB>>>(w2h, w2l, x2h, x2l,
            b2 + i*C, py, py, C, 0, 0, 0, DFF, 0, 1);
        k_ln<<<dim3(T/16, B), dim3(16,16)>>>(ph, py, ln2g + i*C, ln2b + i*C, x5h, x5l, 1);
    }

    k_copy4<<<(B*C*T)/1024, 256>>>((const float4*)ph, (float4*)(out + SZ));
    k_mma_f<1,128,0><<<dim3(4, 8, B), 256, SMB>>>(pjh, pjl, x5h, x5l, pbv,
        out + 2*SZ, out + 3*SZ, 512, 0, 0, 0, C, 0, 1);
}

// round 16
// speedup vs baseline: 1.1603x; 1.0036x over previous
#include <cuda_runtime.h>
#include <math.h>

#define B 8
#define T 512
#define C 512
#define DFF 2048
#define H 8
#define LYR 6
#define W 4
#define DK 64
#define NREL 9

typedef unsigned long long u64;
typedef unsigned int u32;

// ---------------- scratch ----------------------------------------------------
__device__ float g_h[B*C*T];
__device__ float g_qkv[B*3*C*T];
__device__ float g_y[B*C*T];
__device__ float g_mask[B*T];
__device__ float g_b3[LYR*3*C];
// activation panels, pair-major: [b][ct][pair 32][516], bf16x2 hi/lo
__device__ u32 g_px512_hi[B*8*32*516],   g_px512_lo[B*8*32*516];
__device__ u32 g_px2048_hi[B*32*32*516], g_px2048_lo[B*32*32*516];
// weight fragment arrays (per-layer reused => L2-resident)
__device__ u32 g_wqkv_hi[32*12*1024],  g_wqkv_lo[32*12*1024];
__device__ u32 g_wo_hi[32*4*1024],     g_wo_lo[32*4*1024];
__device__ u32 g_w1_hi[3*32*16*1024],  g_w1_lo[3*32*16*1024];
__device__ u32 g_w2_hi[3*128*4*1024],  g_w2_lo[3*128*4*1024];
__device__ u32 g_pj_hi[32*8*1024],     g_pj_lo[32*8*1024];

// ---------------- helpers ------------------------------------------------------
__device__ __forceinline__ u64 ffma2(u64 a, u64 b, u64 c) {
    u64 d; asm("fma.rn.f32x2 %0, %1, %2, %3;" : "=l"(d) : "l"(a), "l"(b), "l"(c));
    return d;
}
__device__ __forceinline__ u64 fpack2(float lo, float hi) {
    u64 d; asm("mov.b64 %0, {%1, %2};" : "=l"(d) : "f"(lo), "f"(hi));
    return d;
}
__device__ __forceinline__ float2 funpack2(u64 v) {
    float2 r; asm("mov.b64 {%0, %1}, %2;" : "=f"(r.x), "=f"(r.y) : "l"(v));
    return r;
}
__device__ __forceinline__ u32 bf2(float h, float l) {
    u32 r; asm("cvt.rn.bf16x2.f32 %0, %1, %2;" : "=r"(r) : "f"(h), "f"(l));
    return r;
}
__device__ __forceinline__ void split2(float f0, float f1, u32& hv, u32& lv) {
    hv = bf2(f1, f0);
    float r0 = f0 - __uint_as_float(hv << 16);
    float r1 = f1 - __uint_as_float(hv & 0xffff0000u);
    lv = bf2(r1, r0);
}
__device__ __forceinline__ void mma16(float* d, const u32* a, u32 b0, u32 b1) {
    asm("mma.sync.aligned.m16n8k16.row.col.f32.bf16.bf16.f32 "
        "{%0,%1,%2,%3}, {%4,%5,%6,%7}, {%8,%9}, {%0,%1,%2,%3};"
        : "+f"(d[0]), "+f"(d[1]), "+f"(d[2]), "+f"(d[3])
        : "r"(a[0]), "r"(a[1]), "r"(a[2]), "r"(a[3]), "r"(b0), "r"(b1));
}
__device__ __forceinline__ u32 smem_u32(const void* p) {
    u32 a; asm("{ .reg .u64 t; cvta.to.shared.u64 t, %1; cvt.u32.u64 %0, t; }"
               : "=r"(a) : "l"(p));
    return a;
}
__device__ __forceinline__ void cp16(u32 dst, const void* src) {
    asm volatile("{ .reg .u64 g; cvta.to.global.u64 g, %1; "
                 "cp.async.cg.shared.global [%0], [g], 16; }"
                 :: "r"(dst), "l"(src) : "memory");
}

// ---------------- pad zeroing for both panels -----------------------------------
__global__ void k_zpad() {
    int r = blockIdx.x*256 + threadIdx.x;
    u32 *hi, *lo; int row;
    if (r < 2048)       { hi = g_px512_hi;  lo = g_px512_lo;  row = r; }
    else if (r < 10240) { hi = g_px2048_hi; lo = g_px2048_lo; row = r - 2048; }
    else return;
    size_t base = (size_t)row * 516;
    hi[base] = 0u;     lo[base] = 0u;
    hi[base+513] = 0u; lo[base+513] = 0u;
    hi[base+514] = 0u; lo[base+514] = 0u;
    hi[base+515] = 0u; lo[base+515] = 0u;
}

// ---------------- embedding + mask + qkv-input panel ----------------------------
__global__ void k_embed(const int* __restrict__ x, const int* __restrict__ xlen,
                        const float* __restrict__ emb,
                        float* __restrict__ out_xemb, float* __restrict__ out_mask) {
    int b = blockIdx.y;
    int t = blockIdx.x * 32 + threadIdx.x;
    int xi = x[b*T + t];
    float mk = (t < xlen[b]) ? 1.f : 0.f;
    const float SQ = 22.627416997969522f;
    for (int p = threadIdx.y; p < 256; p += 8) {
        int c0 = 2*p;
        float v0 = emb[xi*C + c0] * SQ;
        float v1 = emb[xi*C + c0 + 1] * SQ;
        out_xemb[((size_t)b*C + c0)*T + t] = v0;
        out_xemb[((size_t)b*C + c0 + 1)*T + t] = v1;
        float h0 = v0*mk, h1 = v1*mk;
        g_h[((size_t)b*C + c0)*T + t] = h0;
        g_h[((size_t)b*C + c0 + 1)*T + t] = h1;
        u32 hv, lv; split2(h0, h1, hv, lv);
        size_t pb = ((size_t)(b*8 + (p >> 5))*32 + (p & 31))*516 + t + 1;
        g_px512_hi[pb] = hv; g_px512_lo[pb] = lv;
    }
    if (threadIdx.y == 0) {
        g_mask[b*T + t] = mk;
        out_mask[b*T + t] = mk;
    }
}

__global__ void k_copy4(const float4* __restrict__ src, float4* __restrict__ dst) {
    int i = blockIdx.x * 256 + threadIdx.x;
    dst[i] = src[i];
}

__global__ void k_bias3(const float* __restrict__ bq, const float* __restrict__ bk,
                        const float* __restrict__ bv, float* __restrict__ b3) {
    int l = blockIdx.y;
    int i = blockIdx.x*256 + threadIdx.x;
    float v;
    if (i < 512)       v = bq[l*C + i] * 0.125f;
    else if (i < 1024) v = bk[l*C + i - 512];
    else               v = bv[l*C + i - 1024];
    b3[l*1536 + i] = v;
}

// ---------------- generic weight pack (proj only) -------------------------------
__global__ void k_packwf(const float* __restrict__ Wm, float scale,
                         u32* __restrict__ hi, u32* __restrict__ lo,
                         int ostride, int KKf, int CT16, int OT, int otOff) {
    int ot = blockIdx.x, c16 = blockIdx.y, kp = blockIdx.z;
    int tid = threadIdx.x, s = tid >> 5, l = tid & 31;
    int g = l >> 2, tq = l & 3;
    int wm = s >> 2, mi = s & 3;
    int obase = ot*128 + wm*64 + mi*16 + g;
    u32 rh[4], rl[4];
#pragma unroll
    for (int r = 0; r < 4; r++) {
        int o = obase + (r & 1)*8;
        int pair = (r < 2) ? tq : tq + 4;
        int ce = c16*16 + 2*pair;
        float f0 = Wm[(size_t)o*ostride + (size_t)ce*KKf + kp] * scale;
        float f1 = Wm[(size_t)o*ostride + (size_t)(ce+1)*KKf + kp] * scale;
        split2(f0, f1, rh[r], rl[r]);
    }
    size_t base = ((size_t)((kp*CT16 + c16)*OT + otOff + ot))*1024 + (s*32 + l)*4;
    *(uint4*)&hi[base] = make_uint4(rh[0], rh[1], rh[2], rh[3]);
    *(uint4*)&lo[base] = make_uint4(rl[0], rl[1], rl[2], rl[3]);
}

// ---------------- merged per-layer weight pack ----------------------------------
__global__ void k_packall(const float* __restrict__ Wq, const float* __restrict__ Wk,
                          const float* __restrict__ Wv, const float* __restrict__ Wo,
                          const float* __restrict__ w1, const float* __restrict__ w2,
                          u32* __restrict__ qh, u32* __restrict__ ql,
                          u32* __restrict__ oh, u32* __restrict__ ol,
                          u32* __restrict__ w1h, u32* __restrict__ w1l,
                          u32* __restrict__ w2h, u32* __restrict__ w2l) {
    int bx = blockIdx.x;
    const float* Wm; float scale = 1.f;
    u32 *hi, *lo;
    int ostride, KKf, CT16, OT, otOff, ot, c16, kp;
    if (bx < 512) {
        int m = bx >> 7, r = bx & 127;
        ot = r & 3; c16 = r >> 2; kp = 0;
        ostride = C; KKf = 1; CT16 = 32;
        if (m == 0)      { Wm = Wq; scale = 0.125f; hi = qh; lo = ql; OT = 12; otOff = 0; }
        else if (m == 1) { Wm = Wk; hi = qh; lo = ql; OT = 12; otOff = 4; }
        else if (m == 2) { Wm = Wv; hi = qh; lo = ql; OT = 12; otOff = 8; }
        else             { Wm = Wo; hi = oh; lo = ol; OT = 4;  otOff = 0; }
    } else if (bx < 2048) {
        int r = bx - 512;
        ot = r & 15; c16 = (r >> 4) & 31; kp = r >> 9;
        Wm = w1; hi = w1h; lo = w1l; ostride = C*3; KKf = 3; CT16 = 32; OT = 16; otOff = 0;
    } else {
        int r = bx - 2048;
        ot = r & 3; c16 = (r >> 2) & 127; kp = r >> 9;
        Wm = w2; hi = w2h; lo = w2l; ostride = DFF*3; KKf = 3; CT16 = 128; OT = 4; otOff = 0;
    }
    int tid = threadIdx.x, s = tid >> 5, l = tid & 31;
    int g = l >> 2, tq = l & 3;
    int wm = s >> 2, mi = s & 3;
    int obase = ot*128 + wm*64 + mi*16 + g;
    u32 rh[4], rl[4];
#pragma unroll
    for (int r = 0; r < 4; r++) {
        int o = obase + (r & 1)*8;
        int pair = (r < 2) ? tq : tq + 4;
        int ce = c16*16 + 2*pair;
        float f0 = Wm[(size_t)o*ostride + (size_t)ce*KKf + kp] * scale;
        float f1 = Wm[(size_t)o*ostride + (size_t)(ce+1)*KKf + kp] * scale;
        split2(f0, f1, rh[r], rl[r]);
    }
    size_t base = ((size_t)((kp*CT16 + c16)*OT + otOff + ot))*1024 + (s*32 + l)*4;
    *(uint4*)&hi[base] = make_uint4(rh[0], rh[1], rh[2], rh[3]);
    *(uint4*)&lo[base] = make_uint4(rl[0], rl[1], rl[2], rl[3]);
}

// ---------------- fragment-direct bf16 mma GEMM/conv ---------------------------
// A prefetch distance 3 via 4 rotating register buffers (buffer idx = unit & 3,
// compile-time since U = KK*4 is 0 mod 4).
#define LOADA4(BI, ct_, kp_, k16_) do { \
    size_t ab_ = ((size_t)(((kp_)*CT16 + (ct_)*4 + (k16_))*OT + oy)) << 8; \
    const uint4* Abh_ = (const uint4*)Whi + ab_; \
    const uint4* Abl_ = (const uint4*)Wlo + ab_; \
    _Pragma("unroll") \
    for (int mi_ = 0; mi_ < 4; mi_++) { \
        int s_ = (wm*4 + mi_)*32 + lane; \
        ah[BI][mi_] = Abh_[s_]; al[BI][mi_] = Abl_[s_]; \
    } \
} while (0)

template<int KK, int NT, int PACK>
__global__ __launch_bounds__(256, 1) void k_mma_f(
        const u32* __restrict__ Whi, const u32* __restrict__ Wlo,
        const u32* __restrict__ Xhi, const u32* __restrict__ Xlo,
        const float* __restrict__ bias,
        float* __restrict__ Y0, float* __restrict__ Y1, int Osplit,
        u32* __restrict__ PanHi, u32* __restrict__ PanLo, int CTpan,
        int Cin, int relu, int maskOut) {
    extern __shared__ char smc[];
    const int STG = 64*136;
    const int CHUNKS = 33;
    const int PAD = (KK - 1) / 2;
    const int U = KK*4;
    u32 sb = smem_u32(smc);
    int tid = threadIdx.x, warp = tid >> 5, lane = tid & 31;
    int g = lane >> 2, tq = lane & 3;
    int wm = warp >> 2, wn = warp & 3;
    int t0 = blockIdx.x*NT, oy = blockIdx.y, b = blockIdx.z;
    int OT = gridDim.y;
    int CT = Cin >> 6, CT16 = Cin >> 4;
    const float* mrow = g_mask + b*T;

    float acc[4][4][4];
#pragma unroll
    for (int mi = 0; mi < 4; mi++)
#pragma unroll
        for (int ni = 0; ni < 4; ni++)
#pragma unroll
            for (int q = 0; q < 4; q++) acc[mi][ni][q] = 0.f;

#pragma unroll
    for (int st = 0; st < 3; st++) {
        size_t prow = (size_t)(b*CT + st)*32;
        for (int e = tid; e < 64*CHUNKS; e += 256) {
            int r = e / CHUNKS, cch = e - r*CHUNKS;
            const u32* src = ((r < 32) ? Xhi : Xlo) + (prow + (r & 31))*516 + t0 + cch*4;
            cp16(sb + (u32)(st*STG + r*136 + cch*4)*4, src);
        }
        asm volatile("cp.async.commit_group;" ::: "memory");
    }

    uint4 ah[4][4], al[4][4];
    LOADA4(0, 0, 0, 0);
    LOADA4(1, 0, 0, 1);
    LOADA4(2, 0, 0, 2);

    for (int ct = 0; ct < CT; ct++) {
        asm volatile("cp.async.wait_group 2;" ::: "memory");
        __syncthreads();
        if (ct + 3 < CT) {
            int stg = (ct + 3) & 3;
            size_t prow = (size_t)(b*CT + ct + 3)*32;
            for (int e = tid; e < 64*CHUNKS; e += 256) {
                int r = e / CHUNKS, cch = e - r*CHUNKS;
                const u32* src = ((r < 32) ? Xhi : Xlo) + (prow + (r & 31))*516 + t0 + cch*4;
                cp16(sb + (u32)(stg*STG + r*136 + cch*4)*4, src);
            }
        }
        asm volatile("cp.async.commit_group;" ::: "memory");

        const u32* Bst = (const u32*)smc + (ct & 3)*STG;
#pragma unroll
        for (int ui = 0; ui < U; ui++) {
            const int kp = ui >> 2, k16 = ui & 3;
            const int ccoff = kp + 1 - PAD;
            const int pf = ui + 3;
            const int pb = pf & 3;
            if (pf < U) {
                LOADA4(pb, ct, (pf >> 2), (pf & 3));
            } else if (ct + 1 < CT) {
                const int p2 = pf - U;
                LOADA4(pb, ct + 1, (p2 >> 2), (p2 & 3));
            }
            const int cb = ui & 3;
            int rb = k16*8;
#pragma unroll
            for (int ni = 0; ni < 4; ni++) {
                int cc = wn*32 + ni*8 + g + ccoff;
                u32 bh0 = Bst[(rb+tq)*136 + cc];
                u32 bh1 = Bst[(rb+tq+4)*136 + cc];
                u32 bl0 = Bst[(32+rb+tq)*136 + cc];
                u32 bl1 = Bst[(32+rb+tq+4)*136 + cc];
#pragma unroll
                for (int mi = 0; mi < 4; mi++) {
                    mma16(acc[mi][ni], (const u32*)&al[cb][mi], bh0, bh1);
                    mma16(acc[mi][ni], (const u32*)&ah[cb][mi], bl0, bl1);
                    mma16(acc[mi][ni], (const u32*)&ah[cb][mi], bh0, bh1);
                }
            }
        }
    }
    __syncthreads();
    if (PACK == 0) {
#pragma unroll
        for (int mi = 0; mi < 4; mi++) {
#pragma unroll
            for (int half = 0; half < 2; half++) {
                int o = oy*128 + wm*64 + mi*16 + g + half*8;
                float bi = bias[o];
                float* Yp; size_t rowb;
                if (o < Osplit) { Yp = Y0; rowb = ((size_t)b*Osplit + o)*T; }
                else            { Yp = Y1; rowb = ((size_t)b*Osplit + (o - Osplit))*T; }
#pragma unroll
                for (int ni = 0; ni < 4; ni++) {
                    int t = t0 + wn*32 + ni*8 + 2*tq;
                    float v0 = acc[mi][ni][half*2 + 0] + bi;
                    float v1 = acc[mi][ni][half*2 + 1] + bi;
                    if (relu) { v0 = fmaxf(v0, 0.f); v1 = fmaxf(v1, 0.f); }
                    if (maskOut) { v0 *= mrow[t]; v1 *= mrow[t+1]; }
                    *(float2*)&Yp[rowb + t] = make_float2(v0, v1);
                }
            }
        }
    } else {
#pragma unroll
        for (int mi = 0; mi < 4; mi++) {
#pragma unroll
            for (int half = 0; half < 2; half++) {
                int o = oy*128 + wm*64 + mi*16 + g + half*8;
                float bi = bias[o];
                size_t pbase = ((size_t)(b*CTpan + (o >> 6))*32 + ((o & 63) >> 1))*516;
#pragma unroll
                for (int ni = 0; ni < 4; ni++) {
                    int t = t0 + wn*32 + ni*8 + 2*tq;
                    float v0 = acc[mi][ni][half*2 + 0] + bi;
                    float v1 = acc[mi][ni][half*2 + 1] + bi;
                    if (relu) { v0 = fmaxf(v0, 0.f); v1 = fmaxf(v1, 0.f); }
                    v0 *= mrow[t]; v1 *= mrow[t+1];
                    float p0 = __shfl_xor_sync(0xffffffffu, v0, 4);
                    float p1 = __shfl_xor_sync(0xffffffffu, v1, 4);
                    if (!(g & 1)) {
                        u32 h0, l0, h1, l1;
                        split2(v0, p0, h0, l0);
                        split2(v1, p1, h1, l1);
                        PanHi[pbase + t + 1] = h0; PanHi[pbase + t + 2] = h1;
                        PanLo[pbase + t + 1] = l0; PanLo[pbase + t + 2] = l1;
                    }
                }
            }
        }
    }
}

// ---------------- fused flash attention -> packed ctx panels -------------------
#define OFF_Q   0
#define OFF_KV  34816
#define OFF_PS  52224
#define OFF_BND 86016
#define OFF_BAC 91136
#define OFF_RKS 96256
#define OFF_RVS 98704
#define OFF_MS  101152
#define OFF_MTV 103200
#define OFF_MRO 103712
#define OFF_SSM 104224
#define OFF_SCL 104736
#define FSM_TOTAL 105248
__global__ __launch_bounds__(256, 2) void k_flash(
        const float* __restrict__ qkv,
        u32* __restrict__ PanHi, u32* __restrict__ PanLo,
        const float* __restrict__ rk_g, const float* __restrict__ rv_g) {
    extern __shared__ char fsm[];
    float* Qs   = (float*)(fsm + OFF_Q);
    float* Ks   = (float*)(fsm + OFF_KV);
    u64*   Vd   = (u64*)(fsm + OFF_KV);
    float* Ps   = (float*)(fsm + OFF_PS);
    float* bnd  = (float*)(fsm + OFF_BND);
    float* bacc = (float*)(fsm + OFF_BAC);
    float* rks  = (float*)(fsm + OFF_RKS);
    float* rvs  = (float*)(fsm + OFF_RVS);
    float* ms   = (float*)(fsm + OFF_MS);
    float* mtv  = (float*)(fsm + OFF_MTV);
    float* mro  = (float*)(fsm + OFF_MRO);
    float* ssum = (float*)(fsm + OFF_SSM);
    float* scal = (float*)(fsm + OFF_SCL);

    int lid = threadIdx.x;
    int t0 = blockIdx.x * 128;
    int bh = blockIdx.y, b = bh >> 3, h = bh & 7;
    const float* qb = qkv + ((size_t)b*1536 + h*DK)*T;
    const float* kb = qkv + ((size_t)b*1536 + 512 + h*DK)*T;
    const float* vb = qkv + ((size_t)b*1536 + 1024 + h*DK)*T;
    int txq = lid & 7,  tyq = lid >> 3;
    int txc = lid & 15, tyc = lid >> 4;

#pragma unroll
    for (int it = 0; it < 32; it++) {
        int e = lid + it*256;
        int tloc = e & 127, dd = e >> 7;
        Qs[tloc*68 + dd] = qb[(size_t)dd*T + t0 + tloc];
    }
    for (int e = lid; e < 9*64; e += 256) {
        rks[(e >> 6)*68 + (e & 63)] = rk_g[e];
        rvs[(e >> 6)*68 + (e & 63)] = rv_g[e];
    }
    for (int e = lid; e < T; e += 256) ms[e] = g_mask[b*T + e];
    if (lid < 128) {
        mtv[lid] = g_mask[b*T + t0 + lid];
        mro[lid] = -3.4e38f;
        ssum[lid] = 0.f;
    }
    for (int e = lid; e < 128*10; e += 256) bacc[e] = 0.f;
    __syncthreads();
    for (int e = lid; e < 128*9; e += 256) {
        int t = e / 9, dt = e - t*9;
        float dot = 0.f;
#pragma unroll
        for (int d = 0; d < 64; d++)
            dot += Qs[t*68 + d] * rks[dt*68 + d];
        bnd[t*10 + dt] = dot;
    }

    u64 oacc[4][4];
#pragma unroll
    for (int i = 0; i < 4; i++)
#pragma unroll
        for (int j = 0; j < 4; j++) oacc[i][j] = 0ull;

    for (int s0 = 0; s0 < T; s0 += 64) {
        __syncthreads();
#pragma unroll
        for (int it = 0; it < 16; it++) {
            int e = lid + it*256;
            int dd = e >> 6, ss = e & 63;
            Ks[dd*68 + ss] = kb[(size_t)dd*T + s0 + ss];
        }
        __syncthreads();
        u64 sacc[4][4];
#pragma unroll
        for (int i = 0; i < 4; i++)
#pragma unroll
            for (int j = 0; j < 4; j++) sacc[i][j] = 0ull;
#pragma unroll 16
        for (int kk = 0; kk < 64; kk++) {
            ulonglong2 xa = *(const ulonglong2*)&Ks[kk*68 + txq*8];
            ulonglong2 xb = *(const ulonglong2*)&Ks[kk*68 + txq*8 + 4];
#pragma unroll
            for (int i = 0; i < 4; i++) {
                float qv = Qs[(tyq*4+i)*68 + kk];
                u64 w = fpack2(qv, qv);
                sacc[i][0] = ffma2(w, xa.x, sacc[i][0]);
                sacc[i][1] = ffma2(w, xa.y, sacc[i][1]);
                sacc[i][2] = ffma2(w, xb.x, sacc[i][2]);
                sacc[i][3] = ffma2(w, xb.y, sacc[i][3]);
            }
        }
        float sv[4][8];
#pragma unroll
        for (int i = 0; i < 4; i++) {
            int tl = tyq*4 + i;
            float mt = mtv[tl];
            float rmax = -3.4e38f;
#pragma unroll
            for (int jp = 0; jp < 4; jp++) {
                float2 f = funpack2(sacc[i][jp]);
                sv[i][2*jp] = f.x; sv[i][2*jp+1] = f.y;
            }
#pragma unroll
            for (int j = 0; j < 8; j++) {
                int sg = s0 + txq*8 + j;
                float v = sv[i][j];
                int dtix = sg - (t0 + tl) + W;
                if ((unsigned)dtix < 9u) v += bnd[tl*10 + dtix];
                if (mt * ms[sg] == 0.f) v = -1e4f;
                sv[i][j] = v;
                rmax = fmaxf(rmax, v);
            }
#pragma unroll
            for (int o = 1; o <= 4; o <<= 1)
                rmax = fmaxf(rmax, __shfl_xor_sync(0xffffffffu, rmax, o));
            if (txq == 0) {
                float old = mro[tl];
                float nm = fmaxf(old, rmax);
                scal[tl] = expf(old - nm);
                mro[tl] = nm;
            }
        }
        __syncthreads();
#pragma unroll
        for (int i = 0; i < 4; i++) {
            int tl = tyq*4 + i;
            float nm = mro[tl];
            float cs = 0.f;
#pragma unroll
            for (int j = 0; j < 8; j++) {
                float e = expf(sv[i][j] - nm);
                cs += e;
                Ps[(txq*8 + j)*132 + tl] = e;
            }
#pragma unroll
            for (int o = 1; o <= 4; o <<= 1)
                cs += __shfl_xor_sync(0xffffffffu, cs, o);
            if (txq == 0) ssum[tl] = ssum[tl]*scal[tl] + cs;
        }
        __syncthreads();
        for (int e = lid; e < 128*9; e += 256) {
            int t = e / 9, dt = e - t*9;
            float v = bacc[t*10 + dt] * scal[t];
            int sg = t0 + t + dt - W;
            if (sg >= s0 && sg < s0 + 64) v += Ps[(sg - s0)*132 + t];
            bacc[t*10 + dt] = v;
        }
#pragma unroll
        for (int jp = 0; jp < 4; jp++) {
            int tp = txc*4 + jp;
            float se = scal[2*tp], so = scal[2*tp + 1];
#pragma unroll
            for (int i = 0; i < 4; i++) {
                float2 f = funpack2(oacc[i][jp]);
                oacc[i][jp] = fpack2(f.x*se, f.y*so);
            }
        }
#pragma unroll
        for (int sub = 0; sub < 2; sub++) {
            __syncthreads();
#pragma unroll
            for (int it = 0; it < 8; it++) {
                int e = lid + it*256;
                int dd = e >> 5, ss = e & 31;
                float v = vb[(size_t)dd*T + s0 + sub*32 + ss];
                Vd[dd*33 + ss] = fpack2(v, v);
            }
            __syncthreads();
#pragma unroll 8
            for (int kk = 0; kk < 32; kk++) {
                ulonglong2 xa = *(const ulonglong2*)&Ps[(sub*32+kk)*132 + txc*8];
                ulonglong2 xb = *(const ulonglong2*)&Ps[(sub*32+kk)*132 + txc*8 + 4];
#pragma unroll
                for (int i = 0; i < 4; i++) {
                    u64 w = Vd[(tyc*4+i)*33 + kk];
                    oacc[i][0] = ffma2(w, xa.x, oacc[i][0]);
                    oacc[i][1] = ffma2(w, xa.y, oacc[i][1]);
                    oacc[i][2] = ffma2(w, xb.x, oacc[i][2]);
                    oacc[i][3] = ffma2(w, xb.y, oacc[i][3]);
                }
            }
        }
    }
    __syncthreads();
#pragma unroll
    for (int jp = 0; jp < 4; jp++) {
        int tp = txc*4 + jp;
        float inve = 1.f / ssum[2*tp];
        float invo = 1.f / ssum[2*tp + 1];
        float vals[4][2];
#pragma unroll
        for (int i = 0; i < 4; i++) {
            int d = tyc*4 + i;
            float be = 0.f, bo = 0.f;
#pragma unroll
            for (int dt = 0; dt < 9; dt++) {
                float rv = rvs[dt*68 + d];
                be += bacc[(2*tp)*10 + dt]   * rv;
                bo += bacc[(2*tp+1)*10 + dt] * rv;
            }
            float2 f = funpack2(oacc[i][jp]);
            vals[i][0] = (f.x + be)*inve;
            vals[i][1] = (f.y + bo)*invo;
        }
#pragma unroll
        for (int pp = 0; pp < 2; pp++) {
            int P = tyc*2 + pp;
            size_t pbase = ((size_t)(b*8 + h)*32 + P)*516 + t0 + 2*tp + 1;
            u32 h0, l0, h1, l1;
            split2(vals[2*pp][0], vals[2*pp+1][0], h0, l0);
            split2(vals[2*pp][1], vals[2*pp+1][1], h1, l1);
            PanHi[pbase]     = h0; PanLo[pbase]     = l0;
            PanHi[pbase + 1] = h1; PanLo[pbase + 1] = l1;
        }
    }
}

// ---------------- channel LayerNorm + packed panel output ----------------------
__global__ void k_ln(float* __restrict__ hbuf, const float* __restrict__ yv,
                     const float* __restrict__ g, const float* __restrict__ bb,
                     u32* __restrict__ PanHi, u32* __restrict__ PanLo,
                     int maskOut) {
    int tx = threadIdx.x, ty = threadIdx.y;
    int t = blockIdx.x*16 + tx, b = blockIdx.y;
    float s = 0.f, s2 = 0.f;
    for (int p = ty; p < 256; p += 16) {
        size_t idx = ((size_t)b*C + 2*p)*T + t;
        float v0 = hbuf[idx] + yv[idx];
        float v1 = hbuf[idx + T] + yv[idx + T];
        s += v0 + v1; s2 += v0*v0 + v1*v1;
    }
    __shared__ float rs[16][17], rs2[16][17];
    rs[ty][tx] = s; rs2[ty][tx] = s2;
    __syncthreads();
    if (ty == 0) {
        for (int j = 1; j < 16; j++) { s += rs[j][tx]; s2 += rs2[j][tx]; }
        float m = s / C;
        float var = s2 / C - m*m;
        rs[0][tx] = m;
        rs2[0][tx] = rsqrtf(var + 1e-5f);
    }
    __syncthreads();
    float m = rs[0][tx], r = rs2[0][tx];
    float mk = g_mask[b*T + t];
    float fm = maskOut ? mk : 1.f;
    for (int p = ty; p < 256; p += 16) {
        size_t idx = ((size_t)b*C + 2*p)*T + t;
        float v0 = hbuf[idx] + yv[idx];
        float v1 = hbuf[idx + T] + yv[idx + T];
        v0 = (v0 - m)*r*g[2*p]   + bb[2*p];
        v1 = (v1 - m)*r*g[2*p+1] + bb[2*p+1];
        hbuf[idx]     = v0 * fm;
        hbuf[idx + T] = v1 * fm;
        u32 hv, lv; split2(v0*mk, v1*mk, hv, lv);
        size_t pb = ((size_t)(b*8 + (p >> 5))*32 + (p & 31))*516 + t + 1;
        PanHi[pb] = hv; PanLo[pb] = lv;
    }
}

// ---------------- launch -------------------------------------------------------
extern "C" void kernel_launch(void* const* d_in, const int* in_sizes, int n_in,
                              void* d_out, int out_size) {
    const int*   x    = (const int*)d_in[0];
    const int*   xlen = (const int*)d_in[1];
    const float* emb  = (const float*)d_in[2];
    const float* Wq = (const float*)d_in[3],  *bq = (const float*)d_in[4];
    const float* Wk = (const float*)d_in[5],  *bk = (const float*)d_in[6];
    const float* Wv = (const float*)d_in[7],  *bv = (const float*)d_in[8];
    const float* Wo = (const float*)d_in[9],  *bo = (const float*)d_in[10];
    const float* rel_k = (const float*)d_in[11], *rel_v = (const float*)d_in[12];
    const float* ln1g = (const float*)d_in[13], *ln1b = (const float*)d_in[14];
    const float* ln2g = (const float*)d_in[15], *ln2b = (const float*)d_in[16];
    const float* w1 = (const float*)d_in[17], *b1 = (const float*)d_in[18];
    const float* w2 = (const float*)d_in[19], *b2 = (const float*)d_in[20];
    const float* pw = (const float*)d_in[21], *pbv = (const float*)d_in[22];
    float* out = (float*)d_out;
    size_t SZ = (size_t)B*C*T;

    float *ph,*pqkv,*py,*pb3;
    u32 *x5h,*x5l,*x2h,*x2l,*wqh,*wql,*woh,*wol,*w1h,*w1l,*w2h,*w2l,*pjh,*pjl;
    cudaGetSymbolAddress((void**)&ph,   g_h);
    cudaGetSymbolAddress((void**)&pqkv, g_qkv);
    cudaGetSymbolAddress((void**)&py,   g_y);
    cudaGetSymbolAddress((void**)&pb3,  g_b3);
    cudaGetSymbolAddress((void**)&x5h,  g_px512_hi);
    cudaGetSymbolAddress((void**)&x5l,  g_px512_lo);
    cudaGetSymbolAddress((void**)&x2h,  g_px2048_hi);
    cudaGetSymbolAddress((void**)&x2l,  g_px2048_lo);
    cudaGetSymbolAddress((void**)&wqh,  g_wqkv_hi);
    cudaGetSymbolAddress((void**)&wql,  g_wqkv_lo);
    cudaGetSymbolAddress((void**)&woh,  g_wo_hi);
    cudaGetSymbolAddress((void**)&wol,  g_wo_lo);
    cudaGetSymbolAddress((void**)&w1h,  g_w1_hi);
    cudaGetSymbolAddress((void**)&w1l,  g_w1_lo);
    cudaGetSymbolAddress((void**)&w2h,  g_w2_hi);
    cudaGetSymbolAddress((void**)&w2l,  g_w2_lo);
    cudaGetSymbolAddress((void**)&pjh,  g_pj_hi);
    cudaGetSymbolAddress((void**)&pjl,  g_pj_lo);

    const int SMB = 64*136*4*4;
    static int attr_set = 0;
    if (!attr_set) {
        cudaFuncSetAttribute((void*)k_mma_f<1,128,0>, cudaFuncAttributeMaxDynamicSharedMemorySize, SMB);
        cudaFuncSetAttribute((void*)k_mma_f<3,128,0>, cudaFuncAttributeMaxDynamicSharedMemorySize, SMB);
        cudaFuncSetAttribute((void*)k_mma_f<3,128,1>, cudaFuncAttributeMaxDynamicSharedMemorySize, SMB);
        cudaFuncSetAttribute((void*)k_flash, cudaFuncAttributeMaxDynamicSharedMemorySize, FSM_TOTAL);
        attr_set = 1;
    }

    dim3 tb(32,8);
    k_zpad<<<40, 256>>>();
    k_embed<<<dim3(T/32, B), tb>>>(x, xlen, emb, out, out + 4*SZ);
    k_packwf<<<dim3(8, 32, 1), 256>>>(pw, 1.f, pjh, pjl, C, 1, 32, 8, 0);
    k_bias3<<<dim3(6, LYR), 256>>>(bq, bk, bv, pb3);

    for (int i = 0; i < LYR; i++) {
        k_packall<<<3584, 256>>>(Wq + (size_t)i*C*C, Wk + (size_t)i*C*C,
                                 Wv + (size_t)i*C*C, Wo + (size_t)i*C*C,
                                 w1 + (size_t)i*DFF*C*3, w2 + (size_t)i*C*DFF*3,
                                 wqh, wql, woh, wol, w1h, w1l, w2h, w2l);

        k_mma_f<1,128,0><<<dim3(4, 12, B), 256, SMB>>>(wqh, wql, x5h, x5l,
            pb3 + i*1536, pqkv, pqkv, 1536, 0, 0, 0, C, 0, 0);
        k_flash<<<dim3(T/128, B*H), 256, FSM_TOTAL>>>(pqkv, x5h, x5l,
            rel_k + (size_t)i*NREL*DK, rel_v + (size_t)i*NREL*DK);
        k_mma_f<1,128,0><<<dim3(4, 4, B), 256, SMB>>>(woh, wol, x5h, x5l,
            bo + i*C, py, py, C, 0, 0, 0, C, 0, 0);
        k_ln<<<dim3(T/16, B), dim3(16,16)>>>(ph, py, ln1g + i*C, ln1b + i*C, x5h, x5l, 0);

        k_mma_f<3,128,1><<<dim3(4, 16, B), 256, SMB>>>(w1h, w1l, x5h, x5l,
            b1 + i*DFF, 0, 0, 0, x2h, x2l, 32, C, 1, 0);
        k_mma_f<3,128,0><<<dim3(4, 4, B), 256, SMB>>>(w2h, w2l, x2h, x2l,
            b2 + i*C, py, py, C, 0, 0, 0, DFF, 0, 1);
        k_ln<<<dim3(T/16, B), dim3(16,16)>>>(ph, py, ln2g + i*C, ln2b + i*C, x5h, x5l, 1);
    }

    k_copy4<<<(B*C*T)/1024, 256>>>((const float4*)ph, (float4*)(out + SZ));
    // NOTE: last ln2 already wrote the masked-h panel (x5) -> proj consumes it directly.
    k_mma_f<1,128,0><<<dim3(4, 8, B), 256, SMB>>>(pjh, pjl, x5h, x5l, pbv,
        out + 2*SZ, out + 3*SZ, 512, 0, 0, 0, C, 0, 1);
}